// round 6
// baseline (speedup 1.0000x reference)
#include <cuda_runtime.h>
#include <cstdint>

// ---------------------------------------------------------------------------
// Problem constants
// ---------------------------------------------------------------------------
constexpr int kN    = 512;
constexpr int kBZ   = 32;
constexpr int kTC   = 256;
constexpr int kF1   = 256;
constexpr int kF2   = 128;
constexpr int kE    = 524288;
constexpr int kNTOT = kBZ * kN;          // 16384
constexpr int kKTOT = kF2 * 2 * kN;      // 131072

// ---------------------------------------------------------------------------
// Scratch (offsets in floats).  H|SC1 adjacent, XW2|XWS2 adjacent (merged gemm2)
// ---------------------------------------------------------------------------
constexpr long OFF_EG   = 0;
constexpr long OFF_FG   = OFF_EG   + (long)kNTOT;
constexpr long OFF_A8   = OFF_FG   + (long)kNTOT;                // u8 view
constexpr long OFF_DISD = OFF_A8   + (long)kBZ * kN * kN / 4;
constexpr long OFF_XW1  = OFF_DISD + (long)kNTOT;
constexpr long OFF_H    = OFF_XW1  + (long)kNTOT * kF1;
constexpr long OFF_SC1  = OFF_H    + (long)kNTOT * kF1;          // contiguous after H
constexpr long OFF_XW2  = OFF_SC1  + (long)kNTOT * kF1;
constexpr long OFF_XWS2 = OFF_XW2  + (long)kNTOT * kF2;          // contiguous after XW2
constexpr long OFF_EMB  = OFF_XWS2 + (long)kNTOT * kF2;
constexpr long OFF_DISS = OFF_EMB  + (long)kNTOT * 256;
constexpr long OFF_DEGS = OFF_DISS + (long)kNTOT;                // int
constexpr long OFF_H1   = OFF_DEGS + (long)kNTOT;
constexpr long OFF_NS   = OFF_H1   + (long)kBZ * 256;            // int, kNTOT+1
constexpr long OFF_CUR  = OFF_NS   + (long)kNTOT + 4;            // int
constexpr long OFF_ESRC = OFF_CUR  + (long)kNTOT;                // int, kE
constexpr long SCRATCH_FLOATS = OFF_ESRC + (long)kE;

__device__ __align__(16) float g_scratch[SCRATCH_FLOATS];

// ---------------------------------------------------------------------------
// tf32 / ldmatrix helpers
// ---------------------------------------------------------------------------
__device__ __forceinline__ uint32_t f2tf(float x) {
    uint32_t r;
    asm("cvt.rna.tf32.f32 %0, %1;" : "=r"(r) : "f"(x));
    return r;
}
__device__ __forceinline__ void mma_tf32(float* d, const uint32_t* a,
                                         uint32_t b0, uint32_t b1) {
    asm volatile(
        "mma.sync.aligned.m16n8k8.row.col.f32.tf32.tf32.f32 "
        "{%0,%1,%2,%3},{%4,%5,%6,%7},{%8,%9},{%0,%1,%2,%3};"
        : "+f"(d[0]), "+f"(d[1]), "+f"(d[2]), "+f"(d[3])
        : "r"(a[0]), "r"(a[1]), "r"(a[2]), "r"(a[3]), "r"(b0), "r"(b1));
}
__device__ __forceinline__ void ldsm4(uint32_t* r, uint32_t addr) {
    asm volatile("ldmatrix.sync.aligned.m8n8.x4.shared.b16 {%0,%1,%2,%3}, [%4];"
                 : "=r"(r[0]), "=r"(r[1]), "=r"(r[2]), "=r"(r[3]) : "r"(addr));
}
__device__ __forceinline__ uint32_t smem_u32(const void* p) {
    return (uint32_t)__cvta_generic_to_shared(p);
}

// ---------------------------------------------------------------------------
// Small kernels
// ---------------------------------------------------------------------------
__global__ void k_zeroS(int* degS, float* h1) {
    int i = blockIdx.x * 256 + threadIdx.x;
    if (i < kNTOT) degS[i] = 0;
    if (i < kBZ * 256) h1[i] = 0.f;
}

// per node: u=relu(t); E=exp(lr1-lr0+b1-b0), F=exp(ls1-ls0)
__global__ void k_lslr(const float* __restrict__ t, const float* __restrict__ fcw,
                       const float* __restrict__ fcb,
                       float* __restrict__ Eg, float* __restrict__ Fg) {
    int warp = (blockIdx.x * blockDim.x + threadIdx.x) >> 5;
    int lane = threadIdx.x & 31;
    if (warp >= kNTOT) return;
    const float* tn = t + (long)warp * kTC;
    const float* w0 = fcw;
    const float* w1 = fcw + 512;
    float s0 = 0.f, s1 = 0.f, r0 = 0.f, r1 = 0.f;
#pragma unroll
    for (int q = 0; q < 8; q++) {
        int d = lane + 32 * q;
        float u = fmaxf(tn[d], 0.f);
        s0 += u * w0[d];       s1 += u * w1[d];
        r0 += u * w0[256 + d]; r1 += u * w1[256 + d];
    }
#pragma unroll
    for (int off = 16; off; off >>= 1) {
        s0 += __shfl_down_sync(0xffffffffu, s0, off);
        s1 += __shfl_down_sync(0xffffffffu, s1, off);
        r0 += __shfl_down_sync(0xffffffffu, r0, off);
        r1 += __shfl_down_sync(0xffffffffu, r1, off);
    }
    if (lane == 0) {
        Eg[warp] = expf(r1 - r0 + fcb[1] - fcb[0]);
        Fg[warp] = expf(s1 - s0);
    }
}

// A8[b][i][j] = (y0>=y1) via l1 >= l0*E_i*F_j, l=-log(clamp(u))
__global__ void k_buildA(const float* __restrict__ gu,
                         const float* __restrict__ Eg, const float* __restrict__ Fg,
                         unsigned char* __restrict__ A8) {
    int idx = blockIdx.x * 256 + threadIdx.x;
    int j0 = (idx & 127) << 2;
    int i  = (idx >> 7) & 511;
    int b  = idx >> 16;
    float Ei = Eg[b * kN + i];
    float4 Fv = *reinterpret_cast<const float4*>(Fg + b * kN + j0);
    const float4* g4 = reinterpret_cast<const float4*>(
        gu + ((long)(b * kN + i) * kN + j0) * 2);
    float4 u01 = g4[0];
    float4 u23 = g4[1];
    auto bit = [&](float ux, float uy, float Fj) -> unsigned char {
        ux = fminf(fmaxf(ux, 1e-9f), 1.0f - 1e-9f);
        uy = fminf(fmaxf(uy, 1e-9f), 1.0f - 1e-9f);
        float l0 = -logf(ux);
        float l1 = -logf(uy);
        return (l1 >= l0 * Ei * Fj) ? 1 : 0;
    };
    uchar4 r;
    r.x = bit(u01.x, u01.y, Fv.x);
    r.y = bit(u01.z, u01.w, Fv.y);
    r.z = bit(u23.x, u23.y, Fv.z);
    r.w = bit(u23.z, u23.w, Fv.w);
    *reinterpret_cast<uchar4*>(A8 + (long)(b * kN + i) * kN + j0) = r;
}

// disD[b][j] = rsqrt(1 + sum_i A8[b][i][j])  — direct, no atomics
__global__ void k_colsumD(const unsigned char* __restrict__ A8,
                          float* __restrict__ disD) {
    int b = blockIdx.x;
    int j = blockIdx.y * 128 + threadIdx.x;
    const unsigned char* Ab = A8 + (long)b * kN * kN;
    int s = 0;
#pragma unroll 8
    for (int r = 0; r < kN; r++) s += Ab[(long)r * kN + j];
    disD[b * kN + j] = rsqrtf(1.f + (float)s);
}

__global__ void k_degS(const int* __restrict__ colp, int* degS) {
    int e = blockIdx.x * 256 + threadIdx.x;
    if (e < kE) atomicAdd(&degS[colp[e]], 1);
}

__global__ void k_disS(const int* __restrict__ degS, float* __restrict__ disS) {
    int n = blockIdx.x * 256 + threadIdx.x;
    if (n < kNTOT) disS[n] = rsqrtf((float)degS[n] + 1.f);
}

// exclusive prefix-sum of degS -> nodeStart, cursor
__global__ void k_scan(const int* __restrict__ degS, int* __restrict__ ns,
                       int* __restrict__ cur) {
    __shared__ int sm[1024];
    int tid = threadIdx.x;
    int base = tid * 16;
    int local[16];
    int sum = 0;
#pragma unroll
    for (int v = 0; v < 16; v++) { local[v] = degS[base + v]; sum += local[v]; }
    sm[tid] = sum;
    __syncthreads();
    for (int off = 1; off < 1024; off <<= 1) {
        int v = (tid >= off) ? sm[tid - off] : 0;
        __syncthreads();
        sm[tid] += v;
        __syncthreads();
    }
    int run = sm[tid] - sum;
#pragma unroll
    for (int v = 0; v < 16; v++) {
        ns[base + v] = run;
        cur[base + v] = run;
        run += local[v];
    }
    if (tid == 1023) ns[kNTOT] = run;
}

__global__ void k_fill(const int* __restrict__ rowp, const int* __restrict__ colp,
                       int* cur, int* __restrict__ esrc) {
    int e = blockIdx.x * 256 + threadIdx.x;
    if (e < kE) {
        int c = colp[e];
        int p = atomicAdd(&cur[c], 1);
        esrc[p] = rowp[e];
    }
}

// ---------------------------------------------------------------------------
// CSR gather: WPN warps per node, 128 features each
// ---------------------------------------------------------------------------
template <int WPN>
__global__ __launch_bounds__(256) void k_gather(
        const int* __restrict__ ns, const int* __restrict__ esrc,
        const float* __restrict__ xw, const float* __restrict__ disS,
        const float* __restrict__ bias, float* __restrict__ out,
        int outStride, int outOffset) {
    constexpr int F = WPN * 128;
    int gw = (blockIdx.x * 256 + threadIdx.x) >> 5;
    int lane = threadIdx.x & 31;
    int node = gw / WPN;
    int part = gw % WPN;
    if (node >= kNTOT) return;
    int off = part * 128 + lane * 4;
    float dc = disS[node];
    float4 acc;
    {
        float4 xv = *reinterpret_cast<const float4*>(xw + (long)node * F + off);
        float4 bb = *reinterpret_cast<const float4*>(bias + off);
        float d2 = dc * dc;
        acc = make_float4(xv.x * d2 + bb.x, xv.y * d2 + bb.y,
                          xv.z * d2 + bb.z, xv.w * d2 + bb.w);
    }
    int s = ns[node], e = ns[node + 1];
    int i = s;
    for (; i + 4 <= e; i += 4) {
        int r0 = esrc[i], r1 = esrc[i + 1], r2 = esrc[i + 2], r3 = esrc[i + 3];
        float s0 = disS[r0] * dc, s1 = disS[r1] * dc;
        float s2 = disS[r2] * dc, s3 = disS[r3] * dc;
        float4 x0 = *reinterpret_cast<const float4*>(xw + (long)r0 * F + off);
        float4 x1 = *reinterpret_cast<const float4*>(xw + (long)r1 * F + off);
        float4 x2 = *reinterpret_cast<const float4*>(xw + (long)r2 * F + off);
        float4 x3 = *reinterpret_cast<const float4*>(xw + (long)r3 * F + off);
        acc.x += x0.x * s0 + x1.x * s1 + x2.x * s2 + x3.x * s3;
        acc.y += x0.y * s0 + x1.y * s1 + x2.y * s2 + x3.y * s3;
        acc.z += x0.z * s0 + x1.z * s1 + x2.z * s2 + x3.z * s3;
        acc.w += x0.w * s0 + x1.w * s1 + x2.w * s2 + x3.w * s3;
    }
    for (; i < e; i++) {
        int r = esrc[i];
        float sr = disS[r] * dc;
        float4 xv = *reinterpret_cast<const float4*>(xw + (long)r * F + off);
        acc.x += xv.x * sr; acc.y += xv.y * sr;
        acc.z += xv.z * sr; acc.w += xv.w * sr;
    }
    *reinterpret_cast<float4*>(out + (long)node * outStride + outOffset + off) = acc;
}

// ---------------------------------------------------------------------------
// tf32 NT GEMM with ldmatrix fragment loads: C[MxNf] = A[MxK] @ B[NfxK]^T
// SMEM [128][20]: row stride 80B (16B-aligned), 8-row ldmatrix groups hit all
// 32 banks once (stride-20 pattern) — conflict-free.
// ---------------------------------------------------------------------------
template <bool RELU_A>
__global__ __launch_bounds__(256) void k_gemm_tf32(
        const float* __restrict__ A, long aStride,
        const float* __restrict__ B,
        float* __restrict__ C, long cStride,
        int Nf, int K) {
    __shared__ uint32_t As[2][128][20];
    __shared__ uint32_t Bs[2][128][20];
    const float* Ab = A + (long)blockIdx.z * aStride;
    float* Cb = C + (long)blockIdx.z * cStride;
    int m0 = blockIdx.y * 128, n0 = blockIdx.x * 128;
    int t = threadIdx.x;
    int wid = t >> 5, lane = t & 31;
    int mw = (wid >> 1) * 32, nw = (wid & 1) * 64;
    int g = lane >> 2, tg = lane & 3;
    int lrow16 = lane & 15;            // ldmatrix row within 16-row block
    int lhalf4 = (lane >> 4) * 4;      // ldmatrix k-half (0 or 4)
    int lr = t >> 2, lc = (t & 3) << 2;

    uint32_t sA[2] = { smem_u32(&As[0][0][0]), smem_u32(&As[1][0][0]) };
    uint32_t sB[2] = { smem_u32(&Bs[0][0][0]), smem_u32(&Bs[1][0][0]) };

    float acc[2][8][4];
#pragma unroll
    for (int i = 0; i < 2; i++)
#pragma unroll
        for (int j = 0; j < 8; j++)
#pragma unroll
            for (int c = 0; c < 4; c++) acc[i][j][c] = 0.f;

    const float* aP0 = Ab + (long)(m0 + lr) * K + lc;
    const float* aP1 = Ab + (long)(m0 + lr + 64) * K + lc;
    const float* bP0 = B + (long)(n0 + lr) * K + lc;
    const float* bP1 = B + (long)(n0 + lr + 64) * K + lc;

    auto cvt4 = [](float4 v, bool relu) -> uint4 {
        if (relu) {
            v.x = fmaxf(v.x, 0.f); v.y = fmaxf(v.y, 0.f);
            v.z = fmaxf(v.z, 0.f); v.w = fmaxf(v.w, 0.f);
        }
        uint4 r;
        r.x = f2tf(v.x); r.y = f2tf(v.y); r.z = f2tf(v.z); r.w = f2tf(v.w);
        return r;
    };

    {
        uint4 a0 = cvt4(*reinterpret_cast<const float4*>(aP0), RELU_A);
        uint4 a1 = cvt4(*reinterpret_cast<const float4*>(aP1), RELU_A);
        uint4 b0 = cvt4(*reinterpret_cast<const float4*>(bP0), false);
        uint4 b1 = cvt4(*reinterpret_cast<const float4*>(bP1), false);
        *reinterpret_cast<uint4*>(&As[0][lr][lc]) = a0;
        *reinterpret_cast<uint4*>(&As[0][lr + 64][lc]) = a1;
        *reinterpret_cast<uint4*>(&Bs[0][lr][lc]) = b0;
        *reinterpret_cast<uint4*>(&Bs[0][lr + 64][lc]) = b1;
    }
    __syncthreads();

    int buf = 0;
    for (int k0 = 0; k0 < K; k0 += 16) {
        bool more = (k0 + 16) < K;
        float4 na0, na1, nb0, nb1;
        if (more) {
            na0 = *reinterpret_cast<const float4*>(aP0 + k0 + 16);
            na1 = *reinterpret_cast<const float4*>(aP1 + k0 + 16);
            nb0 = *reinterpret_cast<const float4*>(bP0 + k0 + 16);
            nb1 = *reinterpret_cast<const float4*>(bP1 + k0 + 16);
        }
#pragma unroll
        for (int s = 0; s < 2; s++) {
            int kcol = s * 8 + lhalf4;
            uint32_t af0[4], af1[4];
            ldsm4(af0, sA[buf] + ((mw + lrow16) * 20 + kcol) * 4);
            ldsm4(af1, sA[buf] + ((mw + 16 + lrow16) * 20 + kcol) * 4);
#pragma unroll
            for (int p = 0; p < 4; p++) {
                uint32_t bf[4];
                ldsm4(bf, sB[buf] + ((nw + p * 16 + lrow16) * 20 + kcol) * 4);
                mma_tf32(acc[0][2 * p],     af0, bf[0], bf[2]);
                mma_tf32(acc[0][2 * p + 1], af0, bf[1], bf[3]);
                mma_tf32(acc[1][2 * p],     af1, bf[0], bf[2]);
                mma_tf32(acc[1][2 * p + 1], af1, bf[1], bf[3]);
            }
        }
        if (more) {
            int nb = buf ^ 1;
            *reinterpret_cast<uint4*>(&As[nb][lr][lc]) = cvt4(na0, RELU_A);
            *reinterpret_cast<uint4*>(&As[nb][lr + 64][lc]) = cvt4(na1, RELU_A);
            *reinterpret_cast<uint4*>(&Bs[nb][lr][lc]) = cvt4(nb0, false);
            *reinterpret_cast<uint4*>(&Bs[nb][lr + 64][lc]) = cvt4(nb1, false);
            __syncthreads();
            buf = nb;
        }
    }

#pragma unroll
    for (int mt = 0; mt < 2; mt++) {
        int row = m0 + mw + mt * 16 + g;
#pragma unroll
        for (int j = 0; j < 8; j++) {
            int col = n0 + nw + j * 8 + 2 * tg;
            *reinterpret_cast<float2*>(Cb + (long)row * Nf + col) =
                make_float2(acc[mt][j][0], acc[mt][j][1]);
            *reinterpret_cast<float2*>(Cb + (long)(row + 8) * Nf + col) =
                make_float2(acc[mt][j][2], acc[mt][j][3]);
        }
    }
}

// ---------------------------------------------------------------------------
// tf32 dense GCN propagation (scalar-LDS version, unchanged)
// ---------------------------------------------------------------------------
template <bool RELU>
__global__ __launch_bounds__(256) void k_prop_tf32(
        const unsigned char* __restrict__ Adj8, const float* __restrict__ XW,
        const float* __restrict__ dis, const float* __restrict__ bias,
        float* __restrict__ out, int F, int outStride, int outOffset) {
    __shared__ uint32_t As[2][16][136];
    __shared__ uint32_t Bs[2][16][136];
    int b = blockIdx.z;
    const unsigned char* Ab = Adj8 + (long)b * kN * kN;
    const float* Xb = XW + (long)b * kN * F;
    const float* db = dis + b * kN;
    float* Ob = out + (long)b * kN * outStride + outOffset;
    int i0 = blockIdx.y * 128, f0 = blockIdx.x * 128;
    int t = threadIdx.x;
    int wid = t >> 5, lane = t & 31;
    int mw = (wid >> 1) * 32, nw = (wid & 1) * 64;
    int g = lane >> 2, tg = lane & 3;
    int jj = t >> 4;
    int ii = (t & 15) << 3;

    float acc[2][8][4];
#pragma unroll
    for (int i = 0; i < 2; i++)
#pragma unroll
        for (int j = 0; j < 8; j++)
#pragma unroll
            for (int c = 0; c < 4; c++) acc[i][j][c] = 0.f;

    constexpr uint32_t ONE = 0x3F800000u;
    auto stTile = [&](int bufI, uint2 rawA, float4 x0, float4 x1, float dj) {
        uint4 ua0, ua1, ux0, ux1;
        ua0.x = (rawA.x & 0xffu)         ? ONE : 0u;
        ua0.y = ((rawA.x >> 8) & 0xffu)  ? ONE : 0u;
        ua0.z = ((rawA.x >> 16) & 0xffu) ? ONE : 0u;
        ua0.w = ((rawA.x >> 24) & 0xffu) ? ONE : 0u;
        ua1.x = (rawA.y & 0xffu)         ? ONE : 0u;
        ua1.y = ((rawA.y >> 8) & 0xffu)  ? ONE : 0u;
        ua1.z = ((rawA.y >> 16) & 0xffu) ? ONE : 0u;
        ua1.w = ((rawA.y >> 24) & 0xffu) ? ONE : 0u;
        ux0.x = f2tf(x0.x * dj); ux0.y = f2tf(x0.y * dj);
        ux0.z = f2tf(x0.z * dj); ux0.w = f2tf(x0.w * dj);
        ux1.x = f2tf(x1.x * dj); ux1.y = f2tf(x1.y * dj);
        ux1.z = f2tf(x1.z * dj); ux1.w = f2tf(x1.w * dj);
        *reinterpret_cast<uint4*>(&As[bufI][jj][ii]) = ua0;
        *reinterpret_cast<uint4*>(&As[bufI][jj][ii + 4]) = ua1;
        *reinterpret_cast<uint4*>(&Bs[bufI][jj][ii]) = ux0;
        *reinterpret_cast<uint4*>(&Bs[bufI][jj][ii + 4]) = ux1;
    };

    {
        uint2 rawA = *reinterpret_cast<const uint2*>(Ab + (long)jj * kN + i0 + ii);
        const float* xp = Xb + (long)jj * F + f0 + ii;
        stTile(0, rawA,
               *reinterpret_cast<const float4*>(xp),
               *reinterpret_cast<const float4*>(xp + 4),
               db[jj]);
    }
    __syncthreads();

    int buf = 0;
    for (int j0 = 0; j0 < kN; j0 += 16) {
        bool more = (j0 + 16) < kN;
        uint2 nraw;
        float4 nx0, nx1;
        float djn = 0.f;
        if (more) {
            nraw = *reinterpret_cast<const uint2*>(
                Ab + (long)(j0 + 16 + jj) * kN + i0 + ii);
            const float* xp = Xb + (long)(j0 + 16 + jj) * F + f0 + ii;
            nx0 = *reinterpret_cast<const float4*>(xp);
            nx1 = *reinterpret_cast<const float4*>(xp + 4);
            djn = db[j0 + 16 + jj];
        }
#pragma unroll
        for (int s = 0; s < 2; s++) {
            int kk = s * 8 + tg;
            uint32_t af[2][4];
#pragma unroll
            for (int mt = 0; mt < 2; mt++) {
                int m = mw + mt * 16 + g;
                af[mt][0] = As[buf][kk][m];
                af[mt][1] = As[buf][kk][m + 8];
                af[mt][2] = As[buf][kk + 4][m];
                af[mt][3] = As[buf][kk + 4][m + 8];
            }
#pragma unroll
            for (int j = 0; j < 8; j++) {
                int n = nw + j * 8 + g;
                uint32_t b0 = Bs[buf][kk][n];
                uint32_t b1 = Bs[buf][kk + 4][n];
                mma_tf32(acc[0][j], af[0], b0, b1);
                mma_tf32(acc[1][j], af[1], b0, b1);
            }
        }
        if (more) {
            int nb = buf ^ 1;
            stTile(nb, nraw, nx0, nx1, djn);
            __syncthreads();
            buf = nb;
        }
    }

#pragma unroll
    for (int mt = 0; mt < 2; mt++) {
        int rowA = i0 + mw + mt * 16 + g;
        float diA = db[rowA], diB = db[rowA + 8];
#pragma unroll
        for (int j = 0; j < 8; j++) {
            int col = f0 + nw + j * 8 + 2 * tg;
            float2 bb = *reinterpret_cast<const float2*>(bias + col);
            float2 xA = *reinterpret_cast<const float2*>(Xb + (long)rowA * F + col);
            float2 xB = *reinterpret_cast<const float2*>(Xb + (long)(rowA + 8) * F + col);
            float v0 = diA * (acc[mt][j][0] + diA * xA.x) + bb.x;
            float v1 = diA * (acc[mt][j][1] + diA * xA.y) + bb.y;
            float v2 = diB * (acc[mt][j][2] + diB * xB.x) + bb.x;
            float v3 = diB * (acc[mt][j][3] + diB * xB.y) + bb.y;
            if (RELU) {
                v0 = fmaxf(v0, 0.f); v1 = fmaxf(v1, 0.f);
                v2 = fmaxf(v2, 0.f); v3 = fmaxf(v3, 0.f);
            }
            *reinterpret_cast<float2*>(Ob + (long)rowA * outStride + col) =
                make_float2(v0, v1);
            *reinterpret_cast<float2*>(Ob + (long)(rowA + 8) * outStride + col) =
                make_float2(v2, v3);
        }
    }
}

// ---------------------------------------------------------------------------
// fcn1 split-K + head
// ---------------------------------------------------------------------------
__global__ void k_fcn1(const float* __restrict__ emb, const float* __restrict__ W,
                       float* __restrict__ h1) {
    constexpr int KC = kKTOT / 128;
    __shared__ float As[16][32];
    __shared__ float Bs[16][64];
    int n0 = blockIdx.x * 64;
    int kbase = blockIdx.y * KC;
    int t = threadIdx.x;
    int m = t & 31;
    int nb = (t >> 5) << 3;
    float acc[8];
#pragma unroll
    for (int j = 0; j < 8; j++) acc[j] = 0.f;

    for (int k0 = kbase; k0 < kbase + KC; k0 += 16) {
        if (t < 128) {
            int row = t >> 2, c4 = (t & 3) << 2;
            float4 a = *reinterpret_cast<const float4*>(emb + (long)row * kKTOT + k0 + c4);
            As[c4 + 0][row] = a.x; As[c4 + 1][row] = a.y;
            As[c4 + 2][row] = a.z; As[c4 + 3][row] = a.w;
        }
        {
            int row = t >> 2, c4 = (t & 3) << 2;
            float4 b = *reinterpret_cast<const float4*>(W + (long)(n0 + row) * kKTOT + k0 + c4);
            Bs[c4 + 0][row] = b.x; Bs[c4 + 1][row] = b.y;
            Bs[c4 + 2][row] = b.z; Bs[c4 + 3][row] = b.w;
        }
        __syncthreads();
#pragma unroll
        for (int k = 0; k < 16; k++) {
            float a = As[k][m];
#pragma unroll
            for (int j = 0; j < 8; j++) acc[j] += a * Bs[k][nb + j];
        }
        __syncthreads();
    }
#pragma unroll
    for (int j = 0; j < 8; j++)
        atomicAdd(&h1[m * 256 + n0 + nb + j], acc[j]);
}

__global__ void k_fcn23(const float* __restrict__ h1g,
                        const float* __restrict__ b1, const float* __restrict__ w2,
                        const float* __restrict__ b2, const float* __restrict__ w3,
                        const float* __restrict__ b3, float* __restrict__ out) {
    __shared__ float h1s[32][256];
    __shared__ float h2s[32][32];
    int t = threadIdx.x;
    for (int idx = t; idx < 32 * 256; idx += 1024) {
        float v = h1g[idx] + b1[idx & 255];
        h1s[idx >> 8][idx & 255] = (v >= 0.f) ? v : 0.2f * v;
    }
    __syncthreads();
    {
        int b = t >> 5, o = t & 31;
        float s = 0.f;
#pragma unroll 8
        for (int k = 0; k < 256; k++) s += h1s[b][k] * w2[o * 256 + k];
        s += b2[o];
        h2s[b][o] = (s >= 0.f) ? s : 0.2f * s;
    }
    __syncthreads();
    if (t < 64) {
        int b = t >> 1, o = t & 1;
        float s = 0.f;
#pragma unroll
        for (int k = 0; k < 32; k++) s += h2s[b][k] * w3[o * 32 + k];
        out[b * 2 + o] = s + b3[o];
    }
}

// ---------------------------------------------------------------------------
// Launch
// ---------------------------------------------------------------------------
extern "C" void kernel_launch(void* const* d_in, const int* in_sizes, int n_in,
                              void* d_out, int out_size) {
    const float* x    = (const float*)d_in[0];
    const float* t    = (const float*)d_in[1];
    const float* gu   = (const float*)d_in[2];
    const int*   ei   = (const int*)d_in[3];
    const float* w1   = (const float*)d_in[4];
    const float* b1   = (const float*)d_in[5];
    const float* w2   = (const float*)d_in[6];
    const float* b2   = (const float*)d_in[7];
    const float* fcw  = (const float*)d_in[8];
    const float* fcb  = (const float*)d_in[9];
    const float* f1w  = (const float*)d_in[10];
    const float* f1b  = (const float*)d_in[11];
    const float* f2w  = (const float*)d_in[12];
    const float* f2b  = (const float*)d_in[13];
    const float* f3w  = (const float*)d_in[14];
    const float* f3b  = (const float*)d_in[15];
    float* out = (float*)d_out;

    const int* rowp = ei;
    const int* colp = ei + kE;

    float* base = nullptr;
    cudaGetSymbolAddress((void**)&base, g_scratch);
    float* p_E    = base + OFF_EG;
    float* p_F    = base + OFF_FG;
    unsigned char* p_A8 = (unsigned char*)(base + OFF_A8);
    float* p_disD = base + OFF_DISD;
    float* p_xw1  = base + OFF_XW1;     // shared: dense prop1 + sparse gather1
    float* p_h    = base + OFF_H;       // [H | SC1] contiguous
    float* p_sc1  = base + OFF_SC1;
    float* p_xw2  = base + OFF_XW2;     // [XW2 | XWS2] contiguous
    float* p_xws2 = base + OFF_XWS2;
    float* p_emb  = base + OFF_EMB;
    float* p_disS = base + OFF_DISS;
    int*   p_degS = (int*)(base + OFF_DEGS);
    float* p_h1   = base + OFF_H1;
    int*   p_ns   = (int*)(base + OFF_NS);
    int*   p_cur  = (int*)(base + OFF_CUR);
    int*   p_esrc = (int*)(base + OFF_ESRC);

    // 0-2: prep
    k_zeroS<<<64, 256>>>(p_degS, p_h1);
    k_lslr<<<kNTOT / 8, 256>>>(t, fcw, fcb, p_E, p_F);
    k_buildA<<<kBZ * kN * kN / 1024, 256>>>(gu, p_E, p_F, p_A8);

    // 3: shared layer-1 feature GEMM (dense AND sparse), flat M=16384
    k_gemm_tf32<false><<<dim3(kF1 / 128, kNTOT / 128, 1), 256>>>(
        x, 0, w1, p_xw1, 0, kF1, kN);

    // 4: dense degrees -> disD (direct)
    k_colsumD<<<dim3(kBZ, 4), 128>>>(p_A8, p_disD);

    // 5: dense prop layer 1 (captured by ncu -s 5)
    k_prop_tf32<true><<<dim3(kF1 / 128, kN / 128, kBZ), 256>>>(
        p_A8, p_xw1, p_disD, b1, p_h, kF1, kF1, 0);

    // 6-9: sparse degrees + CSR
    k_degS<<<kE / 256, 256>>>(colp, p_degS);
    k_disS<<<kNTOT / 256, 256>>>(p_degS, p_disS);
    k_scan<<<1, 1024>>>(p_degS, p_ns, p_cur);
    k_fill<<<kE / 256, 256>>>(rowp, colp, p_cur, p_esrc);

    // 10: sparse gather layer 1 (uses shared p_xw1)
    k_gather<2><<<kNTOT * 2 / 8, 256>>>(p_ns, p_esrc, p_xw1, p_disS, b1,
                                        p_sc1, kF1, 0);

    // 11: merged layer-2 feature GEMM over [H | SC1], M=32768
    k_gemm_tf32<true><<<dim3(kF2 / 128, 2 * kNTOT / 128, 1), 256>>>(
        p_h, 0, w2, p_xw2, 0, kF2, kF1);

    // 12: dense prop layer 2 -> emb[:, 0:128]
    k_prop_tf32<false><<<dim3(kF2 / 128, kN / 128, kBZ), 256>>>(
        p_A8, p_xw2, p_disD, b2, p_emb, kF2, 256, 0);

    // 13: sparse gather layer 2 -> emb[:, 128:256]
    k_gather<1><<<kNTOT / 8, 256>>>(p_ns, p_esrc, p_xws2, p_disS, b2,
                                    p_emb, 256, 128);

    // 14-15: MLP head
    k_fcn1<<<dim3(256 / 64, 128), 256>>>(p_emb, f1w, p_h1);
    k_fcn23<<<1, 1024>>>(p_h1, f1b, f2w, f2b, f3w, f3b, out);
}

// round 7
// speedup vs baseline: 1.0711x; 1.0711x over previous
#include <cuda_runtime.h>
#include <cstdint>

// ---------------------------------------------------------------------------
// Problem constants
// ---------------------------------------------------------------------------
constexpr int kN    = 512;
constexpr int kBZ   = 32;
constexpr int kTC   = 256;
constexpr int kF1   = 256;
constexpr int kF2   = 128;
constexpr int kE    = 524288;
constexpr int kNTOT = kBZ * kN;          // 16384
constexpr int kKTOT = kF2 * 2 * kN;      // 131072

// ---------------------------------------------------------------------------
// Scratch (offsets in floats).  H|SC1 adjacent, XW2|XWS2 adjacent (merged gemm2)
// ---------------------------------------------------------------------------
constexpr long OFF_EG   = 0;
constexpr long OFF_FG   = OFF_EG   + (long)kNTOT;
constexpr long OFF_A8   = OFF_FG   + (long)kNTOT;                // u8 view
constexpr long OFF_DISD = OFF_A8   + (long)kBZ * kN * kN / 4;
constexpr long OFF_DEGD = OFF_DISD + (long)kNTOT;
constexpr long OFF_XW1  = OFF_DEGD + (long)kNTOT;
constexpr long OFF_H    = OFF_XW1  + (long)kNTOT * kF1;
constexpr long OFF_SC1  = OFF_H    + (long)kNTOT * kF1;          // contiguous after H
constexpr long OFF_XW2  = OFF_SC1  + (long)kNTOT * kF1;
constexpr long OFF_XWS2 = OFF_XW2  + (long)kNTOT * kF2;          // contiguous after XW2
constexpr long OFF_EMB  = OFF_XWS2 + (long)kNTOT * kF2;
constexpr long OFF_DISS = OFF_EMB  + (long)kNTOT * 256;
constexpr long OFF_DEGS = OFF_DISS + (long)kNTOT;                // int
constexpr long OFF_H1   = OFF_DEGS + (long)kNTOT;
constexpr long OFF_NS   = OFF_H1   + (long)kBZ * 256;            // int, kNTOT+1
constexpr long OFF_CUR  = OFF_NS   + (long)kNTOT + 4;            // int
constexpr long OFF_ESRC = OFF_CUR  + (long)kNTOT;                // int, kE
constexpr long SCRATCH_FLOATS = OFF_ESRC + (long)kE;

__device__ __align__(16) float g_scratch[SCRATCH_FLOATS];

// ---------------------------------------------------------------------------
// tf32 / ldmatrix helpers
// ---------------------------------------------------------------------------
__device__ __forceinline__ uint32_t f2tf(float x) {
    uint32_t r;
    asm("cvt.rna.tf32.f32 %0, %1;" : "=r"(r) : "f"(x));
    return r;
}
__device__ __forceinline__ void mma_tf32(float* d, const uint32_t* a,
                                         uint32_t b0, uint32_t b1) {
    asm volatile(
        "mma.sync.aligned.m16n8k8.row.col.f32.tf32.tf32.f32 "
        "{%0,%1,%2,%3},{%4,%5,%6,%7},{%8,%9},{%0,%1,%2,%3};"
        : "+f"(d[0]), "+f"(d[1]), "+f"(d[2]), "+f"(d[3])
        : "r"(a[0]), "r"(a[1]), "r"(a[2]), "r"(a[3]), "r"(b0), "r"(b1));
}
__device__ __forceinline__ void ldsm4(uint32_t* r, uint32_t addr) {
    asm volatile("ldmatrix.sync.aligned.m8n8.x4.shared.b16 {%0,%1,%2,%3}, [%4];"
                 : "=r"(r[0]), "=r"(r[1]), "=r"(r[2]), "=r"(r[3]) : "r"(addr));
}
__device__ __forceinline__ uint32_t smem_u32(const void* p) {
    return (uint32_t)__cvta_generic_to_shared(p);
}

// ---------------------------------------------------------------------------
// Small kernels
// ---------------------------------------------------------------------------
__global__ void k_zero(int* degS, float* h1, float* degD) {
    int i = blockIdx.x * 256 + threadIdx.x;
    if (i < kNTOT) { degS[i] = 0; degD[i] = 1.f; }
    if (i < kBZ * 256) h1[i] = 0.f;
}

// per node: u=relu(t); E=exp(lr1-lr0+b1-b0), F=exp(ls1-ls0)
__global__ void k_lslr(const float* __restrict__ t, const float* __restrict__ fcw,
                       const float* __restrict__ fcb,
                       float* __restrict__ Eg, float* __restrict__ Fg) {
    int warp = (blockIdx.x * blockDim.x + threadIdx.x) >> 5;
    int lane = threadIdx.x & 31;
    if (warp >= kNTOT) return;
    const float* tn = t + (long)warp * kTC;
    const float* w0 = fcw;
    const float* w1 = fcw + 512;
    float s0 = 0.f, s1 = 0.f, r0 = 0.f, r1 = 0.f;
#pragma unroll
    for (int q = 0; q < 8; q++) {
        int d = lane + 32 * q;
        float u = fmaxf(tn[d], 0.f);
        s0 += u * w0[d];       s1 += u * w1[d];
        r0 += u * w0[256 + d]; r1 += u * w1[256 + d];
    }
#pragma unroll
    for (int off = 16; off; off >>= 1) {
        s0 += __shfl_down_sync(0xffffffffu, s0, off);
        s1 += __shfl_down_sync(0xffffffffu, s1, off);
        r0 += __shfl_down_sync(0xffffffffu, r0, off);
        r1 += __shfl_down_sync(0xffffffffu, r1, off);
    }
    if (lane == 0) {
        Eg[warp] = expf(r1 - r0 + fcb[1] - fcb[0]);
        Fg[warp] = expf(s1 - s0);
    }
}

// A8[b][i][j] = (y0>=y1) via l1 >= l0*E_i*F_j, l=-log(clamp(u)); fast log
__global__ void k_buildA(const float* __restrict__ gu,
                         const float* __restrict__ Eg, const float* __restrict__ Fg,
                         unsigned char* __restrict__ A8) {
    int idx = blockIdx.x * 256 + threadIdx.x;
    int j0 = (idx & 127) << 2;
    int i  = (idx >> 7) & 511;
    int b  = idx >> 16;
    float Ei = Eg[b * kN + i];
    float4 Fv = *reinterpret_cast<const float4*>(Fg + b * kN + j0);
    const float4* g4 = reinterpret_cast<const float4*>(
        gu + ((long)(b * kN + i) * kN + j0) * 2);
    float4 u01 = g4[0];
    float4 u23 = g4[1];
    auto bit = [&](float ux, float uy, float Fj) -> unsigned char {
        ux = fminf(fmaxf(ux, 1e-9f), 1.0f - 1e-9f);
        uy = fminf(fmaxf(uy, 1e-9f), 1.0f - 1e-9f);
        float l0 = -__logf(ux);
        float l1 = -__logf(uy);
        return (l1 >= l0 * Ei * Fj) ? 1 : 0;
    };
    uchar4 r;
    r.x = bit(u01.x, u01.y, Fv.x);
    r.y = bit(u01.z, u01.w, Fv.y);
    r.z = bit(u23.x, u23.y, Fv.z);
    r.w = bit(u23.z, u23.w, Fv.w);
    *reinterpret_cast<uchar4*>(A8 + (long)(b * kN + i) * kN + j0) = r;
}

// partial column sums of A8 (64 rows per block) -> atomic into degD (init 1.0)
__global__ void k_colsum_part(const unsigned char* __restrict__ A8,
                              float* __restrict__ degD) {
    int b = blockIdx.x;
    int j = threadIdx.x;
    int r0 = blockIdx.y * 64;
    const unsigned char* Ab = A8 + (long)b * kN * kN;
    int s = 0;
#pragma unroll 8
    for (int r = r0; r < r0 + 64; r++) s += Ab[(long)r * kN + j];
    atomicAdd(&degD[b * kN + j], (float)s);
}

__global__ void k_degS(const int* __restrict__ colp, int* degS) {
    int e = blockIdx.x * 256 + threadIdx.x;
    if (e < kE) atomicAdd(&degS[colp[e]], 1);
}

// disD = rsqrt(degD); disS = rsqrt(degS+1)
__global__ void k_dis(const float* __restrict__ degD, const int* __restrict__ degS,
                      float* __restrict__ disD, float* __restrict__ disS) {
    int i = blockIdx.x * 256 + threadIdx.x;
    if (i < kNTOT) {
        disD[i] = rsqrtf(degD[i]);
        disS[i] = rsqrtf((float)degS[i] + 1.f);
    }
}

// exclusive prefix-sum of degS -> nodeStart, cursor
__global__ void k_scan(const int* __restrict__ degS, int* __restrict__ ns,
                       int* __restrict__ cur) {
    __shared__ int sm[1024];
    int tid = threadIdx.x;
    int base = tid * 16;
    int local[16];
    int sum = 0;
#pragma unroll
    for (int v = 0; v < 16; v++) { local[v] = degS[base + v]; sum += local[v]; }
    sm[tid] = sum;
    __syncthreads();
    for (int off = 1; off < 1024; off <<= 1) {
        int v = (tid >= off) ? sm[tid - off] : 0;
        __syncthreads();
        sm[tid] += v;
        __syncthreads();
    }
    int run = sm[tid] - sum;
#pragma unroll
    for (int v = 0; v < 16; v++) {
        ns[base + v] = run;
        cur[base + v] = run;
        run += local[v];
    }
    if (tid == 1023) ns[kNTOT] = run;
}

__global__ void k_fill(const int* __restrict__ rowp, const int* __restrict__ colp,
                       int* cur, int* __restrict__ esrc) {
    int e = blockIdx.x * 256 + threadIdx.x;
    if (e < kE) {
        int c = colp[e];
        int p = atomicAdd(&cur[c], 1);
        esrc[p] = rowp[e];
    }
}

// ---------------------------------------------------------------------------
// CSR gather: WPN warps per node, 128 features each; 8-deep edge unroll
// ---------------------------------------------------------------------------
template <int WPN>
__global__ __launch_bounds__(256) void k_gather(
        const int* __restrict__ ns, const int* __restrict__ esrc,
        const float* __restrict__ xw, const float* __restrict__ disS,
        const float* __restrict__ bias, float* __restrict__ out,
        int outStride, int outOffset) {
    constexpr int F = WPN * 128;
    int gw = (blockIdx.x * 256 + threadIdx.x) >> 5;
    int lane = threadIdx.x & 31;
    int node = gw / WPN;
    int part = gw % WPN;
    if (node >= kNTOT) return;
    int off = part * 128 + lane * 4;
    float dc = disS[node];
    float4 acc;
    {
        float4 xv = *reinterpret_cast<const float4*>(xw + (long)node * F + off);
        float4 bb = *reinterpret_cast<const float4*>(bias + off);
        float d2 = dc * dc;
        acc = make_float4(xv.x * d2 + bb.x, xv.y * d2 + bb.y,
                          xv.z * d2 + bb.z, xv.w * d2 + bb.w);
    }
    int s = ns[node], e = ns[node + 1];
    int i = s;
    for (; i + 8 <= e; i += 8) {
        int r[8];
        float sc[8];
        float4 xv[8];
#pragma unroll
        for (int q = 0; q < 8; q++) r[q] = esrc[i + q];
#pragma unroll
        for (int q = 0; q < 8; q++) sc[q] = disS[r[q]] * dc;
#pragma unroll
        for (int q = 0; q < 8; q++)
            xv[q] = *reinterpret_cast<const float4*>(xw + (long)r[q] * F + off);
#pragma unroll
        for (int q = 0; q < 8; q++) {
            acc.x += xv[q].x * sc[q];
            acc.y += xv[q].y * sc[q];
            acc.z += xv[q].z * sc[q];
            acc.w += xv[q].w * sc[q];
        }
    }
    for (; i < e; i++) {
        int r = esrc[i];
        float sr = disS[r] * dc;
        float4 xv = *reinterpret_cast<const float4*>(xw + (long)r * F + off);
        acc.x += xv.x * sr; acc.y += xv.y * sr;
        acc.z += xv.z * sr; acc.w += xv.w * sr;
    }
    *reinterpret_cast<float4*>(out + (long)node * outStride + outOffset + off) = acc;
}

// ---------------------------------------------------------------------------
// tf32 NT GEMM with ldmatrix fragment loads: C[MxNf] = A[MxK] @ B[NfxK]^T
// ---------------------------------------------------------------------------
template <bool RELU_A>
__global__ __launch_bounds__(256) void k_gemm_tf32(
        const float* __restrict__ A, long aStride,
        const float* __restrict__ B,
        float* __restrict__ C, long cStride,
        int Nf, int K) {
    __shared__ uint32_t As[2][128][20];
    __shared__ uint32_t Bs[2][128][20];
    const float* Ab = A + (long)blockIdx.z * aStride;
    float* Cb = C + (long)blockIdx.z * cStride;
    int m0 = blockIdx.y * 128, n0 = blockIdx.x * 128;
    int t = threadIdx.x;
    int wid = t >> 5, lane = t & 31;
    int mw = (wid >> 1) * 32, nw = (wid & 1) * 64;
    int g = lane >> 2, tg = lane & 3;
    int lrow16 = lane & 15;
    int lhalf4 = (lane >> 4) * 4;
    int lr = t >> 2, lc = (t & 3) << 2;

    uint32_t sA[2] = { smem_u32(&As[0][0][0]), smem_u32(&As[1][0][0]) };
    uint32_t sB[2] = { smem_u32(&Bs[0][0][0]), smem_u32(&Bs[1][0][0]) };

    float acc[2][8][4];
#pragma unroll
    for (int i = 0; i < 2; i++)
#pragma unroll
        for (int j = 0; j < 8; j++)
#pragma unroll
            for (int c = 0; c < 4; c++) acc[i][j][c] = 0.f;

    const float* aP0 = Ab + (long)(m0 + lr) * K + lc;
    const float* aP1 = Ab + (long)(m0 + lr + 64) * K + lc;
    const float* bP0 = B + (long)(n0 + lr) * K + lc;
    const float* bP1 = B + (long)(n0 + lr + 64) * K + lc;

    auto cvt4 = [](float4 v, bool relu) -> uint4 {
        if (relu) {
            v.x = fmaxf(v.x, 0.f); v.y = fmaxf(v.y, 0.f);
            v.z = fmaxf(v.z, 0.f); v.w = fmaxf(v.w, 0.f);
        }
        uint4 r;
        r.x = f2tf(v.x); r.y = f2tf(v.y); r.z = f2tf(v.z); r.w = f2tf(v.w);
        return r;
    };

    {
        uint4 a0 = cvt4(*reinterpret_cast<const float4*>(aP0), RELU_A);
        uint4 a1 = cvt4(*reinterpret_cast<const float4*>(aP1), RELU_A);
        uint4 b0 = cvt4(*reinterpret_cast<const float4*>(bP0), false);
        uint4 b1 = cvt4(*reinterpret_cast<const float4*>(bP1), false);
        *reinterpret_cast<uint4*>(&As[0][lr][lc]) = a0;
        *reinterpret_cast<uint4*>(&As[0][lr + 64][lc]) = a1;
        *reinterpret_cast<uint4*>(&Bs[0][lr][lc]) = b0;
        *reinterpret_cast<uint4*>(&Bs[0][lr + 64][lc]) = b1;
    }
    __syncthreads();

    int buf = 0;
    for (int k0 = 0; k0 < K; k0 += 16) {
        bool more = (k0 + 16) < K;
        float4 na0, na1, nb0, nb1;
        if (more) {
            na0 = *reinterpret_cast<const float4*>(aP0 + k0 + 16);
            na1 = *reinterpret_cast<const float4*>(aP1 + k0 + 16);
            nb0 = *reinterpret_cast<const float4*>(bP0 + k0 + 16);
            nb1 = *reinterpret_cast<const float4*>(bP1 + k0 + 16);
        }
#pragma unroll
        for (int s = 0; s < 2; s++) {
            int kcol = s * 8 + lhalf4;
            uint32_t af0[4], af1[4];
            ldsm4(af0, sA[buf] + ((mw + lrow16) * 20 + kcol) * 4);
            ldsm4(af1, sA[buf] + ((mw + 16 + lrow16) * 20 + kcol) * 4);
#pragma unroll
            for (int p = 0; p < 4; p++) {
                uint32_t bf[4];
                ldsm4(bf, sB[buf] + ((nw + p * 16 + lrow16) * 20 + kcol) * 4);
                mma_tf32(acc[0][2 * p],     af0, bf[0], bf[2]);
                mma_tf32(acc[0][2 * p + 1], af0, bf[1], bf[3]);
                mma_tf32(acc[1][2 * p],     af1, bf[0], bf[2]);
                mma_tf32(acc[1][2 * p + 1], af1, bf[1], bf[3]);
            }
        }
        if (more) {
            int nb = buf ^ 1;
            *reinterpret_cast<uint4*>(&As[nb][lr][lc]) = cvt4(na0, RELU_A);
            *reinterpret_cast<uint4*>(&As[nb][lr + 64][lc]) = cvt4(na1, RELU_A);
            *reinterpret_cast<uint4*>(&Bs[nb][lr][lc]) = cvt4(nb0, false);
            *reinterpret_cast<uint4*>(&Bs[nb][lr + 64][lc]) = cvt4(nb1, false);
            __syncthreads();
            buf = nb;
        }
    }

#pragma unroll
    for (int mt = 0; mt < 2; mt++) {
        int row = m0 + mw + mt * 16 + g;
#pragma unroll
        for (int j = 0; j < 8; j++) {
            int col = n0 + nw + j * 8 + 2 * tg;
            *reinterpret_cast<float2*>(Cb + (long)row * Nf + col) =
                make_float2(acc[mt][j][0], acc[mt][j][1]);
            *reinterpret_cast<float2*>(Cb + (long)(row + 8) * Nf + col) =
                make_float2(acc[mt][j][2], acc[mt][j][3]);
        }
    }
}

// ---------------------------------------------------------------------------
// tf32 dense GCN propagation — A tiles loaded as uint8, expanded to tf32 one-bits
// ---------------------------------------------------------------------------
template <bool RELU>
__global__ __launch_bounds__(256) void k_prop_tf32(
        const unsigned char* __restrict__ Adj8, const float* __restrict__ XW,
        const float* __restrict__ dis, const float* __restrict__ bias,
        float* __restrict__ out, int F, int outStride, int outOffset) {
    __shared__ uint32_t As[2][16][136];
    __shared__ uint32_t Bs[2][16][136];
    int b = blockIdx.z;
    const unsigned char* Ab = Adj8 + (long)b * kN * kN;
    const float* Xb = XW + (long)b * kN * F;
    const float* db = dis + b * kN;
    float* Ob = out + (long)b * kN * outStride + outOffset;
    int i0 = blockIdx.y * 128, f0 = blockIdx.x * 128;
    int t = threadIdx.x;
    int wid = t >> 5, lane = t & 31;
    int mw = (wid >> 1) * 32, nw = (wid & 1) * 64;
    int g = lane >> 2, tg = lane & 3;
    int jj = t >> 4;
    int ii = (t & 15) << 3;

    float acc[2][8][4];
#pragma unroll
    for (int i = 0; i < 2; i++)
#pragma unroll
        for (int j = 0; j < 8; j++)
#pragma unroll
            for (int c = 0; c < 4; c++) acc[i][j][c] = 0.f;

    constexpr uint32_t ONE = 0x3F800000u;
    auto stTile = [&](int bufI, uint2 rawA, float4 x0, float4 x1, float dj) {
        uint4 ua0, ua1, ux0, ux1;
        ua0.x = (rawA.x & 0xffu)         ? ONE : 0u;
        ua0.y = ((rawA.x >> 8) & 0xffu)  ? ONE : 0u;
        ua0.z = ((rawA.x >> 16) & 0xffu) ? ONE : 0u;
        ua0.w = ((rawA.x >> 24) & 0xffu) ? ONE : 0u;
        ua1.x = (rawA.y & 0xffu)         ? ONE : 0u;
        ua1.y = ((rawA.y >> 8) & 0xffu)  ? ONE : 0u;
        ua1.z = ((rawA.y >> 16) & 0xffu) ? ONE : 0u;
        ua1.w = ((rawA.y >> 24) & 0xffu) ? ONE : 0u;
        ux0.x = f2tf(x0.x * dj); ux0.y = f2tf(x0.y * dj);
        ux0.z = f2tf(x0.z * dj); ux0.w = f2tf(x0.w * dj);
        ux1.x = f2tf(x1.x * dj); ux1.y = f2tf(x1.y * dj);
        ux1.z = f2tf(x1.z * dj); ux1.w = f2tf(x1.w * dj);
        *reinterpret_cast<uint4*>(&As[bufI][jj][ii]) = ua0;
        *reinterpret_cast<uint4*>(&As[bufI][jj][ii + 4]) = ua1;
        *reinterpret_cast<uint4*>(&Bs[bufI][jj][ii]) = ux0;
        *reinterpret_cast<uint4*>(&Bs[bufI][jj][ii + 4]) = ux1;
    };

    {
        uint2 rawA = *reinterpret_cast<const uint2*>(Ab + (long)jj * kN + i0 + ii);
        const float* xp = Xb + (long)jj * F + f0 + ii;
        stTile(0, rawA,
               *reinterpret_cast<const float4*>(xp),
               *reinterpret_cast<const float4*>(xp + 4),
               db[jj]);
    }
    __syncthreads();

    int buf = 0;
    for (int j0 = 0; j0 < kN; j0 += 16) {
        bool more = (j0 + 16) < kN;
        uint2 nraw;
        float4 nx0, nx1;
        float djn = 0.f;
        if (more) {
            nraw = *reinterpret_cast<const uint2*>(
                Ab + (long)(j0 + 16 + jj) * kN + i0 + ii);
            const float* xp = Xb + (long)(j0 + 16 + jj) * F + f0 + ii;
            nx0 = *reinterpret_cast<const float4*>(xp);
            nx1 = *reinterpret_cast<const float4*>(xp + 4);
            djn = db[j0 + 16 + jj];
        }
#pragma unroll
        for (int s = 0; s < 2; s++) {
            int kk = s * 8 + tg;
            uint32_t af[2][4];
#pragma unroll
            for (int mt = 0; mt < 2; mt++) {
                int m = mw + mt * 16 + g;
                af[mt][0] = As[buf][kk][m];
                af[mt][1] = As[buf][kk][m + 8];
                af[mt][2] = As[buf][kk + 4][m];
                af[mt][3] = As[buf][kk + 4][m + 8];
            }
#pragma unroll
            for (int j = 0; j < 8; j++) {
                int n = nw + j * 8 + g;
                uint32_t b0 = Bs[buf][kk][n];
                uint32_t b1 = Bs[buf][kk + 4][n];
                mma_tf32(acc[0][j], af[0], b0, b1);
                mma_tf32(acc[1][j], af[1], b0, b1);
            }
        }
        if (more) {
            int nb = buf ^ 1;
            stTile(nb, nraw, nx0, nx1, djn);
            __syncthreads();
            buf = nb;
        }
    }

#pragma unroll
    for (int mt = 0; mt < 2; mt++) {
        int rowA = i0 + mw + mt * 16 + g;
        float diA = db[rowA], diB = db[rowA + 8];
#pragma unroll
        for (int j = 0; j < 8; j++) {
            int col = f0 + nw + j * 8 + 2 * tg;
            float2 bb = *reinterpret_cast<const float2*>(bias + col);
            float2 xA = *reinterpret_cast<const float2*>(Xb + (long)rowA * F + col);
            float2 xB = *reinterpret_cast<const float2*>(Xb + (long)(rowA + 8) * F + col);
            float v0 = diA * (acc[mt][j][0] + diA * xA.x) + bb.x;
            float v1 = diA * (acc[mt][j][1] + diA * xA.y) + bb.y;
            float v2 = diB * (acc[mt][j][2] + diB * xB.x) + bb.x;
            float v3 = diB * (acc[mt][j][3] + diB * xB.y) + bb.y;
            if (RELU) {
                v0 = fmaxf(v0, 0.f); v1 = fmaxf(v1, 0.f);
                v2 = fmaxf(v2, 0.f); v3 = fmaxf(v3, 0.f);
            }
            *reinterpret_cast<float2*>(Ob + (long)rowA * outStride + col) =
                make_float2(v0, v1);
            *reinterpret_cast<float2*>(Ob + (long)(rowA + 8) * outStride + col) =
                make_float2(v2, v3);
        }
    }
}

// ---------------------------------------------------------------------------
// fcn1 split-K + head
// ---------------------------------------------------------------------------
__global__ void k_fcn1(const float* __restrict__ emb, const float* __restrict__ W,
                       float* __restrict__ h1) {
    constexpr int KC = kKTOT / 128;
    __shared__ float As[16][32];
    __shared__ float Bs[16][64];
    int n0 = blockIdx.x * 64;
    int kbase = blockIdx.y * KC;
    int t = threadIdx.x;
    int m = t & 31;
    int nb = (t >> 5) << 3;
    float acc[8];
#pragma unroll
    for (int j = 0; j < 8; j++) acc[j] = 0.f;

    for (int k0 = kbase; k0 < kbase + KC; k0 += 16) {
        if (t < 128) {
            int row = t >> 2, c4 = (t & 3) << 2;
            float4 a = *reinterpret_cast<const float4*>(emb + (long)row * kKTOT + k0 + c4);
            As[c4 + 0][row] = a.x; As[c4 + 1][row] = a.y;
            As[c4 + 2][row] = a.z; As[c4 + 3][row] = a.w;
        }
        {
            int row = t >> 2, c4 = (t & 3) << 2;
            float4 b = *reinterpret_cast<const float4*>(W + (long)(n0 + row) * kKTOT + k0 + c4);
            Bs[c4 + 0][row] = b.x; Bs[c4 + 1][row] = b.y;
            Bs[c4 + 2][row] = b.z; Bs[c4 + 3][row] = b.w;
        }
        __syncthreads();
#pragma unroll
        for (int k = 0; k < 16; k++) {
            float a = As[k][m];
#pragma unroll
            for (int j = 0; j < 8; j++) acc[j] += a * Bs[k][nb + j];
        }
        __syncthreads();
    }
#pragma unroll
    for (int j = 0; j < 8; j++)
        atomicAdd(&h1[m * 256 + n0 + nb + j], acc[j]);
}

__global__ void k_fcn23(const float* __restrict__ h1g,
                        const float* __restrict__ b1, const float* __restrict__ w2,
                        const float* __restrict__ b2, const float* __restrict__ w3,
                        const float* __restrict__ b3, float* __restrict__ out) {
    __shared__ float h1s[32][256];
    __shared__ float h2s[32][32];
    int t = threadIdx.x;
    for (int idx = t; idx < 32 * 256; idx += 1024) {
        float v = h1g[idx] + b1[idx & 255];
        h1s[idx >> 8][idx & 255] = (v >= 0.f) ? v : 0.2f * v;
    }
    __syncthreads();
    {
        int b = t >> 5, o = t & 31;
        float s = 0.f;
#pragma unroll 8
        for (int k = 0; k < 256; k++) s += h1s[b][k] * w2[o * 256 + k];
        s += b2[o];
        h2s[b][o] = (s >= 0.f) ? s : 0.2f * s;
    }
    __syncthreads();
    if (t < 64) {
        int b = t >> 1, o = t & 1;
        float s = 0.f;
#pragma unroll
        for (int k = 0; k < 32; k++) s += h2s[b][k] * w3[o * 32 + k];
        out[b * 2 + o] = s + b3[o];
    }
}

// ---------------------------------------------------------------------------
// Launch
// ---------------------------------------------------------------------------
extern "C" void kernel_launch(void* const* d_in, const int* in_sizes, int n_in,
                              void* d_out, int out_size) {
    const float* x    = (const float*)d_in[0];
    const float* t    = (const float*)d_in[1];
    const float* gu   = (const float*)d_in[2];
    const int*   ei   = (const int*)d_in[3];
    const float* w1   = (const float*)d_in[4];
    const float* b1   = (const float*)d_in[5];
    const float* w2   = (const float*)d_in[6];
    const float* b2   = (const float*)d_in[7];
    const float* fcw  = (const float*)d_in[8];
    const float* fcb  = (const float*)d_in[9];
    const float* f1w  = (const float*)d_in[10];
    const float* f1b  = (const float*)d_in[11];
    const float* f2w  = (const float*)d_in[12];
    const float* f2b  = (const float*)d_in[13];
    const float* f3w  = (const float*)d_in[14];
    const float* f3b  = (const float*)d_in[15];
    float* out = (float*)d_out;

    const int* rowp = ei;
    const int* colp = ei + kE;

    float* base = nullptr;
    cudaGetSymbolAddress((void**)&base, g_scratch);
    float* p_E    = base + OFF_EG;
    float* p_F    = base + OFF_FG;
    unsigned char* p_A8 = (unsigned char*)(base + OFF_A8);
    float* p_disD = base + OFF_DISD;
    float* p_degD = base + OFF_DEGD;
    float* p_xw1  = base + OFF_XW1;     // shared: dense prop1 + sparse gather1
    float* p_h    = base + OFF_H;       // [H | SC1] contiguous
    float* p_sc1  = base + OFF_SC1;
    float* p_xw2  = base + OFF_XW2;     // [XW2 | XWS2] contiguous
    float* p_xws2 = base + OFF_XWS2;
    float* p_emb  = base + OFF_EMB;
    float* p_disS = base + OFF_DISS;
    int*   p_degS = (int*)(base + OFF_DEGS);
    float* p_h1   = base + OFF_H1;
    int*   p_ns   = (int*)(base + OFF_NS);
    int*   p_cur  = (int*)(base + OFF_CUR);
    int*   p_esrc = (int*)(base + OFF_ESRC);

    // prep
    k_zero<<<64, 256>>>(p_degS, p_h1, p_degD);
    k_lslr<<<kNTOT / 8, 256>>>(t, fcw, fcb, p_E, p_F);
    k_buildA<<<kBZ * kN * kN / 1024, 256>>>(gu, p_E, p_F, p_A8);

    // shared layer-1 feature GEMM (dense AND sparse), flat M=16384
    k_gemm_tf32<false><<<dim3(kF1 / 128, kNTOT / 128, 1), 256>>>(
        x, 0, w1, p_xw1, 0, kF1, kN);

    // degrees + CSR
    k_colsum_part<<<dim3(kBZ, 8), kN>>>(p_A8, p_degD);
    k_degS<<<kE / 256, 256>>>(colp, p_degS);
    k_dis<<<kNTOT / 256, 256>>>(p_degD, p_degS, p_disD, p_disS);
    k_scan<<<1, 1024>>>(p_degS, p_ns, p_cur);
    k_fill<<<kE / 256, 256>>>(rowp, colp, p_cur, p_esrc);

    // dense prop layer 1
    k_prop_tf32<true><<<dim3(kF1 / 128, kN / 128, kBZ), 256>>>(
        p_A8, p_xw1, p_disD, b1, p_h, kF1, kF1, 0);

    // sparse gather layer 1 (uses shared p_xw1)
    k_gather<2><<<kNTOT * 2 / 8, 256>>>(p_ns, p_esrc, p_xw1, p_disS, b1,
                                        p_sc1, kF1, 0);

    // merged layer-2 feature GEMM over [H | SC1], M=32768
    k_gemm_tf32<true><<<dim3(kF2 / 128, 2 * kNTOT / 128, 1), 256>>>(
        p_h, 0, w2, p_xw2, 0, kF2, kF1);

    // dense prop layer 2 -> emb[:, 0:128]
    k_prop_tf32<false><<<dim3(kF2 / 128, kN / 128, kBZ), 256>>>(
        p_A8, p_xw2, p_disD, b2, p_emb, kF2, 256, 0);

    // sparse gather layer 2 -> emb[:, 128:256]
    k_gather<1><<<kNTOT / 8, 256>>>(p_ns, p_esrc, p_xws2, p_disS, b2,
                                    p_emb, 256, 128);

    // MLP head
    k_fcn1<<<dim3(256 / 64, 128), 256>>>(p_emb, f1w, p_h1);
    k_fcn23<<<1, 1024>>>(p_h1, f1b, f2w, f2b, f3w, f3b, out);
}

// round 8
// speedup vs baseline: 1.0781x; 1.0065x over previous
#include <cuda_runtime.h>
#include <cuda_fp16.h>
#include <cstdint>

// ---------------------------------------------------------------------------
// Problem constants
// ---------------------------------------------------------------------------
constexpr int kN    = 512;
constexpr int kBZ   = 32;
constexpr int kTC   = 256;
constexpr int kF1   = 256;
constexpr int kF2   = 128;
constexpr int kE    = 524288;
constexpr int kNTOT = kBZ * kN;          // 16384
constexpr int kKTOT = kF2 * 2 * kN;      // 131072

// ---------------------------------------------------------------------------
// Scratch (offsets in floats)
// ---------------------------------------------------------------------------
constexpr long OFF_EG   = 0;
constexpr long OFF_FG   = OFF_EG   + (long)kNTOT;
constexpr long OFF_A8   = OFF_FG   + (long)kNTOT;                // u8 view
constexpr long OFF_DISD = OFF_A8   + (long)kBZ * kN * kN / 4;
constexpr long OFF_DEGD = OFF_DISD + (long)kNTOT;
constexpr long OFF_XW1  = OFF_DEGD + (long)kNTOT;
constexpr long OFF_H    = OFF_XW1  + (long)kNTOT * kF1;
constexpr long OFF_SC1  = OFF_H    + (long)kNTOT * kF1;          // contiguous after H
constexpr long OFF_XW2  = OFF_SC1  + (long)kNTOT * kF1;
constexpr long OFF_XWS2 = OFF_XW2  + (long)kNTOT * kF2;          // contiguous after XW2
constexpr long OFF_EMB  = OFF_XWS2 + (long)kNTOT * kF2;
constexpr long OFF_DISS = OFF_EMB  + (long)kNTOT * 256;
constexpr long OFF_DEGS = OFF_DISS + (long)kNTOT;                // int
constexpr long OFF_H1   = OFF_DEGS + (long)kNTOT;
constexpr long OFF_NS   = OFF_H1   + (long)kBZ * 256;            // int, kNTOT+1
constexpr long OFF_CUR  = OFF_NS   + (long)kNTOT + 4;            // int
constexpr long OFF_ESRC = OFF_CUR  + (long)kNTOT;                // int, kE
constexpr long OFF_XW1H = OFF_ESRC + (long)kE;                   // half, kNTOT*kF1
constexpr long OFF_XWS2H= OFF_XW1H + (long)kNTOT * kF1 / 2;      // half, kNTOT*kF2
constexpr long SCRATCH_FLOATS = OFF_XWS2H + (long)kNTOT * kF2 / 2;

__device__ __align__(16) float g_scratch[SCRATCH_FLOATS];

// ---------------------------------------------------------------------------
// tf32 / ldmatrix helpers
// ---------------------------------------------------------------------------
__device__ __forceinline__ uint32_t f2tf(float x) {
    uint32_t r;
    asm("cvt.rna.tf32.f32 %0, %1;" : "=r"(r) : "f"(x));
    return r;
}
__device__ __forceinline__ void mma_tf32(float* d, const uint32_t* a,
                                         uint32_t b0, uint32_t b1) {
    asm volatile(
        "mma.sync.aligned.m16n8k8.row.col.f32.tf32.tf32.f32 "
        "{%0,%1,%2,%3},{%4,%5,%6,%7},{%8,%9},{%0,%1,%2,%3};"
        : "+f"(d[0]), "+f"(d[1]), "+f"(d[2]), "+f"(d[3])
        : "r"(a[0]), "r"(a[1]), "r"(a[2]), "r"(a[3]), "r"(b0), "r"(b1));
}
__device__ __forceinline__ void ldsm4(uint32_t* r, uint32_t addr) {
    asm volatile("ldmatrix.sync.aligned.m8n8.x4.shared.b16 {%0,%1,%2,%3}, [%4];"
                 : "=r"(r[0]), "=r"(r[1]), "=r"(r[2]), "=r"(r[3]) : "r"(addr));
}
__device__ __forceinline__ uint32_t smem_u32(const void* p) {
    return (uint32_t)__cvta_generic_to_shared(p);
}

// ---------------------------------------------------------------------------
// Small kernels
// ---------------------------------------------------------------------------
__global__ void k_zero(int* degS, float* h1, float* degD) {
    int i = blockIdx.x * 256 + threadIdx.x;
    if (i < kNTOT) { degS[i] = 0; degD[i] = 1.f; }
    if (i < kBZ * 256) h1[i] = 0.f;
}

__global__ void k_lslr(const float* __restrict__ t, const float* __restrict__ fcw,
                       const float* __restrict__ fcb,
                       float* __restrict__ Eg, float* __restrict__ Fg) {
    int warp = (blockIdx.x * blockDim.x + threadIdx.x) >> 5;
    int lane = threadIdx.x & 31;
    if (warp >= kNTOT) return;
    const float* tn = t + (long)warp * kTC;
    const float* w0 = fcw;
    const float* w1 = fcw + 512;
    float s0 = 0.f, s1 = 0.f, r0 = 0.f, r1 = 0.f;
#pragma unroll
    for (int q = 0; q < 8; q++) {
        int d = lane + 32 * q;
        float u = fmaxf(tn[d], 0.f);
        s0 += u * w0[d];       s1 += u * w1[d];
        r0 += u * w0[256 + d]; r1 += u * w1[256 + d];
    }
#pragma unroll
    for (int off = 16; off; off >>= 1) {
        s0 += __shfl_down_sync(0xffffffffu, s0, off);
        s1 += __shfl_down_sync(0xffffffffu, s1, off);
        r0 += __shfl_down_sync(0xffffffffu, r0, off);
        r1 += __shfl_down_sync(0xffffffffu, r1, off);
    }
    if (lane == 0) {
        Eg[warp] = expf(r1 - r0 + fcb[1] - fcb[0]);
        Fg[warp] = expf(s1 - s0);
    }
}

__global__ void k_buildA(const float* __restrict__ gu,
                         const float* __restrict__ Eg, const float* __restrict__ Fg,
                         unsigned char* __restrict__ A8) {
    int idx = blockIdx.x * 256 + threadIdx.x;
    int j0 = (idx & 127) << 2;
    int i  = (idx >> 7) & 511;
    int b  = idx >> 16;
    float Ei = Eg[b * kN + i];
    float4 Fv = *reinterpret_cast<const float4*>(Fg + b * kN + j0);
    const float4* g4 = reinterpret_cast<const float4*>(
        gu + ((long)(b * kN + i) * kN + j0) * 2);
    float4 u01 = g4[0];
    float4 u23 = g4[1];
    auto bit = [&](float ux, float uy, float Fj) -> unsigned char {
        ux = fminf(fmaxf(ux, 1e-9f), 1.0f - 1e-9f);
        uy = fminf(fmaxf(uy, 1e-9f), 1.0f - 1e-9f);
        float l0 = -__logf(ux);
        float l1 = -__logf(uy);
        return (l1 >= l0 * Ei * Fj) ? 1 : 0;
    };
    uchar4 r;
    r.x = bit(u01.x, u01.y, Fv.x);
    r.y = bit(u01.z, u01.w, Fv.y);
    r.z = bit(u23.x, u23.y, Fv.z);
    r.w = bit(u23.z, u23.w, Fv.w);
    *reinterpret_cast<uchar4*>(A8 + (long)(b * kN + i) * kN + j0) = r;
}

__global__ void k_colsum_part(const unsigned char* __restrict__ A8,
                              float* __restrict__ degD) {
    int b = blockIdx.x;
    int j = threadIdx.x;
    int r0 = blockIdx.y * 64;
    const unsigned char* Ab = A8 + (long)b * kN * kN;
    int s = 0;
#pragma unroll 8
    for (int r = r0; r < r0 + 64; r++) s += Ab[(long)r * kN + j];
    atomicAdd(&degD[b * kN + j], (float)s);
}

__global__ void k_degS(const int* __restrict__ colp, int* degS) {
    int e = blockIdx.x * 256 + threadIdx.x;
    if (e < kE) atomicAdd(&degS[colp[e]], 1);
}

__global__ void k_dis(const float* __restrict__ degD, const int* __restrict__ degS,
                      float* __restrict__ disD, float* __restrict__ disS) {
    int i = blockIdx.x * 256 + threadIdx.x;
    if (i < kNTOT) {
        disD[i] = rsqrtf(degD[i]);
        disS[i] = rsqrtf((float)degS[i] + 1.f);
    }
}

__global__ void k_scan(const int* __restrict__ degS, int* __restrict__ ns,
                       int* __restrict__ cur) {
    __shared__ int sm[1024];
    int tid = threadIdx.x;
    int base = tid * 16;
    int local[16];
    int sum = 0;
#pragma unroll
    for (int v = 0; v < 16; v++) { local[v] = degS[base + v]; sum += local[v]; }
    sm[tid] = sum;
    __syncthreads();
    for (int off = 1; off < 1024; off <<= 1) {
        int v = (tid >= off) ? sm[tid - off] : 0;
        __syncthreads();
        sm[tid] += v;
        __syncthreads();
    }
    int run = sm[tid] - sum;
#pragma unroll
    for (int v = 0; v < 16; v++) {
        ns[base + v] = run;
        cur[base + v] = run;
        run += local[v];
    }
    if (tid == 1023) ns[kNTOT] = run;
}

__global__ void k_fill(const int* __restrict__ rowp, const int* __restrict__ colp,
                       int* cur, int* __restrict__ esrc) {
    int e = blockIdx.x * 256 + threadIdx.x;
    if (e < kE) {
        int c = colp[e];
        int p = atomicAdd(&cur[c], 1);
        esrc[p] = rowp[e];
    }
}

// ---------------------------------------------------------------------------
// fp16 CSR gather: one warp per node; VH half2 per lane (F = VH*64).
// out[c](fp32) = xwh[c]*dis[c]^2 + bias + sum_e xwh[r]*dis[r]*dis[c]
// ---------------------------------------------------------------------------
template <int VH>   // 4 -> F=256 (16B/lane), 2 -> F=128 (8B/lane)
__global__ __launch_bounds__(256) void k_gather_h(
        const int* __restrict__ ns, const int* __restrict__ esrc,
        const __half2* __restrict__ xwh, const float* __restrict__ disS,
        const float* __restrict__ bias, float* __restrict__ out,
        int outStride, int outOffset) {
    constexpr int F2 = VH * 32;    // half2 per row
    int node = (blockIdx.x * 256 + threadIdx.x) >> 5;
    int lane = threadIdx.x & 31;
    if (node >= kNTOT) return;
    int off2 = lane * VH;
    float dc = disS[node];
    float2 acc[VH];

    auto loadrow = [&](long r, uint32_t* rw) {
        const char* p = reinterpret_cast<const char*>(xwh + r * F2 + off2);
        if (VH == 4) {
            uint4 u = *reinterpret_cast<const uint4*>(p);
            rw[0] = u.x; rw[1] = u.y; rw[2] = u.z; rw[3] = u.w;
        } else {
            uint2 u = *reinterpret_cast<const uint2*>(p);
            rw[0] = u.x; rw[1] = u.y;
        }
    };

    {
        uint32_t rw[VH];
        loadrow(node, rw);
        float d2 = dc * dc;
#pragma unroll
        for (int v = 0; v < VH; v++) {
            float2 xv = __half22float2(*reinterpret_cast<__half2*>(&rw[v]));
            float2 bb = *reinterpret_cast<const float2*>(bias + (off2 + v) * 2);
            acc[v] = make_float2(xv.x * d2 + bb.x, xv.y * d2 + bb.y);
        }
    }
    int s = ns[node], e = ns[node + 1];
    int i = s;
    for (; i + 8 <= e; i += 8) {
        int r[8];
        float sc[8];
        uint32_t rw[8][VH];
#pragma unroll
        for (int q = 0; q < 8; q++) r[q] = esrc[i + q];
#pragma unroll
        for (int q = 0; q < 8; q++) sc[q] = disS[r[q]] * dc;
#pragma unroll
        for (int q = 0; q < 8; q++) loadrow(r[q], rw[q]);
#pragma unroll
        for (int q = 0; q < 8; q++)
#pragma unroll
            for (int v = 0; v < VH; v++) {
                float2 xv = __half22float2(*reinterpret_cast<__half2*>(&rw[q][v]));
                acc[v].x += xv.x * sc[q];
                acc[v].y += xv.y * sc[q];
            }
    }
    for (; i < e; i++) {
        int r = esrc[i];
        float sr = disS[r] * dc;
        uint32_t rw[VH];
        loadrow(r, rw);
#pragma unroll
        for (int v = 0; v < VH; v++) {
            float2 xv = __half22float2(*reinterpret_cast<__half2*>(&rw[v]));
            acc[v].x += xv.x * sr;
            acc[v].y += xv.y * sr;
        }
    }
    float* op = out + (long)node * outStride + outOffset + off2 * 2;
#pragma unroll
    for (int v = 0; v < VH; v++)
        *reinterpret_cast<float2*>(op + v * 2) = acc[v];
}

// ---------------------------------------------------------------------------
// tf32 NT GEMM with ldmatrix fragment loads + optional fp16 mirror output.
// C[MxNf] = A[MxK] @ B[NfxK]^T ; Ch (if non-null) mirrors rows >= hRowStart.
// ---------------------------------------------------------------------------
template <bool RELU_A>
__global__ __launch_bounds__(256) void k_gemm_tf32(
        const float* __restrict__ A, long aStride,
        const float* __restrict__ B,
        float* __restrict__ C, long cStride,
        int Nf, int K, __half* __restrict__ Ch, int hRowStart) {
    __shared__ uint32_t As[2][128][20];
    __shared__ uint32_t Bs[2][128][20];
    const float* Ab = A + (long)blockIdx.z * aStride;
    float* Cb = C + (long)blockIdx.z * cStride;
    int m0 = blockIdx.y * 128, n0 = blockIdx.x * 128;
    int t = threadIdx.x;
    int wid = t >> 5, lane = t & 31;
    int mw = (wid >> 1) * 32, nw = (wid & 1) * 64;
    int g = lane >> 2, tg = lane & 3;
    int lrow16 = lane & 15;
    int lhalf4 = (lane >> 4) * 4;
    int lr = t >> 2, lc = (t & 3) << 2;

    uint32_t sA[2] = { smem_u32(&As[0][0][0]), smem_u32(&As[1][0][0]) };
    uint32_t sB[2] = { smem_u32(&Bs[0][0][0]), smem_u32(&Bs[1][0][0]) };

    float acc[2][8][4];
#pragma unroll
    for (int i = 0; i < 2; i++)
#pragma unroll
        for (int j = 0; j < 8; j++)
#pragma unroll
            for (int c = 0; c < 4; c++) acc[i][j][c] = 0.f;

    const float* aP0 = Ab + (long)(m0 + lr) * K + lc;
    const float* aP1 = Ab + (long)(m0 + lr + 64) * K + lc;
    const float* bP0 = B + (long)(n0 + lr) * K + lc;
    const float* bP1 = B + (long)(n0 + lr + 64) * K + lc;

    auto cvt4 = [](float4 v, bool relu) -> uint4 {
        if (relu) {
            v.x = fmaxf(v.x, 0.f); v.y = fmaxf(v.y, 0.f);
            v.z = fmaxf(v.z, 0.f); v.w = fmaxf(v.w, 0.f);
        }
        uint4 r;
        r.x = f2tf(v.x); r.y = f2tf(v.y); r.z = f2tf(v.z); r.w = f2tf(v.w);
        return r;
    };

    {
        uint4 a0 = cvt4(*reinterpret_cast<const float4*>(aP0), RELU_A);
        uint4 a1 = cvt4(*reinterpret_cast<const float4*>(aP1), RELU_A);
        uint4 b0 = cvt4(*reinterpret_cast<const float4*>(bP0), false);
        uint4 b1 = cvt4(*reinterpret_cast<const float4*>(bP1), false);
        *reinterpret_cast<uint4*>(&As[0][lr][lc]) = a0;
        *reinterpret_cast<uint4*>(&As[0][lr + 64][lc]) = a1;
        *reinterpret_cast<uint4*>(&Bs[0][lr][lc]) = b0;
        *reinterpret_cast<uint4*>(&Bs[0][lr + 64][lc]) = b1;
    }
    __syncthreads();

    int buf = 0;
    for (int k0 = 0; k0 < K; k0 += 16) {
        bool more = (k0 + 16) < K;
        float4 na0, na1, nb0, nb1;
        if (more) {
            na0 = *reinterpret_cast<const float4*>(aP0 + k0 + 16);
            na1 = *reinterpret_cast<const float4*>(aP1 + k0 + 16);
            nb0 = *reinterpret_cast<const float4*>(bP0 + k0 + 16);
            nb1 = *reinterpret_cast<const float4*>(bP1 + k0 + 16);
        }
#pragma unroll
        for (int s = 0; s < 2; s++) {
            int kcol = s * 8 + lhalf4;
            uint32_t af0[4], af1[4];
            ldsm4(af0, sA[buf] + ((mw + lrow16) * 20 + kcol) * 4);
            ldsm4(af1, sA[buf] + ((mw + 16 + lrow16) * 20 + kcol) * 4);
#pragma unroll
            for (int p = 0; p < 4; p++) {
                uint32_t bf[4];
                ldsm4(bf, sB[buf] + ((nw + p * 16 + lrow16) * 20 + kcol) * 4);
                mma_tf32(acc[0][2 * p],     af0, bf[0], bf[2]);
                mma_tf32(acc[0][2 * p + 1], af0, bf[1], bf[3]);
                mma_tf32(acc[1][2 * p],     af1, bf[0], bf[2]);
                mma_tf32(acc[1][2 * p + 1], af1, bf[1], bf[3]);
            }
        }
        if (more) {
            int nb = buf ^ 1;
            *reinterpret_cast<uint4*>(&As[nb][lr][lc]) = cvt4(na0, RELU_A);
            *reinterpret_cast<uint4*>(&As[nb][lr + 64][lc]) = cvt4(na1, RELU_A);
            *reinterpret_cast<uint4*>(&Bs[nb][lr][lc]) = cvt4(nb0, false);
            *reinterpret_cast<uint4*>(&Bs[nb][lr + 64][lc]) = cvt4(nb1, false);
            __syncthreads();
            buf = nb;
        }
    }

    bool doH = (Ch != nullptr) && (m0 >= hRowStart);
#pragma unroll
    for (int mt = 0; mt < 2; mt++) {
        int row = m0 + mw + mt * 16 + g;
#pragma unroll
        for (int j = 0; j < 8; j++) {
            int col = n0 + nw + j * 8 + 2 * tg;
            float2 v0 = make_float2(acc[mt][j][0], acc[mt][j][1]);
            float2 v1 = make_float2(acc[mt][j][2], acc[mt][j][3]);
            *reinterpret_cast<float2*>(Cb + (long)row * Nf + col) = v0;
            *reinterpret_cast<float2*>(Cb + (long)(row + 8) * Nf + col) = v1;
            if (doH) {
                long hr = row - hRowStart;
                *reinterpret_cast<__half2*>(Ch + hr * Nf + col) =
                    __floats2half2_rn(v0.x, v0.y);
                *reinterpret_cast<__half2*>(Ch + (hr + 8) * Nf + col) =
                    __floats2half2_rn(v1.x, v1.y);
            }
        }
    }
}

// ---------------------------------------------------------------------------
// tf32 dense GCN propagation — A tiles loaded as uint8, expanded to tf32 one-bits
// ---------------------------------------------------------------------------
template <bool RELU>
__global__ __launch_bounds__(256) void k_prop_tf32(
        const unsigned char* __restrict__ Adj8, const float* __restrict__ XW,
        const float* __restrict__ dis, const float* __restrict__ bias,
        float* __restrict__ out, int F, int outStride, int outOffset) {
    __shared__ uint32_t As[2][16][136];
    __shared__ uint32_t Bs[2][16][136];
    int b = blockIdx.z;
    const unsigned char* Ab = Adj8 + (long)b * kN * kN;
    const float* Xb = XW + (long)b * kN * F;
    const float* db = dis + b * kN;
    float* Ob = out + (long)b * kN * outStride + outOffset;
    int i0 = blockIdx.y * 128, f0 = blockIdx.x * 128;
    int t = threadIdx.x;
    int wid = t >> 5, lane = t & 31;
    int mw = (wid >> 1) * 32, nw = (wid & 1) * 64;
    int g = lane >> 2, tg = lane & 3;
    int jj = t >> 4;
    int ii = (t & 15) << 3;

    float acc[2][8][4];
#pragma unroll
    for (int i = 0; i < 2; i++)
#pragma unroll
        for (int j = 0; j < 8; j++)
#pragma unroll
            for (int c = 0; c < 4; c++) acc[i][j][c] = 0.f;

    constexpr uint32_t ONE = 0x3F800000u;
    auto stTile = [&](int bufI, uint2 rawA, float4 x0, float4 x1, float dj) {
        uint4 ua0, ua1, ux0, ux1;
        ua0.x = (rawA.x & 0xffu)         ? ONE : 0u;
        ua0.y = ((rawA.x >> 8) & 0xffu)  ? ONE : 0u;
        ua0.z = ((rawA.x >> 16) & 0xffu) ? ONE : 0u;
        ua0.w = ((rawA.x >> 24) & 0xffu) ? ONE : 0u;
        ua1.x = (rawA.y & 0xffu)         ? ONE : 0u;
        ua1.y = ((rawA.y >> 8) & 0xffu)  ? ONE : 0u;
        ua1.z = ((rawA.y >> 16) & 0xffu) ? ONE : 0u;
        ua1.w = ((rawA.y >> 24) & 0xffu) ? ONE : 0u;
        ux0.x = f2tf(x0.x * dj); ux0.y = f2tf(x0.y * dj);
        ux0.z = f2tf(x0.z * dj); ux0.w = f2tf(x0.w * dj);
        ux1.x = f2tf(x1.x * dj); ux1.y = f2tf(x1.y * dj);
        ux1.z = f2tf(x1.z * dj); ux1.w = f2tf(x1.w * dj);
        *reinterpret_cast<uint4*>(&As[bufI][jj][ii]) = ua0;
        *reinterpret_cast<uint4*>(&As[bufI][jj][ii + 4]) = ua1;
        *reinterpret_cast<uint4*>(&Bs[bufI][jj][ii]) = ux0;
        *reinterpret_cast<uint4*>(&Bs[bufI][jj][ii + 4]) = ux1;
    };

    {
        uint2 rawA = *reinterpret_cast<const uint2*>(Ab + (long)jj * kN + i0 + ii);
        const float* xp = Xb + (long)jj * F + f0 + ii;
        stTile(0, rawA,
               *reinterpret_cast<const float4*>(xp),
               *reinterpret_cast<const float4*>(xp + 4),
               db[jj]);
    }
    __syncthreads();

    int buf = 0;
    for (int j0 = 0; j0 < kN; j0 += 16) {
        bool more = (j0 + 16) < kN;
        uint2 nraw;
        float4 nx0, nx1;
        float djn = 0.f;
        if (more) {
            nraw = *reinterpret_cast<const uint2*>(
                Ab + (long)(j0 + 16 + jj) * kN + i0 + ii);
            const float* xp = Xb + (long)(j0 + 16 + jj) * F + f0 + ii;
            nx0 = *reinterpret_cast<const float4*>(xp);
            nx1 = *reinterpret_cast<const float4*>(xp + 4);
            djn = db[j0 + 16 + jj];
        }
#pragma unroll
        for (int s = 0; s < 2; s++) {
            int kk = s * 8 + tg;
            uint32_t af[2][4];
#pragma unroll
            for (int mt = 0; mt < 2; mt++) {
                int m = mw + mt * 16 + g;
                af[mt][0] = As[buf][kk][m];
                af[mt][1] = As[buf][kk][m + 8];
                af[mt][2] = As[buf][kk + 4][m];
                af[mt][3] = As[buf][kk + 4][m + 8];
            }
#pragma unroll
            for (int j = 0; j < 8; j++) {
                int n = nw + j * 8 + g;
                uint32_t b0 = Bs[buf][kk][n];
                uint32_t b1 = Bs[buf][kk + 4][n];
                mma_tf32(acc[0][j], af[0], b0, b1);
                mma_tf32(acc[1][j], af[1], b0, b1);
            }
        }
        if (more) {
            int nb = buf ^ 1;
            stTile(nb, nraw, nx0, nx1, djn);
            __syncthreads();
            buf = nb;
        }
    }

#pragma unroll
    for (int mt = 0; mt < 2; mt++) {
        int rowA = i0 + mw + mt * 16 + g;
        float diA = db[rowA], diB = db[rowA + 8];
#pragma unroll
        for (int j = 0; j < 8; j++) {
            int col = f0 + nw + j * 8 + 2 * tg;
            float2 bb = *reinterpret_cast<const float2*>(bias + col);
            float2 xA = *reinterpret_cast<const float2*>(Xb + (long)rowA * F + col);
            float2 xB = *reinterpret_cast<const float2*>(Xb + (long)(rowA + 8) * F + col);
            float v0 = diA * (acc[mt][j][0] + diA * xA.x) + bb.x;
            float v1 = diA * (acc[mt][j][1] + diA * xA.y) + bb.y;
            float v2 = diB * (acc[mt][j][2] + diB * xB.x) + bb.x;
            float v3 = diB * (acc[mt][j][3] + diB * xB.y) + bb.y;
            if (RELU) {
                v0 = fmaxf(v0, 0.f); v1 = fmaxf(v1, 0.f);
                v2 = fmaxf(v2, 0.f); v3 = fmaxf(v3, 0.f);
            }
            *reinterpret_cast<float2*>(Ob + (long)rowA * outStride + col) =
                make_float2(v0, v1);
            *reinterpret_cast<float2*>(Ob + (long)(rowA + 8) * outStride + col) =
                make_float2(v2, v3);
        }
    }
}

// ---------------------------------------------------------------------------
// fcn1 split-K + head
// ---------------------------------------------------------------------------
__global__ void k_fcn1(const float* __restrict__ emb, const float* __restrict__ W,
                       float* __restrict__ h1) {
    constexpr int KC = kKTOT / 128;
    __shared__ float As[16][32];
    __shared__ float Bs[16][64];
    int n0 = blockIdx.x * 64;
    int kbase = blockIdx.y * KC;
    int t = threadIdx.x;
    int m = t & 31;
    int nb = (t >> 5) << 3;
    float acc[8];
#pragma unroll
    for (int j = 0; j < 8; j++) acc[j] = 0.f;

    for (int k0 = kbase; k0 < kbase + KC; k0 += 16) {
        if (t < 128) {
            int row = t >> 2, c4 = (t & 3) << 2;
            float4 a = *reinterpret_cast<const float4*>(emb + (long)row * kKTOT + k0 + c4);
            As[c4 + 0][row] = a.x; As[c4 + 1][row] = a.y;
            As[c4 + 2][row] = a.z; As[c4 + 3][row] = a.w;
        }
        {
            int row = t >> 2, c4 = (t & 3) << 2;
            float4 b = *reinterpret_cast<const float4*>(W + (long)(n0 + row) * kKTOT + k0 + c4);
            Bs[c4 + 0][row] = b.x; Bs[c4 + 1][row] = b.y;
            Bs[c4 + 2][row] = b.z; Bs[c4 + 3][row] = b.w;
        }
        __syncthreads();
#pragma unroll
        for (int k = 0; k < 16; k++) {
            float a = As[k][m];
#pragma unroll
            for (int j = 0; j < 8; j++) acc[j] += a * Bs[k][nb + j];
        }
        __syncthreads();
    }
#pragma unroll
    for (int j = 0; j < 8; j++)
        atomicAdd(&h1[m * 256 + n0 + nb + j], acc[j]);
}

__global__ void k_fcn23(const float* __restrict__ h1g,
                        const float* __restrict__ b1, const float* __restrict__ w2,
                        const float* __restrict__ b2, const float* __restrict__ w3,
                        const float* __restrict__ b3, float* __restrict__ out) {
    __shared__ float h1s[32][256];
    __shared__ float h2s[32][32];
    int t = threadIdx.x;
    for (int idx = t; idx < 32 * 256; idx += 1024) {
        float v = h1g[idx] + b1[idx & 255];
        h1s[idx >> 8][idx & 255] = (v >= 0.f) ? v : 0.2f * v;
    }
    __syncthreads();
    {
        int b = t >> 5, o = t & 31;
        float s = 0.f;
#pragma unroll 8
        for (int k = 0; k < 256; k++) s += h1s[b][k] * w2[o * 256 + k];
        s += b2[o];
        h2s[b][o] = (s >= 0.f) ? s : 0.2f * s;
    }
    __syncthreads();
    if (t < 64) {
        int b = t >> 1, o = t & 1;
        float s = 0.f;
#pragma unroll
        for (int k = 0; k < 32; k++) s += h2s[b][k] * w3[o * 32 + k];
        out[b * 2 + o] = s + b3[o];
    }
}

// ---------------------------------------------------------------------------
// Launch
// ---------------------------------------------------------------------------
extern "C" void kernel_launch(void* const* d_in, const int* in_sizes, int n_in,
                              void* d_out, int out_size) {
    const float* x    = (const float*)d_in[0];
    const float* t    = (const float*)d_in[1];
    const float* gu   = (const float*)d_in[2];
    const int*   ei   = (const int*)d_in[3];
    const float* w1   = (const float*)d_in[4];
    const float* b1   = (const float*)d_in[5];
    const float* w2   = (const float*)d_in[6];
    const float* b2   = (const float*)d_in[7];
    const float* fcw  = (const float*)d_in[8];
    const float* fcb  = (const float*)d_in[9];
    const float* f1w  = (const float*)d_in[10];
    const float* f1b  = (const float*)d_in[11];
    const float* f2w  = (const float*)d_in[12];
    const float* f2b  = (const float*)d_in[13];
    const float* f3w  = (const float*)d_in[14];
    const float* f3b  = (const float*)d_in[15];
    float* out = (float*)d_out;

    const int* rowp = ei;
    const int* colp = ei + kE;

    float* base = nullptr;
    cudaGetSymbolAddress((void**)&base, g_scratch);
    float* p_E     = base + OFF_EG;
    float* p_F     = base + OFF_FG;
    unsigned char* p_A8 = (unsigned char*)(base + OFF_A8);
    float* p_disD  = base + OFF_DISD;
    float* p_degD  = base + OFF_DEGD;
    float* p_xw1   = base + OFF_XW1;     // fp32: dense prop1
    float* p_h     = base + OFF_H;       // [H | SC1] contiguous
    float* p_sc1   = base + OFF_SC1;
    float* p_xw2   = base + OFF_XW2;     // [XW2 | XWS2] contiguous (fp32)
    float* p_emb   = base + OFF_EMB;
    float* p_disS  = base + OFF_DISS;
    int*   p_degS  = (int*)(base + OFF_DEGS);
    float* p_h1    = base + OFF_H1;
    int*   p_ns    = (int*)(base + OFF_NS);
    int*   p_cur   = (int*)(base + OFF_CUR);
    int*   p_esrc  = (int*)(base + OFF_ESRC);
    __half* p_xw1h  = (__half*)(base + OFF_XW1H);   // fp16 mirror for gather1
    __half* p_xws2h = (__half*)(base + OFF_XWS2H);  // fp16 mirror for gather2

    // prep
    k_zero<<<64, 256>>>(p_degS, p_h1, p_degD);
    k_lslr<<<kNTOT / 8, 256>>>(t, fcw, fcb, p_E, p_F);
    k_buildA<<<kBZ * kN * kN / 1024, 256>>>(gu, p_E, p_F, p_A8);

    // shared layer-1 feature GEMM (fp32 out + fp16 mirror), flat M=16384
    k_gemm_tf32<false><<<dim3(kF1 / 128, kNTOT / 128, 1), 256>>>(
        x, 0, w1, p_xw1, 0, kF1, kN, p_xw1h, 0);

    // degrees + CSR
    k_colsum_part<<<dim3(kBZ, 8), kN>>>(p_A8, p_degD);
    k_degS<<<kE / 256, 256>>>(colp, p_degS);
    k_dis<<<kNTOT / 256, 256>>>(p_degD, p_degS, p_disD, p_disS);
    k_scan<<<1, 1024>>>(p_degS, p_ns, p_cur);
    k_fill<<<kE / 256, 256>>>(rowp, colp, p_cur, p_esrc);

    // dense prop layer 1
    k_prop_tf32<true><<<dim3(kF1 / 128, kN / 128, kBZ), 256>>>(
        p_A8, p_xw1, p_disD, b1, p_h, kF1, kF1, 0);

    // sparse gather layer 1 (fp16 rows)
    k_gather_h<4><<<kNTOT / 8, 256>>>(p_ns, p_esrc, (const __half2*)p_xw1h,
                                      p_disS, b1, p_sc1, kF1, 0);

    // merged layer-2 feature GEMM over [H | SC1], M=32768;
    // fp16 mirror only for SC1 rows (>= kNTOT) -> xws2h
    k_gemm_tf32<true><<<dim3(kF2 / 128, 2 * kNTOT / 128, 1), 256>>>(
        p_h, 0, w2, p_xw2, 0, kF2, kF1, p_xws2h, kNTOT);

    // dense prop layer 2 -> emb[:, 0:128]
    k_prop_tf32<false><<<dim3(kF2 / 128, kN / 128, kBZ), 256>>>(
        p_A8, p_xw2, p_disD, b2, p_emb, kF2, 256, 0);

    // sparse gather layer 2 -> emb[:, 128:256] (fp16 rows)
    k_gather_h<2><<<kNTOT / 8, 256>>>(p_ns, p_esrc, (const __half2*)p_xws2h,
                                      p_disS, b2, p_emb, 256, 128);

    // MLP head
    k_fcn1<<<dim3(256 / 64, 128), 256>>>(p_emb, f1w, p_h1);
    k_fcn23<<<1, 1024>>>(p_h1, f1b, f2w, f2b, f3w, f3b, out);
}

// round 9
// speedup vs baseline: 1.0948x; 1.0155x over previous
#include <cuda_runtime.h>
#include <cuda_fp16.h>
#include <cstdint>

// ---------------------------------------------------------------------------
// Problem constants
// ---------------------------------------------------------------------------
constexpr int kN    = 512;
constexpr int kBZ   = 32;
constexpr int kTC   = 256;
constexpr int kF1   = 256;
constexpr int kF2   = 128;
constexpr int kE    = 524288;
constexpr int kNTOT = kBZ * kN;          // 16384
constexpr int kKTOT = kF2 * 2 * kN;      // 131072

// ---------------------------------------------------------------------------
// Scratch (offsets in floats)
// ---------------------------------------------------------------------------
constexpr long OFF_EG   = 0;
constexpr long OFF_FG   = OFF_EG   + (long)kNTOT;
constexpr long OFF_A8   = OFF_FG   + (long)kNTOT;                // u8 view
constexpr long OFF_DISD = OFF_A8   + (long)kBZ * kN * kN / 4;
constexpr long OFF_DEGD = OFF_DISD + (long)kNTOT;
constexpr long OFF_XW1  = OFF_DEGD + (long)kNTOT;
constexpr long OFF_H    = OFF_XW1  + (long)kNTOT * kF1;
constexpr long OFF_SC1  = OFF_H    + (long)kNTOT * kF1;          // contiguous after H
constexpr long OFF_XW2  = OFF_SC1  + (long)kNTOT * kF1;
constexpr long OFF_XWS2 = OFF_XW2  + (long)kNTOT * kF2;          // contiguous after XW2
constexpr long OFF_EMB  = OFF_XWS2 + (long)kNTOT * kF2;
constexpr long OFF_DISS = OFF_EMB  + (long)kNTOT * 256;
constexpr long OFF_DEGS = OFF_DISS + (long)kNTOT;                // int
constexpr long OFF_H1   = OFF_DEGS + (long)kNTOT;
constexpr long OFF_NS   = OFF_H1   + (long)kBZ * 256;            // int, kNTOT+1
constexpr long OFF_CUR  = OFF_NS   + (long)kNTOT + 4;            // int
constexpr long OFF_ESRC = OFF_CUR  + (long)kNTOT;                // int, kE
constexpr long OFF_XW1H = OFF_ESRC + (long)kE;                   // half, kNTOT*kF1
constexpr long OFF_XWS2H= OFF_XW1H + (long)kNTOT * kF1 / 2;      // half, kNTOT*kF2
constexpr long SCRATCH_FLOATS = OFF_XWS2H + (long)kNTOT * kF2 / 2;

__device__ __align__(16) float g_scratch[SCRATCH_FLOATS];

// ---------------------------------------------------------------------------
// tf32 / ldmatrix helpers
// ---------------------------------------------------------------------------
__device__ __forceinline__ uint32_t f2tf(float x) {
    uint32_t r;
    asm("cvt.rna.tf32.f32 %0, %1;" : "=r"(r) : "f"(x));
    return r;
}
__device__ __forceinline__ void mma_tf32(float* d, const uint32_t* a,
                                         uint32_t b0, uint32_t b1) {
    asm volatile(
        "mma.sync.aligned.m16n8k8.row.col.f32.tf32.tf32.f32 "
        "{%0,%1,%2,%3},{%4,%5,%6,%7},{%8,%9},{%0,%1,%2,%3};"
        : "+f"(d[0]), "+f"(d[1]), "+f"(d[2]), "+f"(d[3])
        : "r"(a[0]), "r"(a[1]), "r"(a[2]), "r"(a[3]), "r"(b0), "r"(b1));
}
__device__ __forceinline__ void ldsm4(uint32_t* r, uint32_t addr) {
    asm volatile("ldmatrix.sync.aligned.m8n8.x4.shared.b16 {%0,%1,%2,%3}, [%4];"
                 : "=r"(r[0]), "=r"(r[1]), "=r"(r[2]), "=r"(r[3]) : "r"(addr));
}
__device__ __forceinline__ uint32_t smem_u32(const void* p) {
    return (uint32_t)__cvta_generic_to_shared(p);
}

// ---------------------------------------------------------------------------
// Small kernels
// ---------------------------------------------------------------------------
__global__ void k_zero(int* degS, float* h1, float* degD) {
    int i = blockIdx.x * 256 + threadIdx.x;
    if (i < kNTOT) { degS[i] = 0; degD[i] = 1.f; }
    if (i < kBZ * 256) h1[i] = 0.f;
}

__global__ void k_lslr(const float* __restrict__ t, const float* __restrict__ fcw,
                       const float* __restrict__ fcb,
                       float* __restrict__ Eg, float* __restrict__ Fg) {
    int warp = (blockIdx.x * blockDim.x + threadIdx.x) >> 5;
    int lane = threadIdx.x & 31;
    if (warp >= kNTOT) return;
    const float* tn = t + (long)warp * kTC;
    const float* w0 = fcw;
    const float* w1 = fcw + 512;
    float s0 = 0.f, s1 = 0.f, r0 = 0.f, r1 = 0.f;
#pragma unroll
    for (int q = 0; q < 8; q++) {
        int d = lane + 32 * q;
        float u = fmaxf(tn[d], 0.f);
        s0 += u * w0[d];       s1 += u * w1[d];
        r0 += u * w0[256 + d]; r1 += u * w1[256 + d];
    }
#pragma unroll
    for (int off = 16; off; off >>= 1) {
        s0 += __shfl_down_sync(0xffffffffu, s0, off);
        s1 += __shfl_down_sync(0xffffffffu, s1, off);
        r0 += __shfl_down_sync(0xffffffffu, r0, off);
        r1 += __shfl_down_sync(0xffffffffu, r1, off);
    }
    if (lane == 0) {
        Eg[warp] = expf(r1 - r0 + fcb[1] - fcb[0]);
        Fg[warp] = expf(s1 - s0);
    }
}

__global__ void k_buildA(const float* __restrict__ gu,
                         const float* __restrict__ Eg, const float* __restrict__ Fg,
                         unsigned char* __restrict__ A8) {
    int idx = blockIdx.x * 256 + threadIdx.x;
    int j0 = (idx & 127) << 2;
    int i  = (idx >> 7) & 511;
    int b  = idx >> 16;
    float Ei = Eg[b * kN + i];
    float4 Fv = *reinterpret_cast<const float4*>(Fg + b * kN + j0);
    const float4* g4 = reinterpret_cast<const float4*>(
        gu + ((long)(b * kN + i) * kN + j0) * 2);
    float4 u01 = g4[0];
    float4 u23 = g4[1];
    auto bit = [&](float ux, float uy, float Fj) -> unsigned char {
        ux = fminf(fmaxf(ux, 1e-9f), 1.0f - 1e-9f);
        uy = fminf(fmaxf(uy, 1e-9f), 1.0f - 1e-9f);
        float l0 = -__logf(ux);
        float l1 = -__logf(uy);
        return (l1 >= l0 * Ei * Fj) ? 1 : 0;
    };
    uchar4 r;
    r.x = bit(u01.x, u01.y, Fv.x);
    r.y = bit(u01.z, u01.w, Fv.y);
    r.z = bit(u23.x, u23.y, Fv.z);
    r.w = bit(u23.z, u23.w, Fv.w);
    *reinterpret_cast<uchar4*>(A8 + (long)(b * kN + i) * kN + j0) = r;
}

__global__ void k_colsum_part(const unsigned char* __restrict__ A8,
                              float* __restrict__ degD) {
    int b = blockIdx.x;
    int j = threadIdx.x;
    int r0 = blockIdx.y * 64;
    const unsigned char* Ab = A8 + (long)b * kN * kN;
    int s = 0;
#pragma unroll 8
    for (int r = r0; r < r0 + 64; r++) s += Ab[(long)r * kN + j];
    atomicAdd(&degD[b * kN + j], (float)s);
}

__global__ void k_degS(const int* __restrict__ colp, int* degS) {
    int e = blockIdx.x * 256 + threadIdx.x;
    if (e < kE) atomicAdd(&degS[colp[e]], 1);
}

__global__ void k_dis(const float* __restrict__ degD, const int* __restrict__ degS,
                      float* __restrict__ disD, float* __restrict__ disS) {
    int i = blockIdx.x * 256 + threadIdx.x;
    if (i < kNTOT) {
        disD[i] = rsqrtf(degD[i]);
        disS[i] = rsqrtf((float)degS[i] + 1.f);
    }
}

__global__ void k_scan(const int* __restrict__ degS, int* __restrict__ ns,
                       int* __restrict__ cur) {
    __shared__ int sm[1024];
    int tid = threadIdx.x;
    int base = tid * 16;
    int local[16];
    int sum = 0;
#pragma unroll
    for (int v = 0; v < 16; v++) { local[v] = degS[base + v]; sum += local[v]; }
    sm[tid] = sum;
    __syncthreads();
    for (int off = 1; off < 1024; off <<= 1) {
        int v = (tid >= off) ? sm[tid - off] : 0;
        __syncthreads();
        sm[tid] += v;
        __syncthreads();
    }
    int run = sm[tid] - sum;
#pragma unroll
    for (int v = 0; v < 16; v++) {
        ns[base + v] = run;
        cur[base + v] = run;
        run += local[v];
    }
    if (tid == 1023) ns[kNTOT] = run;
}

__global__ void k_fill(const int* __restrict__ rowp, const int* __restrict__ colp,
                       int* cur, int* __restrict__ esrc) {
    int e = blockIdx.x * 256 + threadIdx.x;
    if (e < kE) {
        int c = colp[e];
        int p = atomicAdd(&cur[c], 1);
        esrc[p] = rowp[e];
    }
}

// ---------------------------------------------------------------------------
// fp16 CSR gather: one warp per node; VH half2 per lane (F = VH*64).
// ---------------------------------------------------------------------------
template <int VH>   // 4 -> F=256 (16B/lane), 2 -> F=128 (8B/lane)
__global__ __launch_bounds__(256) void k_gather_h(
        const int* __restrict__ ns, const int* __restrict__ esrc,
        const __half2* __restrict__ xwh, const float* __restrict__ disS,
        const float* __restrict__ bias, float* __restrict__ out,
        int outStride, int outOffset) {
    constexpr int F2 = VH * 32;    // half2 per row
    int node = (blockIdx.x * 256 + threadIdx.x) >> 5;
    int lane = threadIdx.x & 31;
    if (node >= kNTOT) return;
    int off2 = lane * VH;
    float dc = disS[node];
    float2 acc[VH];

    auto loadrow = [&](long r, uint32_t* rw) {
        const char* p = reinterpret_cast<const char*>(xwh + r * F2 + off2);
        if (VH == 4) {
            uint4 u = *reinterpret_cast<const uint4*>(p);
            rw[0] = u.x; rw[1] = u.y; rw[2] = u.z; rw[3] = u.w;
        } else {
            uint2 u = *reinterpret_cast<const uint2*>(p);
            rw[0] = u.x; rw[1] = u.y;
        }
    };

    {
        uint32_t rw[VH];
        loadrow(node, rw);
        float d2 = dc * dc;
#pragma unroll
        for (int v = 0; v < VH; v++) {
            float2 xv = __half22float2(*reinterpret_cast<__half2*>(&rw[v]));
            float2 bb = *reinterpret_cast<const float2*>(bias + (off2 + v) * 2);
            acc[v] = make_float2(xv.x * d2 + bb.x, xv.y * d2 + bb.y);
        }
    }
    int s = ns[node], e = ns[node + 1];
    int i = s;
    for (; i + 8 <= e; i += 8) {
        int r[8];
        float sc[8];
        uint32_t rw[8][VH];
#pragma unroll
        for (int q = 0; q < 8; q++) r[q] = esrc[i + q];
#pragma unroll
        for (int q = 0; q < 8; q++) sc[q] = disS[r[q]] * dc;
#pragma unroll
        for (int q = 0; q < 8; q++) loadrow(r[q], rw[q]);
#pragma unroll
        for (int q = 0; q < 8; q++)
#pragma unroll
            for (int v = 0; v < VH; v++) {
                float2 xv = __half22float2(*reinterpret_cast<__half2*>(&rw[q][v]));
                acc[v].x += xv.x * sc[q];
                acc[v].y += xv.y * sc[q];
            }
    }
    for (; i < e; i++) {
        int r = esrc[i];
        float sr = disS[r] * dc;
        uint32_t rw[VH];
        loadrow(r, rw);
#pragma unroll
        for (int v = 0; v < VH; v++) {
            float2 xv = __half22float2(*reinterpret_cast<__half2*>(&rw[v]));
            acc[v].x += xv.x * sr;
            acc[v].y += xv.y * sr;
        }
    }
    float* op = out + (long)node * outStride + outOffset + off2 * 2;
#pragma unroll
    for (int v = 0; v < VH; v++)
        *reinterpret_cast<float2*>(op + v * 2) = acc[v];
}

// ---------------------------------------------------------------------------
// tf32 NT GEMM with ldmatrix fragment loads + optional fp16 mirror output.
// ---------------------------------------------------------------------------
template <bool RELU_A>
__global__ __launch_bounds__(256) void k_gemm_tf32(
        const float* __restrict__ A, long aStride,
        const float* __restrict__ B,
        float* __restrict__ C, long cStride,
        int Nf, int K, __half* __restrict__ Ch, int hRowStart) {
    __shared__ uint32_t As[2][128][20];
    __shared__ uint32_t Bs[2][128][20];
    const float* Ab = A + (long)blockIdx.z * aStride;
    float* Cb = C + (long)blockIdx.z * cStride;
    int m0 = blockIdx.y * 128, n0 = blockIdx.x * 128;
    int t = threadIdx.x;
    int wid = t >> 5, lane = t & 31;
    int mw = (wid >> 1) * 32, nw = (wid & 1) * 64;
    int g = lane >> 2, tg = lane & 3;
    int lrow16 = lane & 15;
    int lhalf4 = (lane >> 4) * 4;
    int lr = t >> 2, lc = (t & 3) << 2;

    uint32_t sA[2] = { smem_u32(&As[0][0][0]), smem_u32(&As[1][0][0]) };
    uint32_t sB[2] = { smem_u32(&Bs[0][0][0]), smem_u32(&Bs[1][0][0]) };

    float acc[2][8][4];
#pragma unroll
    for (int i = 0; i < 2; i++)
#pragma unroll
        for (int j = 0; j < 8; j++)
#pragma unroll
            for (int c = 0; c < 4; c++) acc[i][j][c] = 0.f;

    const float* aP0 = Ab + (long)(m0 + lr) * K + lc;
    const float* aP1 = Ab + (long)(m0 + lr + 64) * K + lc;
    const float* bP0 = B + (long)(n0 + lr) * K + lc;
    const float* bP1 = B + (long)(n0 + lr + 64) * K + lc;

    auto cvt4 = [](float4 v, bool relu) -> uint4 {
        if (relu) {
            v.x = fmaxf(v.x, 0.f); v.y = fmaxf(v.y, 0.f);
            v.z = fmaxf(v.z, 0.f); v.w = fmaxf(v.w, 0.f);
        }
        uint4 r;
        r.x = f2tf(v.x); r.y = f2tf(v.y); r.z = f2tf(v.z); r.w = f2tf(v.w);
        return r;
    };

    {
        uint4 a0 = cvt4(*reinterpret_cast<const float4*>(aP0), RELU_A);
        uint4 a1 = cvt4(*reinterpret_cast<const float4*>(aP1), RELU_A);
        uint4 b0 = cvt4(*reinterpret_cast<const float4*>(bP0), false);
        uint4 b1 = cvt4(*reinterpret_cast<const float4*>(bP1), false);
        *reinterpret_cast<uint4*>(&As[0][lr][lc]) = a0;
        *reinterpret_cast<uint4*>(&As[0][lr + 64][lc]) = a1;
        *reinterpret_cast<uint4*>(&Bs[0][lr][lc]) = b0;
        *reinterpret_cast<uint4*>(&Bs[0][lr + 64][lc]) = b1;
    }
    __syncthreads();

    int buf = 0;
    for (int k0 = 0; k0 < K; k0 += 16) {
        bool more = (k0 + 16) < K;
        float4 na0, na1, nb0, nb1;
        if (more) {
            na0 = *reinterpret_cast<const float4*>(aP0 + k0 + 16);
            na1 = *reinterpret_cast<const float4*>(aP1 + k0 + 16);
            nb0 = *reinterpret_cast<const float4*>(bP0 + k0 + 16);
            nb1 = *reinterpret_cast<const float4*>(bP1 + k0 + 16);
        }
#pragma unroll
        for (int s = 0; s < 2; s++) {
            int kcol = s * 8 + lhalf4;
            uint32_t af0[4], af1[4];
            ldsm4(af0, sA[buf] + ((mw + lrow16) * 20 + kcol) * 4);
            ldsm4(af1, sA[buf] + ((mw + 16 + lrow16) * 20 + kcol) * 4);
#pragma unroll
            for (int p = 0; p < 4; p++) {
                uint32_t bf[4];
                ldsm4(bf, sB[buf] + ((nw + p * 16 + lrow16) * 20 + kcol) * 4);
                mma_tf32(acc[0][2 * p],     af0, bf[0], bf[2]);
                mma_tf32(acc[0][2 * p + 1], af0, bf[1], bf[3]);
                mma_tf32(acc[1][2 * p],     af1, bf[0], bf[2]);
                mma_tf32(acc[1][2 * p + 1], af1, bf[1], bf[3]);
            }
        }
        if (more) {
            int nb = buf ^ 1;
            *reinterpret_cast<uint4*>(&As[nb][lr][lc]) = cvt4(na0, RELU_A);
            *reinterpret_cast<uint4*>(&As[nb][lr + 64][lc]) = cvt4(na1, RELU_A);
            *reinterpret_cast<uint4*>(&Bs[nb][lr][lc]) = cvt4(nb0, false);
            *reinterpret_cast<uint4*>(&Bs[nb][lr + 64][lc]) = cvt4(nb1, false);
            __syncthreads();
            buf = nb;
        }
    }

    bool doH = (Ch != nullptr) && (m0 >= hRowStart);
#pragma unroll
    for (int mt = 0; mt < 2; mt++) {
        int row = m0 + mw + mt * 16 + g;
#pragma unroll
        for (int j = 0; j < 8; j++) {
            int col = n0 + nw + j * 8 + 2 * tg;
            float2 v0 = make_float2(acc[mt][j][0], acc[mt][j][1]);
            float2 v1 = make_float2(acc[mt][j][2], acc[mt][j][3]);
            *reinterpret_cast<float2*>(Cb + (long)row * Nf + col) = v0;
            *reinterpret_cast<float2*>(Cb + (long)(row + 8) * Nf + col) = v1;
            if (doH) {
                long hr = row - hRowStart;
                *reinterpret_cast<__half2*>(Ch + hr * Nf + col) =
                    __floats2half2_rn(v0.x, v0.y);
                *reinterpret_cast<__half2*>(Ch + (hr + 8) * Nf + col) =
                    __floats2half2_rn(v1.x, v1.y);
            }
        }
    }
}

// ---------------------------------------------------------------------------
// tf32 dense GCN propagation — A tiles loaded as uint8, expanded to tf32 one-bits
// ---------------------------------------------------------------------------
template <bool RELU>
__global__ __launch_bounds__(256) void k_prop_tf32(
        const unsigned char* __restrict__ Adj8, const float* __restrict__ XW,
        const float* __restrict__ dis, const float* __restrict__ bias,
        float* __restrict__ out, int F, int outStride, int outOffset) {
    __shared__ uint32_t As[2][16][136];
    __shared__ uint32_t Bs[2][16][136];
    int b = blockIdx.z;
    const unsigned char* Ab = Adj8 + (long)b * kN * kN;
    const float* Xb = XW + (long)b * kN * F;
    const float* db = dis + b * kN;
    float* Ob = out + (long)b * kN * outStride + outOffset;
    int i0 = blockIdx.y * 128, f0 = blockIdx.x * 128;
    int t = threadIdx.x;
    int wid = t >> 5, lane = t & 31;
    int mw = (wid >> 1) * 32, nw = (wid & 1) * 64;
    int g = lane >> 2, tg = lane & 3;
    int jj = t >> 4;
    int ii = (t & 15) << 3;

    float acc[2][8][4];
#pragma unroll
    for (int i = 0; i < 2; i++)
#pragma unroll
        for (int j = 0; j < 8; j++)
#pragma unroll
            for (int c = 0; c < 4; c++) acc[i][j][c] = 0.f;

    constexpr uint32_t ONE = 0x3F800000u;
    auto stTile = [&](int bufI, uint2 rawA, float4 x0, float4 x1, float dj) {
        uint4 ua0, ua1, ux0, ux1;
        ua0.x = (rawA.x & 0xffu)         ? ONE : 0u;
        ua0.y = ((rawA.x >> 8) & 0xffu)  ? ONE : 0u;
        ua0.z = ((rawA.x >> 16) & 0xffu) ? ONE : 0u;
        ua0.w = ((rawA.x >> 24) & 0xffu) ? ONE : 0u;
        ua1.x = (rawA.y & 0xffu)         ? ONE : 0u;
        ua1.y = ((rawA.y >> 8) & 0xffu)  ? ONE : 0u;
        ua1.z = ((rawA.y >> 16) & 0xffu) ? ONE : 0u;
        ua1.w = ((rawA.y >> 24) & 0xffu) ? ONE : 0u;
        ux0.x = f2tf(x0.x * dj); ux0.y = f2tf(x0.y * dj);
        ux0.z = f2tf(x0.z * dj); ux0.w = f2tf(x0.w * dj);
        ux1.x = f2tf(x1.x * dj); ux1.y = f2tf(x1.y * dj);
        ux1.z = f2tf(x1.z * dj); ux1.w = f2tf(x1.w * dj);
        *reinterpret_cast<uint4*>(&As[bufI][jj][ii]) = ua0;
        *reinterpret_cast<uint4*>(&As[bufI][jj][ii + 4]) = ua1;
        *reinterpret_cast<uint4*>(&Bs[bufI][jj][ii]) = ux0;
        *reinterpret_cast<uint4*>(&Bs[bufI][jj][ii + 4]) = ux1;
    };

    {
        uint2 rawA = *reinterpret_cast<const uint2*>(Ab + (long)jj * kN + i0 + ii);
        const float* xp = Xb + (long)jj * F + f0 + ii;
        stTile(0, rawA,
               *reinterpret_cast<const float4*>(xp),
               *reinterpret_cast<const float4*>(xp + 4),
               db[jj]);
    }
    __syncthreads();

    int buf = 0;
    for (int j0 = 0; j0 < kN; j0 += 16) {
        bool more = (j0 + 16) < kN;
        uint2 nraw;
        float4 nx0, nx1;
        float djn = 0.f;
        if (more) {
            nraw = *reinterpret_cast<const uint2*>(
                Ab + (long)(j0 + 16 + jj) * kN + i0 + ii);
            const float* xp = Xb + (long)(j0 + 16 + jj) * F + f0 + ii;
            nx0 = *reinterpret_cast<const float4*>(xp);
            nx1 = *reinterpret_cast<const float4*>(xp + 4);
            djn = db[j0 + 16 + jj];
        }
#pragma unroll
        for (int s = 0; s < 2; s++) {
            int kk = s * 8 + tg;
            uint32_t af[2][4];
#pragma unroll
            for (int mt = 0; mt < 2; mt++) {
                int m = mw + mt * 16 + g;
                af[mt][0] = As[buf][kk][m];
                af[mt][1] = As[buf][kk][m + 8];
                af[mt][2] = As[buf][kk + 4][m];
                af[mt][3] = As[buf][kk + 4][m + 8];
            }
#pragma unroll
            for (int j = 0; j < 8; j++) {
                int n = nw + j * 8 + g;
                uint32_t b0 = Bs[buf][kk][n];
                uint32_t b1 = Bs[buf][kk + 4][n];
                mma_tf32(acc[0][j], af[0], b0, b1);
                mma_tf32(acc[1][j], af[1], b0, b1);
            }
        }
        if (more) {
            int nb = buf ^ 1;
            stTile(nb, nraw, nx0, nx1, djn);
            __syncthreads();
            buf = nb;
        }
    }

#pragma unroll
    for (int mt = 0; mt < 2; mt++) {
        int rowA = i0 + mw + mt * 16 + g;
        float diA = db[rowA], diB = db[rowA + 8];
#pragma unroll
        for (int j = 0; j < 8; j++) {
            int col = f0 + nw + j * 8 + 2 * tg;
            float2 bb = *reinterpret_cast<const float2*>(bias + col);
            float2 xA = *reinterpret_cast<const float2*>(Xb + (long)rowA * F + col);
            float2 xB = *reinterpret_cast<const float2*>(Xb + (long)(rowA + 8) * F + col);
            float v0 = diA * (acc[mt][j][0] + diA * xA.x) + bb.x;
            float v1 = diA * (acc[mt][j][1] + diA * xA.y) + bb.y;
            float v2 = diB * (acc[mt][j][2] + diB * xB.x) + bb.x;
            float v3 = diB * (acc[mt][j][3] + diB * xB.y) + bb.y;
            if (RELU) {
                v0 = fmaxf(v0, 0.f); v1 = fmaxf(v1, 0.f);
                v2 = fmaxf(v2, 0.f); v3 = fmaxf(v3, 0.f);
            }
            *reinterpret_cast<float2*>(Ob + (long)rowA * outStride + col) =
                make_float2(v0, v1);
            *reinterpret_cast<float2*>(Ob + (long)(rowA + 8) * outStride + col) =
                make_float2(v2, v3);
        }
    }
}

// ---------------------------------------------------------------------------
// fcn1 split-K, register double-buffered (hides W-stream latency)
// ---------------------------------------------------------------------------
__global__ void k_fcn1(const float* __restrict__ emb, const float* __restrict__ W,
                       float* __restrict__ h1) {
    constexpr int KC = kKTOT / 128;
    __shared__ float As[16][32];
    __shared__ float Bs[16][64];
    int n0 = blockIdx.x * 64;
    int kbase = blockIdx.y * KC;
    int t = threadIdx.x;
    int m = t & 31;
    int nb = (t >> 5) << 3;
    int row = t >> 2, c4 = (t & 3) << 2;
    float acc[8];
#pragma unroll
    for (int j = 0; j < 8; j++) acc[j] = 0.f;

    float4 aPre, bPre;
    if (t < 128)
        aPre = *reinterpret_cast<const float4*>(emb + (long)row * kKTOT + kbase + c4);
    bPre = *reinterpret_cast<const float4*>(W + (long)(n0 + row) * kKTOT + kbase + c4);

    for (int k0 = kbase; k0 < kbase + KC; k0 += 16) {
        if (t < 128) {
            As[c4 + 0][row] = aPre.x; As[c4 + 1][row] = aPre.y;
            As[c4 + 2][row] = aPre.z; As[c4 + 3][row] = aPre.w;
        }
        Bs[c4 + 0][row] = bPre.x; Bs[c4 + 1][row] = bPre.y;
        Bs[c4 + 2][row] = bPre.z; Bs[c4 + 3][row] = bPre.w;
        __syncthreads();
        bool more = (k0 + 16) < kbase + KC;
        if (more) {
            if (t < 128)
                aPre = *reinterpret_cast<const float4*>(
                    emb + (long)row * kKTOT + k0 + 16 + c4);
            bPre = *reinterpret_cast<const float4*>(
                W + (long)(n0 + row) * kKTOT + k0 + 16 + c4);
        }
#pragma unroll
        for (int k = 0; k < 16; k++) {
            float a = As[k][m];
#pragma unroll
            for (int j = 0; j < 8; j++) acc[j] += a * Bs[k][nb + j];
        }
        __syncthreads();
    }
#pragma unroll
    for (int j = 0; j < 8; j++)
        atomicAdd(&h1[m * 256 + n0 + nb + j], acc[j]);
}

__global__ void k_fcn23(const float* __restrict__ h1g,
                        const float* __restrict__ b1, const float* __restrict__ w2,
                        const float* __restrict__ b2, const float* __restrict__ w3,
                        const float* __restrict__ b3, float* __restrict__ out) {
    __shared__ float h1s[32][256];
    __shared__ float h2s[32][32];
    int t = threadIdx.x;
    for (int idx = t; idx < 32 * 256; idx += 1024) {
        float v = h1g[idx] + b1[idx & 255];
        h1s[idx >> 8][idx & 255] = (v >= 0.f) ? v : 0.2f * v;
    }
    __syncthreads();
    {
        int b = t >> 5, o = t & 31;
        float s = 0.f;
#pragma unroll 8
        for (int k = 0; k < 256; k++) s += h1s[b][k] * w2[o * 256 + k];
        s += b2[o];
        h2s[b][o] = (s >= 0.f) ? s : 0.2f * s;
    }
    __syncthreads();
    if (t < 64) {
        int b = t >> 1, o = t & 1;
        float s = 0.f;
#pragma unroll
        for (int k = 0; k < 32; k++) s += h2s[b][k] * w3[o * 32 + k];
        out[b * 2 + o] = s + b3[o];
    }
}

// ---------------------------------------------------------------------------
// Launch
// ---------------------------------------------------------------------------
extern "C" void kernel_launch(void* const* d_in, const int* in_sizes, int n_in,
                              void* d_out, int out_size) {
    const float* x    = (const float*)d_in[0];
    const float* t    = (const float*)d_in[1];
    const float* gu   = (const float*)d_in[2];
    const int*   ei   = (const int*)d_in[3];
    const float* w1   = (const float*)d_in[4];
    const float* b1   = (const float*)d_in[5];
    const float* w2   = (const float*)d_in[6];
    const float* b2   = (const float*)d_in[7];
    const float* fcw  = (const float*)d_in[8];
    const float* fcb  = (const float*)d_in[9];
    const float* f1w  = (const float*)d_in[10];
    const float* f1b  = (const float*)d_in[11];
    const float* f2w  = (const float*)d_in[12];
    const float* f2b  = (const float*)d_in[13];
    const float* f3w  = (const float*)d_in[14];
    const float* f3b  = (const float*)d_in[15];
    float* out = (float*)d_out;

    const int* rowp = ei;
    const int* colp = ei + kE;

    float* base = nullptr;
    cudaGetSymbolAddress((void**)&base, g_scratch);
    float* p_E     = base + OFF_EG;
    float* p_F     = base + OFF_FG;
    unsigned char* p_A8 = (unsigned char*)(base + OFF_A8);
    float* p_disD  = base + OFF_DISD;
    float* p_degD  = base + OFF_DEGD;
    float* p_xw1   = base + OFF_XW1;
    float* p_h     = base + OFF_H;       // [H | SC1] contiguous
    float* p_sc1   = base + OFF_SC1;
    float* p_xw2   = base + OFF_XW2;     // [XW2 | XWS2] contiguous
    float* p_emb   = base + OFF_EMB;
    float* p_disS  = base + OFF_DISS;
    int*   p_degS  = (int*)(base + OFF_DEGS);
    float* p_h1    = base + OFF_H1;
    int*   p_ns    = (int*)(base + OFF_NS);
    int*   p_cur   = (int*)(base + OFF_CUR);
    int*   p_esrc  = (int*)(base + OFF_ESRC);
    __half* p_xw1h  = (__half*)(base + OFF_XW1H);
    __half* p_xws2h = (__half*)(base + OFF_XWS2H);

    // prep (buildA moved AFTER gemm1 so ncu captures buildA this round)
    k_zero<<<64, 256>>>(p_degS, p_h1, p_degD);                          // 0
    k_lslr<<<kNTOT / 8, 256>>>(t, fcw, fcb, p_E, p_F);                  // 1

    // shared layer-1 feature GEMM (fp32 out + fp16 mirror), flat M=16384
    k_gemm_tf32<false><<<dim3(kF1 / 128, kNTOT / 128, 1), 256>>>(       // 2
        x, 0, w1, p_xw1, 0, kF1, kN, p_xw1h, 0);

    k_buildA<<<kBZ * kN * kN / 1024, 256>>>(gu, p_E, p_F, p_A8);        // 3 (captured)

    // degrees + CSR
    k_colsum_part<<<dim3(kBZ, 8), kN>>>(p_A8, p_degD);
    k_degS<<<kE / 256, 256>>>(colp, p_degS);
    k_dis<<<kNTOT / 256, 256>>>(p_degD, p_degS, p_disD, p_disS);
    k_scan<<<1, 1024>>>(p_degS, p_ns, p_cur);
    k_fill<<<kE / 256, 256>>>(rowp, colp, p_cur, p_esrc);

    // dense prop layer 1
    k_prop_tf32<true><<<dim3(kF1 / 128, kN / 128, kBZ), 256>>>(
        p_A8, p_xw1, p_disD, b1, p_h, kF1, kF1, 0);

    // sparse gather layer 1 (fp16 rows)
    k_gather_h<4><<<kNTOT / 8, 256>>>(p_ns, p_esrc, (const __half2*)p_xw1h,
                                      p_disS, b1, p_sc1, kF1, 0);

    // merged layer-2 feature GEMM over [H | SC1], M=32768
    k_gemm_tf32<true><<<dim3(kF2 / 128, 2 * kNTOT / 128, 1), 256>>>(
        p_h, 0, w2, p_xw2, 0, kF2, kF1, p_xws2h, kNTOT);

    // dense prop layer 2 -> emb[:, 0:128]
    k_prop_tf32<false><<<dim3(kF2 / 128, kN / 128, kBZ), 256>>>(
        p_A8, p_xw2, p_disD, b2, p_emb, kF2, 256, 0);

    // sparse gather layer 2 -> emb[:, 128:256]
    k_gather_h<2><<<kNTOT / 8, 256>>>(p_ns, p_esrc, (const __half2*)p_xws2h,
                                      p_disS, b2, p_emb, 256, 128);

    // MLP head
    k_fcn1<<<dim3(256 / 64, 128), 256>>>(p_emb, f1w, p_h1);
    k_fcn23<<<1, 1024>>>(p_h1, f1b, f2w, f2b, f3w, f3b, out);
}

// round 10
// speedup vs baseline: 1.1611x; 1.0606x over previous
#include <cuda_runtime.h>
#include <cuda_fp16.h>
#include <cstdint>

// ---------------------------------------------------------------------------
// Problem constants
// ---------------------------------------------------------------------------
constexpr int kN    = 512;
constexpr int kBZ   = 32;
constexpr int kTC   = 256;
constexpr int kF1   = 256;
constexpr int kF2   = 128;
constexpr int kE    = 524288;
constexpr int kNTOT = kBZ * kN;          // 16384
constexpr int kKTOT = kF2 * 2 * kN;      // 131072

// ---------------------------------------------------------------------------
// Scratch (offsets in floats)
// ---------------------------------------------------------------------------
constexpr long OFF_EG   = 0;
constexpr long OFF_FG   = OFF_EG   + (long)kNTOT;
constexpr long OFF_A8   = OFF_FG   + (long)kNTOT;                // u8 view
constexpr long OFF_DISD = OFF_A8   + (long)kBZ * kN * kN / 4;
constexpr long OFF_DEGD = OFF_DISD + (long)kNTOT;
constexpr long OFF_XW1  = OFF_DEGD + (long)kNTOT;
constexpr long OFF_H    = OFF_XW1  + (long)kNTOT * kF1;
constexpr long OFF_SC1  = OFF_H    + (long)kNTOT * kF1;          // contiguous after H
constexpr long OFF_XW2  = OFF_SC1  + (long)kNTOT * kF1;
constexpr long OFF_XWS2 = OFF_XW2  + (long)kNTOT * kF2;          // contiguous after XW2
constexpr long OFF_EMB  = OFF_XWS2 + (long)kNTOT * kF2;
constexpr long OFF_DISS = OFF_EMB  + (long)kNTOT * 256;
constexpr long OFF_DEGS = OFF_DISS + (long)kNTOT;                // int
constexpr long OFF_H1   = OFF_DEGS + (long)kNTOT;
constexpr long OFF_NS   = OFF_H1   + (long)kBZ * 256;            // int, kNTOT+1
constexpr long OFF_CUR  = OFF_NS   + (long)kNTOT + 4;            // int
constexpr long OFF_ESRC = OFF_CUR  + (long)kNTOT;                // int, kE
constexpr long OFF_XW1H = OFF_ESRC + (long)kE;                   // half, kNTOT*kF1
constexpr long OFF_XWS2H= OFF_XW1H + (long)kNTOT * kF1 / 2;      // half, kNTOT*kF2
constexpr long SCRATCH_FLOATS = OFF_XWS2H + (long)kNTOT * kF2 / 2;

__device__ __align__(16) float g_scratch[SCRATCH_FLOATS];

// ---------------------------------------------------------------------------
// tf32 / ldmatrix helpers
// ---------------------------------------------------------------------------
__device__ __forceinline__ uint32_t f2tf(float x) {
    uint32_t r;
    asm("cvt.rna.tf32.f32 %0, %1;" : "=r"(r) : "f"(x));
    return r;
}
__device__ __forceinline__ void mma_tf32(float* d, const uint32_t* a,
                                         uint32_t b0, uint32_t b1) {
    asm volatile(
        "mma.sync.aligned.m16n8k8.row.col.f32.tf32.tf32.f32 "
        "{%0,%1,%2,%3},{%4,%5,%6,%7},{%8,%9},{%0,%1,%2,%3};"
        : "+f"(d[0]), "+f"(d[1]), "+f"(d[2]), "+f"(d[3])
        : "r"(a[0]), "r"(a[1]), "r"(a[2]), "r"(a[3]), "r"(b0), "r"(b1));
}
__device__ __forceinline__ void ldsm4(uint32_t* r, uint32_t addr) {
    asm volatile("ldmatrix.sync.aligned.m8n8.x4.shared.b16 {%0,%1,%2,%3}, [%4];"
                 : "=r"(r[0]), "=r"(r[1]), "=r"(r[2]), "=r"(r[3]) : "r"(addr));
}
__device__ __forceinline__ uint32_t smem_u32(const void* p) {
    return (uint32_t)__cvta_generic_to_shared(p);
}

// ---------------------------------------------------------------------------
// Small kernels
// ---------------------------------------------------------------------------
__global__ void k_zeroD(float* h1, float* degD) {
    int i = blockIdx.x * 256 + threadIdx.x;
    if (i < kNTOT) degD[i] = 1.f;
    if (i < kBZ * 256) h1[i] = 0.f;
}
__global__ void k_zeroS(int* degS) {
    int i = blockIdx.x * 256 + threadIdx.x;
    if (i < kNTOT) degS[i] = 0;
}

__global__ void k_lslr(const float* __restrict__ t, const float* __restrict__ fcw,
                       const float* __restrict__ fcb,
                       float* __restrict__ Eg, float* __restrict__ Fg) {
    int warp = (blockIdx.x * blockDim.x + threadIdx.x) >> 5;
    int lane = threadIdx.x & 31;
    if (warp >= kNTOT) return;
    const float* tn = t + (long)warp * kTC;
    const float* w0 = fcw;
    const float* w1 = fcw + 512;
    float s0 = 0.f, s1 = 0.f, r0 = 0.f, r1 = 0.f;
#pragma unroll
    for (int q = 0; q < 8; q++) {
        int d = lane + 32 * q;
        float u = fmaxf(tn[d], 0.f);
        s0 += u * w0[d];       s1 += u * w1[d];
        r0 += u * w0[256 + d]; r1 += u * w1[256 + d];
    }
#pragma unroll
    for (int off = 16; off; off >>= 1) {
        s0 += __shfl_down_sync(0xffffffffu, s0, off);
        s1 += __shfl_down_sync(0xffffffffu, s1, off);
        r0 += __shfl_down_sync(0xffffffffu, r0, off);
        r1 += __shfl_down_sync(0xffffffffu, r1, off);
    }
    if (lane == 0) {
        Eg[warp] = expf(r1 - r0 + fcb[1] - fcb[0]);
        Fg[warp] = expf(s1 - s0);
    }
}

__global__ void k_buildA(const float* __restrict__ gu,
                         const float* __restrict__ Eg, const float* __restrict__ Fg,
                         unsigned char* __restrict__ A8) {
    int idx = blockIdx.x * 256 + threadIdx.x;
    int j0 = (idx & 127) << 2;
    int i  = (idx >> 7) & 511;
    int b  = idx >> 16;
    float Ei = Eg[b * kN + i];
    float4 Fv = *reinterpret_cast<const float4*>(Fg + b * kN + j0);
    const float4* g4 = reinterpret_cast<const float4*>(
        gu + ((long)(b * kN + i) * kN + j0) * 2);
    float4 u01 = g4[0];
    float4 u23 = g4[1];
    auto bit = [&](float ux, float uy, float Fj) -> unsigned char {
        ux = fminf(fmaxf(ux, 1e-9f), 1.0f - 1e-9f);
        uy = fminf(fmaxf(uy, 1e-9f), 1.0f - 1e-9f);
        float l0 = -__logf(ux);
        float l1 = -__logf(uy);
        return (l1 >= l0 * Ei * Fj) ? 1 : 0;
    };
    uchar4 r;
    r.x = bit(u01.x, u01.y, Fv.x);
    r.y = bit(u01.z, u01.w, Fv.y);
    r.z = bit(u23.x, u23.y, Fv.z);
    r.w = bit(u23.z, u23.w, Fv.w);
    *reinterpret_cast<uchar4*>(A8 + (long)(b * kN + i) * kN + j0) = r;
}

__global__ void k_colsum_part(const unsigned char* __restrict__ A8,
                              float* __restrict__ degD) {
    int b = blockIdx.x;
    int j = threadIdx.x;
    int r0 = blockIdx.y * 64;
    const unsigned char* Ab = A8 + (long)b * kN * kN;
    int s = 0;
#pragma unroll 8
    for (int r = r0; r < r0 + 64; r++) s += Ab[(long)r * kN + j];
    atomicAdd(&degD[b * kN + j], (float)s);
}

__global__ void k_degS(const int* __restrict__ colp, int* degS) {
    int e = blockIdx.x * 256 + threadIdx.x;
    if (e < kE) atomicAdd(&degS[colp[e]], 1);
}

__global__ void k_disD(const float* __restrict__ degD, float* __restrict__ disD) {
    int i = blockIdx.x * 256 + threadIdx.x;
    if (i < kNTOT) disD[i] = rsqrtf(degD[i]);
}
__global__ void k_disS(const int* __restrict__ degS, float* __restrict__ disS) {
    int i = blockIdx.x * 256 + threadIdx.x;
    if (i < kNTOT) disS[i] = rsqrtf((float)degS[i] + 1.f);
}

__global__ void k_scan(const int* __restrict__ degS, int* __restrict__ ns,
                       int* __restrict__ cur) {
    __shared__ int sm[1024];
    int tid = threadIdx.x;
    int base = tid * 16;
    int local[16];
    int sum = 0;
#pragma unroll
    for (int v = 0; v < 16; v++) { local[v] = degS[base + v]; sum += local[v]; }
    sm[tid] = sum;
    __syncthreads();
    for (int off = 1; off < 1024; off <<= 1) {
        int v = (tid >= off) ? sm[tid - off] : 0;
        __syncthreads();
        sm[tid] += v;
        __syncthreads();
    }
    int run = sm[tid] - sum;
#pragma unroll
    for (int v = 0; v < 16; v++) {
        ns[base + v] = run;
        cur[base + v] = run;
        run += local[v];
    }
    if (tid == 1023) ns[kNTOT] = run;
}

__global__ void k_fill(const int* __restrict__ rowp, const int* __restrict__ colp,
                       int* cur, int* __restrict__ esrc) {
    int e = blockIdx.x * 256 + threadIdx.x;
    if (e < kE) {
        int c = colp[e];
        int p = atomicAdd(&cur[c], 1);
        esrc[p] = rowp[e];
    }
}

// ---------------------------------------------------------------------------
// fp16 CSR gather: one warp per node; VH half2 per lane (F = VH*64).
// ---------------------------------------------------------------------------
template <int VH>
__global__ __launch_bounds__(256) void k_gather_h(
        const int* __restrict__ ns, const int* __restrict__ esrc,
        const __half2* __restrict__ xwh, const float* __restrict__ disS,
        const float* __restrict__ bias, float* __restrict__ out,
        int outStride, int outOffset) {
    constexpr int F2 = VH * 32;
    int node = (blockIdx.x * 256 + threadIdx.x) >> 5;
    int lane = threadIdx.x & 31;
    if (node >= kNTOT) return;
    int off2 = lane * VH;
    float dc = disS[node];
    float2 acc[VH];

    auto loadrow = [&](long r, uint32_t* rw) {
        const char* p = reinterpret_cast<const char*>(xwh + r * F2 + off2);
        if (VH == 4) {
            uint4 u = *reinterpret_cast<const uint4*>(p);
            rw[0] = u.x; rw[1] = u.y; rw[2] = u.z; rw[3] = u.w;
        } else {
            uint2 u = *reinterpret_cast<const uint2*>(p);
            rw[0] = u.x; rw[1] = u.y;
        }
    };

    {
        uint32_t rw[VH];
        loadrow(node, rw);
        float d2 = dc * dc;
#pragma unroll
        for (int v = 0; v < VH; v++) {
            float2 xv = __half22float2(*reinterpret_cast<__half2*>(&rw[v]));
            float2 bb = *reinterpret_cast<const float2*>(bias + (off2 + v) * 2);
            acc[v] = make_float2(xv.x * d2 + bb.x, xv.y * d2 + bb.y);
        }
    }
    int s = ns[node], e = ns[node + 1];
    int i = s;
    for (; i + 8 <= e; i += 8) {
        int r[8];
        float sc[8];
        uint32_t rw[8][VH];
#pragma unroll
        for (int q = 0; q < 8; q++) r[q] = esrc[i + q];
#pragma unroll
        for (int q = 0; q < 8; q++) sc[q] = disS[r[q]] * dc;
#pragma unroll
        for (int q = 0; q < 8; q++) loadrow(r[q], rw[q]);
#pragma unroll
        for (int q = 0; q < 8; q++)
#pragma unroll
            for (int v = 0; v < VH; v++) {
                float2 xv = __half22float2(*reinterpret_cast<__half2*>(&rw[q][v]));
                acc[v].x += xv.x * sc[q];
                acc[v].y += xv.y * sc[q];
            }
    }
    for (; i < e; i++) {
        int r = esrc[i];
        float sr = disS[r] * dc;
        uint32_t rw[VH];
        loadrow(r, rw);
#pragma unroll
        for (int v = 0; v < VH; v++) {
            float2 xv = __half22float2(*reinterpret_cast<__half2*>(&rw[v]));
            acc[v].x += xv.x * sr;
            acc[v].y += xv.y * sr;
        }
    }
    float* op = out + (long)node * outStride + outOffset + off2 * 2;
#pragma unroll
    for (int v = 0; v < VH; v++)
        *reinterpret_cast<float2*>(op + v * 2) = acc[v];
}

// ---------------------------------------------------------------------------
// tf32 NT GEMM with ldmatrix fragment loads + optional fp16 mirror output.
// ---------------------------------------------------------------------------
template <bool RELU_A>
__global__ __launch_bounds__(256) void k_gemm_tf32(
        const float* __restrict__ A, long aStride,
        const float* __restrict__ B,
        float* __restrict__ C, long cStride,
        int Nf, int K, __half* __restrict__ Ch, int hRowStart) {
    __shared__ uint32_t As[2][128][20];
    __shared__ uint32_t Bs[2][128][20];
    const float* Ab = A + (long)blockIdx.z * aStride;
    float* Cb = C + (long)blockIdx.z * cStride;
    int m0 = blockIdx.y * 128, n0 = blockIdx.x * 128;
    int t = threadIdx.x;
    int wid = t >> 5, lane = t & 31;
    int mw = (wid >> 1) * 32, nw = (wid & 1) * 64;
    int g = lane >> 2, tg = lane & 3;
    int lrow16 = lane & 15;
    int lhalf4 = (lane >> 4) * 4;
    int lr = t >> 2, lc = (t & 3) << 2;

    uint32_t sA[2] = { smem_u32(&As[0][0][0]), smem_u32(&As[1][0][0]) };
    uint32_t sB[2] = { smem_u32(&Bs[0][0][0]), smem_u32(&Bs[1][0][0]) };

    float acc[2][8][4];
#pragma unroll
    for (int i = 0; i < 2; i++)
#pragma unroll
        for (int j = 0; j < 8; j++)
#pragma unroll
            for (int c = 0; c < 4; c++) acc[i][j][c] = 0.f;

    const float* aP0 = Ab + (long)(m0 + lr) * K + lc;
    const float* aP1 = Ab + (long)(m0 + lr + 64) * K + lc;
    const float* bP0 = B + (long)(n0 + lr) * K + lc;
    const float* bP1 = B + (long)(n0 + lr + 64) * K + lc;

    auto cvt4 = [](float4 v, bool relu) -> uint4 {
        if (relu) {
            v.x = fmaxf(v.x, 0.f); v.y = fmaxf(v.y, 0.f);
            v.z = fmaxf(v.z, 0.f); v.w = fmaxf(v.w, 0.f);
        }
        uint4 r;
        r.x = f2tf(v.x); r.y = f2tf(v.y); r.z = f2tf(v.z); r.w = f2tf(v.w);
        return r;
    };

    {
        uint4 a0 = cvt4(*reinterpret_cast<const float4*>(aP0), RELU_A);
        uint4 a1 = cvt4(*reinterpret_cast<const float4*>(aP1), RELU_A);
        uint4 b0 = cvt4(*reinterpret_cast<const float4*>(bP0), false);
        uint4 b1 = cvt4(*reinterpret_cast<const float4*>(bP1), false);
        *reinterpret_cast<uint4*>(&As[0][lr][lc]) = a0;
        *reinterpret_cast<uint4*>(&As[0][lr + 64][lc]) = a1;
        *reinterpret_cast<uint4*>(&Bs[0][lr][lc]) = b0;
        *reinterpret_cast<uint4*>(&Bs[0][lr + 64][lc]) = b1;
    }
    __syncthreads();

    int buf = 0;
    for (int k0 = 0; k0 < K; k0 += 16) {
        bool more = (k0 + 16) < K;
        float4 na0, na1, nb0, nb1;
        if (more) {
            na0 = *reinterpret_cast<const float4*>(aP0 + k0 + 16);
            na1 = *reinterpret_cast<const float4*>(aP1 + k0 + 16);
            nb0 = *reinterpret_cast<const float4*>(bP0 + k0 + 16);
            nb1 = *reinterpret_cast<const float4*>(bP1 + k0 + 16);
        }
#pragma unroll
        for (int s = 0; s < 2; s++) {
            int kcol = s * 8 + lhalf4;
            uint32_t af0[4], af1[4];
            ldsm4(af0, sA[buf] + ((mw + lrow16) * 20 + kcol) * 4);
            ldsm4(af1, sA[buf] + ((mw + 16 + lrow16) * 20 + kcol) * 4);
#pragma unroll
            for (int p = 0; p < 4; p++) {
                uint32_t bf[4];
                ldsm4(bf, sB[buf] + ((nw + p * 16 + lrow16) * 20 + kcol) * 4);
                mma_tf32(acc[0][2 * p],     af0, bf[0], bf[2]);
                mma_tf32(acc[0][2 * p + 1], af0, bf[1], bf[3]);
                mma_tf32(acc[1][2 * p],     af1, bf[0], bf[2]);
                mma_tf32(acc[1][2 * p + 1], af1, bf[1], bf[3]);
            }
        }
        if (more) {
            int nb = buf ^ 1;
            *reinterpret_cast<uint4*>(&As[nb][lr][lc]) = cvt4(na0, RELU_A);
            *reinterpret_cast<uint4*>(&As[nb][lr + 64][lc]) = cvt4(na1, RELU_A);
            *reinterpret_cast<uint4*>(&Bs[nb][lr][lc]) = cvt4(nb0, false);
            *reinterpret_cast<uint4*>(&Bs[nb][lr + 64][lc]) = cvt4(nb1, false);
            __syncthreads();
            buf = nb;
        }
    }

    bool doH = (Ch != nullptr) && (m0 >= hRowStart);
#pragma unroll
    for (int mt = 0; mt < 2; mt++) {
        int row = m0 + mw + mt * 16 + g;
#pragma unroll
        for (int j = 0; j < 8; j++) {
            int col = n0 + nw + j * 8 + 2 * tg;
            float2 v0 = make_float2(acc[mt][j][0], acc[mt][j][1]);
            float2 v1 = make_float2(acc[mt][j][2], acc[mt][j][3]);
            *reinterpret_cast<float2*>(Cb + (long)row * Nf + col) = v0;
            *reinterpret_cast<float2*>(Cb + (long)(row + 8) * Nf + col) = v1;
            if (doH) {
                long hr = row - hRowStart;
                *reinterpret_cast<__half2*>(Ch + hr * Nf + col) =
                    __floats2half2_rn(v0.x, v0.y);
                *reinterpret_cast<__half2*>(Ch + (hr + 8) * Nf + col) =
                    __floats2half2_rn(v1.x, v1.y);
            }
        }
    }
}

// ---------------------------------------------------------------------------
// tf32 dense GCN propagation — A tiles loaded as uint8, expanded to tf32 one-bits
// ---------------------------------------------------------------------------
template <bool RELU>
__global__ __launch_bounds__(256) void k_prop_tf32(
        const unsigned char* __restrict__ Adj8, const float* __restrict__ XW,
        const float* __restrict__ dis, const float* __restrict__ bias,
        float* __restrict__ out, int F, int outStride, int outOffset) {
    __shared__ uint32_t As[2][16][136];
    __shared__ uint32_t Bs[2][16][136];
    int b = blockIdx.z;
    const unsigned char* Ab = Adj8 + (long)b * kN * kN;
    const float* Xb = XW + (long)b * kN * F;
    const float* db = dis + b * kN;
    float* Ob = out + (long)b * kN * outStride + outOffset;
    int i0 = blockIdx.y * 128, f0 = blockIdx.x * 128;
    int t = threadIdx.x;
    int wid = t >> 5, lane = t & 31;
    int mw = (wid >> 1) * 32, nw = (wid & 1) * 64;
    int g = lane >> 2, tg = lane & 3;
    int jj = t >> 4;
    int ii = (t & 15) << 3;

    float acc[2][8][4];
#pragma unroll
    for (int i = 0; i < 2; i++)
#pragma unroll
        for (int j = 0; j < 8; j++)
#pragma unroll
            for (int c = 0; c < 4; c++) acc[i][j][c] = 0.f;

    constexpr uint32_t ONE = 0x3F800000u;
    auto stTile = [&](int bufI, uint2 rawA, float4 x0, float4 x1, float dj) {
        uint4 ua0, ua1, ux0, ux1;
        ua0.x = (rawA.x & 0xffu)         ? ONE : 0u;
        ua0.y = ((rawA.x >> 8) & 0xffu)  ? ONE : 0u;
        ua0.z = ((rawA.x >> 16) & 0xffu) ? ONE : 0u;
        ua0.w = ((rawA.x >> 24) & 0xffu) ? ONE : 0u;
        ua1.x = (rawA.y & 0xffu)         ? ONE : 0u;
        ua1.y = ((rawA.y >> 8) & 0xffu)  ? ONE : 0u;
        ua1.z = ((rawA.y >> 16) & 0xffu) ? ONE : 0u;
        ua1.w = ((rawA.y >> 24) & 0xffu) ? ONE : 0u;
        ux0.x = f2tf(x0.x * dj); ux0.y = f2tf(x0.y * dj);
        ux0.z = f2tf(x0.z * dj); ux0.w = f2tf(x0.w * dj);
        ux1.x = f2tf(x1.x * dj); ux1.y = f2tf(x1.y * dj);
        ux1.z = f2tf(x1.z * dj); ux1.w = f2tf(x1.w * dj);
        *reinterpret_cast<uint4*>(&As[bufI][jj][ii]) = ua0;
        *reinterpret_cast<uint4*>(&As[bufI][jj][ii + 4]) = ua1;
        *reinterpret_cast<uint4*>(&Bs[bufI][jj][ii]) = ux0;
        *reinterpret_cast<uint4*>(&Bs[bufI][jj][ii + 4]) = ux1;
    };

    {
        uint2 rawA = *reinterpret_cast<const uint2*>(Ab + (long)jj * kN + i0 + ii);
        const float* xp = Xb + (long)jj * F + f0 + ii;
        stTile(0, rawA,
               *reinterpret_cast<const float4*>(xp),
               *reinterpret_cast<const float4*>(xp + 4),
               db[jj]);
    }
    __syncthreads();

    int buf = 0;
    for (int j0 = 0; j0 < kN; j0 += 16) {
        bool more = (j0 + 16) < kN;
        uint2 nraw;
        float4 nx0, nx1;
        float djn = 0.f;
        if (more) {
            nraw = *reinterpret_cast<const uint2*>(
                Ab + (long)(j0 + 16 + jj) * kN + i0 + ii);
            const float* xp = Xb + (long)(j0 + 16 + jj) * F + f0 + ii;
            nx0 = *reinterpret_cast<const float4*>(xp);
            nx1 = *reinterpret_cast<const float4*>(xp + 4);
            djn = db[j0 + 16 + jj];
        }
#pragma unroll
        for (int s = 0; s < 2; s++) {
            int kk = s * 8 + tg;
            uint32_t af[2][4];
#pragma unroll
            for (int mt = 0; mt < 2; mt++) {
                int m = mw + mt * 16 + g;
                af[mt][0] = As[buf][kk][m];
                af[mt][1] = As[buf][kk][m + 8];
                af[mt][2] = As[buf][kk + 4][m];
                af[mt][3] = As[buf][kk + 4][m + 8];
            }
#pragma unroll
            for (int j = 0; j < 8; j++) {
                int n = nw + j * 8 + g;
                uint32_t b0 = Bs[buf][kk][n];
                uint32_t b1 = Bs[buf][kk + 4][n];
                mma_tf32(acc[0][j], af[0], b0, b1);
                mma_tf32(acc[1][j], af[1], b0, b1);
            }
        }
        if (more) {
            int nb = buf ^ 1;
            stTile(nb, nraw, nx0, nx1, djn);
            __syncthreads();
            buf = nb;
        }
    }

#pragma unroll
    for (int mt = 0; mt < 2; mt++) {
        int rowA = i0 + mw + mt * 16 + g;
        float diA = db[rowA], diB = db[rowA + 8];
#pragma unroll
        for (int j = 0; j < 8; j++) {
            int col = f0 + nw + j * 8 + 2 * tg;
            float2 bb = *reinterpret_cast<const float2*>(bias + col);
            float2 xA = *reinterpret_cast<const float2*>(Xb + (long)rowA * F + col);
            float2 xB = *reinterpret_cast<const float2*>(Xb + (long)(rowA + 8) * F + col);
            float v0 = diA * (acc[mt][j][0] + diA * xA.x) + bb.x;
            float v1 = diA * (acc[mt][j][1] + diA * xA.y) + bb.y;
            float v2 = diB * (acc[mt][j][2] + diB * xB.x) + bb.x;
            float v3 = diB * (acc[mt][j][3] + diB * xB.y) + bb.y;
            if (RELU) {
                v0 = fmaxf(v0, 0.f); v1 = fmaxf(v1, 0.f);
                v2 = fmaxf(v2, 0.f); v3 = fmaxf(v3, 0.f);
            }
            *reinterpret_cast<float2*>(Ob + (long)rowA * outStride + col) =
                make_float2(v0, v1);
            *reinterpret_cast<float2*>(Ob + (long)(rowA + 8) * outStride + col) =
                make_float2(v2, v3);
        }
    }
}

// ---------------------------------------------------------------------------
// fcn1 split-K, register double-buffered
// ---------------------------------------------------------------------------
__global__ void k_fcn1(const float* __restrict__ emb, const float* __restrict__ W,
                       float* __restrict__ h1) {
    constexpr int KC = kKTOT / 128;
    __shared__ float As[16][32];
    __shared__ float Bs[16][64];
    int n0 = blockIdx.x * 64;
    int kbase = blockIdx.y * KC;
    int t = threadIdx.x;
    int m = t & 31;
    int nb = (t >> 5) << 3;
    int row = t >> 2, c4 = (t & 3) << 2;
    float acc[8];
#pragma unroll
    for (int j = 0; j < 8; j++) acc[j] = 0.f;

    float4 aPre, bPre;
    if (t < 128)
        aPre = *reinterpret_cast<const float4*>(emb + (long)row * kKTOT + kbase + c4);
    bPre = *reinterpret_cast<const float4*>(W + (long)(n0 + row) * kKTOT + kbase + c4);

    for (int k0 = kbase; k0 < kbase + KC; k0 += 16) {
        if (t < 128) {
            As[c4 + 0][row] = aPre.x; As[c4 + 1][row] = aPre.y;
            As[c4 + 2][row] = aPre.z; As[c4 + 3][row] = aPre.w;
        }
        Bs[c4 + 0][row] = bPre.x; Bs[c4 + 1][row] = bPre.y;
        Bs[c4 + 2][row] = bPre.z; Bs[c4 + 3][row] = bPre.w;
        __syncthreads();
        bool more = (k0 + 16) < kbase + KC;
        if (more) {
            if (t < 128)
                aPre = *reinterpret_cast<const float4*>(
                    emb + (long)row * kKTOT + k0 + 16 + c4);
            bPre = *reinterpret_cast<const float4*>(
                W + (long)(n0 + row) * kKTOT + k0 + 16 + c4);
        }
#pragma unroll
        for (int k = 0; k < 16; k++) {
            float a = As[k][m];
#pragma unroll
            for (int j = 0; j < 8; j++) acc[j] += a * Bs[k][nb + j];
        }
        __syncthreads();
    }
#pragma unroll
    for (int j = 0; j < 8; j++)
        atomicAdd(&h1[m * 256 + n0 + nb + j], acc[j]);
}

__global__ void k_fcn23(const float* __restrict__ h1g,
                        const float* __restrict__ b1, const float* __restrict__ w2,
                        const float* __restrict__ b2, const float* __restrict__ w3,
                        const float* __restrict__ b3, float* __restrict__ out) {
    __shared__ float h1s[32][256];
    __shared__ float h2s[32][32];
    int t = threadIdx.x;
    for (int idx = t; idx < 32 * 256; idx += 1024) {
        float v = h1g[idx] + b1[idx & 255];
        h1s[idx >> 8][idx & 255] = (v >= 0.f) ? v : 0.2f * v;
    }
    __syncthreads();
    {
        int b = t >> 5, o = t & 31;
        float s = 0.f;
#pragma unroll 8
        for (int k = 0; k < 256; k++) s += h1s[b][k] * w2[o * 256 + k];
        s += b2[o];
        h2s[b][o] = (s >= 0.f) ? s : 0.2f * s;
    }
    __syncthreads();
    if (t < 64) {
        int b = t >> 1, o = t & 1;
        float s = 0.f;
#pragma unroll
        for (int k = 0; k < 32; k++) s += h2s[b][k] * w3[o * 32 + k];
        out[b * 2 + o] = s + b3[o];
    }
}

// ---------------------------------------------------------------------------
// Launch — fork/join across 2 side streams (created once; capture-legal)
// ---------------------------------------------------------------------------
extern "C" void kernel_launch(void* const* d_in, const int* in_sizes, int n_in,
                              void* d_out, int out_size) {
    const float* x    = (const float*)d_in[0];
    const float* t    = (const float*)d_in[1];
    const float* gu   = (const float*)d_in[2];
    const int*   ei   = (const int*)d_in[3];
    const float* w1   = (const float*)d_in[4];
    const float* b1   = (const float*)d_in[5];
    const float* w2   = (const float*)d_in[6];
    const float* b2   = (const float*)d_in[7];
    const float* fcw  = (const float*)d_in[8];
    const float* fcb  = (const float*)d_in[9];
    const float* f1w  = (const float*)d_in[10];
    const float* f1b  = (const float*)d_in[11];
    const float* f2w  = (const float*)d_in[12];
    const float* f2b  = (const float*)d_in[13];
    const float* f3w  = (const float*)d_in[14];
    const float* f3b  = (const float*)d_in[15];
    float* out = (float*)d_out;

    const int* rowp = ei;
    const int* colp = ei + kE;

    float* base = nullptr;
    cudaGetSymbolAddress((void**)&base, g_scratch);
    float* p_E     = base + OFF_EG;
    float* p_F     = base + OFF_FG;
    unsigned char* p_A8 = (unsigned char*)(base + OFF_A8);
    float* p_disD  = base + OFF_DISD;
    float* p_degD  = base + OFF_DEGD;
    float* p_xw1   = base + OFF_XW1;
    float* p_h     = base + OFF_H;
    float* p_sc1   = base + OFF_SC1;
    float* p_xw2   = base + OFF_XW2;
    float* p_emb   = base + OFF_EMB;
    float* p_disS  = base + OFF_DISS;
    int*   p_degS  = (int*)(base + OFF_DEGS);
    float* p_h1    = base + OFF_H1;
    int*   p_ns    = (int*)(base + OFF_NS);
    int*   p_cur   = (int*)(base + OFF_CUR);
    int*   p_esrc  = (int*)(base + OFF_ESRC);
    __half* p_xw1h  = (__half*)(base + OFF_XW1H);
    __half* p_xws2h = (__half*)(base + OFF_XWS2H);

    // one-time stream/event setup (no device memory allocations)
    static cudaStream_t sG = nullptr, sC = nullptr;
    static cudaEvent_t evStart, evG1, evCSR, evGa1, evG2, evGa2;
    if (!sG) {
        cudaStreamCreateWithFlags(&sG, cudaStreamNonBlocking);
        cudaStreamCreateWithFlags(&sC, cudaStreamNonBlocking);
        cudaEventCreateWithFlags(&evStart, cudaEventDisableTiming);
        cudaEventCreateWithFlags(&evG1, cudaEventDisableTiming);
        cudaEventCreateWithFlags(&evCSR, cudaEventDisableTiming);
        cudaEventCreateWithFlags(&evGa1, cudaEventDisableTiming);
        cudaEventCreateWithFlags(&evG2, cudaEventDisableTiming);
        cudaEventCreateWithFlags(&evGa2, cudaEventDisableTiming);
    }

    cudaEventRecord(evStart, 0);
    cudaStreamWaitEvent(sG, evStart, 0);
    cudaStreamWaitEvent(sC, evStart, 0);

    // main stream: dense prep chain
    k_zeroD<<<64, 256>>>(p_h1, p_degD);                               // 1
    k_lslr<<<kNTOT / 8, 256>>>(t, fcw, fcb, p_E, p_F);                // 2
    k_buildA<<<kBZ * kN * kN / 1024, 256>>>(gu, p_E, p_F, p_A8);      // 3

    // sG: gemm1 (concurrent with prep)                                // 4 (captured)
    k_gemm_tf32<false><<<dim3(kF1 / 128, kNTOT / 128, 1), 256, 0, sG>>>(
        x, 0, w1, p_xw1, 0, kF1, kN, p_xw1h, 0);
    cudaEventRecord(evG1, sG);

    // main: dense degrees
    k_colsum_part<<<dim3(kBZ, 8), kN>>>(p_A8, p_degD);
    k_disD<<<kNTOT / 256, 256>>>(p_degD, p_disD);

    // sC: CSR chain (concurrent with prep + gemm1)
    k_zeroS<<<64, 256, 0, sC>>>(p_degS);
    k_degS<<<kE / 256, 256, 0, sC>>>(colp, p_degS);
    k_disS<<<kNTOT / 256, 256, 0, sC>>>(p_degS, p_disS);
    k_scan<<<1, 1024, 0, sC>>>(p_degS, p_ns, p_cur);
    k_fill<<<kE / 256, 256, 0, sC>>>(rowp, colp, p_cur, p_esrc);
    cudaEventRecord(evCSR, sC);

    // main: prop1 (needs gemm1 + A8 + disD)
    cudaStreamWaitEvent(0, evG1, 0);
    k_prop_tf32<true><<<dim3(kF1 / 128, kN / 128, kBZ), 256>>>(
        p_A8, p_xw1, p_disD, b1, p_h, kF1, kF1, 0);

    // sG: gather1 (needs gemm1 [same stream] + CSR + disS), concurrent w/ prop1
    cudaStreamWaitEvent(sG, evCSR, 0);
    k_gather_h<4><<<kNTOT / 8, 256, 0, sG>>>(p_ns, p_esrc,
        (const __half2*)p_xw1h, p_disS, b1, p_sc1, kF1, 0);
    cudaEventRecord(evGa1, sG);

    // main: merged gemm2 (needs prop1 [this stream] + gather1)
    cudaStreamWaitEvent(0, evGa1, 0);
    k_gemm_tf32<true><<<dim3(kF2 / 128, 2 * kNTOT / 128, 1), 256>>>(
        p_h, 0, w2, p_xw2, 0, kF2, kF1, p_xws2h, kNTOT);
    cudaEventRecord(evG2, 0);

    // sG: gather2 (needs gemm2), concurrent with prop2
    cudaStreamWaitEvent(sG, evG2, 0);
    k_gather_h<2><<<kNTOT / 8, 256, 0, sG>>>(p_ns, p_esrc,
        (const __half2*)p_xws2h, p_disS, b2, p_emb, 256, 128);
    cudaEventRecord(evGa2, sG);

    // main: prop2 -> emb[:, 0:128]
    k_prop_tf32<false><<<dim3(kF2 / 128, kN / 128, kBZ), 256>>>(
        p_A8, p_xw2, p_disD, b2, p_emb, kF2, 256, 0);

    // join + head
    cudaStreamWaitEvent(0, evGa2, 0);
    k_fcn1<<<dim3(256 / 64, 128), 256>>>(p_emb, f1w, p_h1);
    k_fcn23<<<1, 1024>>>(p_h1, f1b, f2w, f2b, f3w, f3b, out);
}

// round 11
// speedup vs baseline: 1.2123x; 1.0440x over previous
#include <cuda_runtime.h>
#include <cuda_fp16.h>
#include <cstdint>

// ---------------------------------------------------------------------------
// Problem constants
// ---------------------------------------------------------------------------
constexpr int kN    = 512;
constexpr int kBZ   = 32;
constexpr int kTC   = 256;
constexpr int kF1   = 256;
constexpr int kF2   = 128;
constexpr int kE    = 524288;
constexpr int kNTOT = kBZ * kN;          // 16384
constexpr int kKTOT = kF2 * 2 * kN;      // 131072

// ---------------------------------------------------------------------------
// Scratch (offsets in floats)
// ---------------------------------------------------------------------------
constexpr long OFF_EG   = 0;
constexpr long OFF_FG   = OFF_EG   + (long)kNTOT;
constexpr long OFF_A8   = OFF_FG   + (long)kNTOT;                // u8 view
constexpr long OFF_DISD = OFF_A8   + (long)kBZ * kN * kN / 4;
constexpr long OFF_DEGD = OFF_DISD + (long)kNTOT;
constexpr long OFF_XW1  = OFF_DEGD + (long)kNTOT;
constexpr long OFF_H    = OFF_XW1  + (long)kNTOT * kF1;
constexpr long OFF_SC1  = OFF_H    + (long)kNTOT * kF1;
constexpr long OFF_XW2  = OFF_SC1  + (long)kNTOT * kF1;
constexpr long OFF_XWS2 = OFF_XW2  + (long)kNTOT * kF2;
constexpr long OFF_EMB  = OFF_XWS2 + (long)kNTOT * kF2;
constexpr long OFF_DISS = OFF_EMB  + (long)kNTOT * 256;
constexpr long OFF_DEGS = OFF_DISS + (long)kNTOT;                // int
constexpr long OFF_H1   = OFF_DEGS + (long)kNTOT;
constexpr long OFF_NS   = OFF_H1   + (long)kBZ * 256;            // int, kNTOT+1
constexpr long OFF_CUR  = OFF_NS   + (long)kNTOT + 4;            // int
constexpr long OFF_ESRC = OFF_CUR  + (long)kNTOT;                // int, kE
constexpr long OFF_XW1H = OFF_ESRC + (long)kE;                   // half
constexpr long OFF_XWS2H= OFF_XW1H + (long)kNTOT * kF1 / 2;      // half
constexpr long SCRATCH_FLOATS = OFF_XWS2H + (long)kNTOT * kF2 / 2;

__device__ __align__(16) float g_scratch[SCRATCH_FLOATS];

// ---------------------------------------------------------------------------
// tf32 / ldmatrix helpers
// ---------------------------------------------------------------------------
__device__ __forceinline__ uint32_t f2tf(float x) {
    uint32_t r;
    asm("cvt.rna.tf32.f32 %0, %1;" : "=r"(r) : "f"(x));
    return r;
}
__device__ __forceinline__ void mma_tf32(float* d, const uint32_t* a,
                                         uint32_t b0, uint32_t b1) {
    asm volatile(
        "mma.sync.aligned.m16n8k8.row.col.f32.tf32.tf32.f32 "
        "{%0,%1,%2,%3},{%4,%5,%6,%7},{%8,%9},{%0,%1,%2,%3};"
        : "+f"(d[0]), "+f"(d[1]), "+f"(d[2]), "+f"(d[3])
        : "r"(a[0]), "r"(a[1]), "r"(a[2]), "r"(a[3]), "r"(b0), "r"(b1));
}
__device__ __forceinline__ void ldsm4(uint32_t* r, uint32_t addr) {
    asm volatile("ldmatrix.sync.aligned.m8n8.x4.shared.b16 {%0,%1,%2,%3}, [%4];"
                 : "=r"(r[0]), "=r"(r[1]), "=r"(r[2]), "=r"(r[3]) : "r"(addr));
}
__device__ __forceinline__ uint32_t smem_u32(const void* p) {
    return (uint32_t)__cvta_generic_to_shared(p);
}

// ---------------------------------------------------------------------------
// Small kernels
// ---------------------------------------------------------------------------
__global__ void k_zeroD(float* degD) {
    int i = blockIdx.x * 256 + threadIdx.x;
    if (i < kNTOT) degD[i] = 1.f;
}
__global__ void k_zeroS(int* degS, float* h1) {
    int i = blockIdx.x * 256 + threadIdx.x;
    if (i < kNTOT) degS[i] = 0;
    if (i < kBZ * 256) h1[i] = 0.f;
}

__global__ void k_lslr(const float* __restrict__ t, const float* __restrict__ fcw,
                       const float* __restrict__ fcb,
                       float* __restrict__ Eg, float* __restrict__ Fg) {
    int warp = (blockIdx.x * blockDim.x + threadIdx.x) >> 5;
    int lane = threadIdx.x & 31;
    if (warp >= kNTOT) return;
    const float* tn = t + (long)warp * kTC;
    const float* w0 = fcw;
    const float* w1 = fcw + 512;
    float s0 = 0.f, s1 = 0.f, r0 = 0.f, r1 = 0.f;
#pragma unroll
    for (int q = 0; q < 8; q++) {
        int d = lane + 32 * q;
        float u = fmaxf(tn[d], 0.f);
        s0 += u * w0[d];       s1 += u * w1[d];
        r0 += u * w0[256 + d]; r1 += u * w1[256 + d];
    }
#pragma unroll
    for (int off = 16; off; off >>= 1) {
        s0 += __shfl_down_sync(0xffffffffu, s0, off);
        s1 += __shfl_down_sync(0xffffffffu, s1, off);
        r0 += __shfl_down_sync(0xffffffffu, r0, off);
        r1 += __shfl_down_sync(0xffffffffu, r1, off);
    }
    if (lane == 0) {
        Eg[warp] = expf(r1 - r0 + fcb[1] - fcb[0]);
        Fg[warp] = expf(s1 - s0);
    }
}

__global__ void k_buildA(const float* __restrict__ gu,
                         const float* __restrict__ Eg, const float* __restrict__ Fg,
                         unsigned char* __restrict__ A8) {
    int idx = blockIdx.x * 256 + threadIdx.x;
    int j0 = (idx & 127) << 2;
    int i  = (idx >> 7) & 511;
    int b  = idx >> 16;
    float Ei = Eg[b * kN + i];
    float4 Fv = *reinterpret_cast<const float4*>(Fg + b * kN + j0);
    const float4* g4 = reinterpret_cast<const float4*>(
        gu + ((long)(b * kN + i) * kN + j0) * 2);
    float4 u01 = g4[0];
    float4 u23 = g4[1];
    auto bit = [&](float ux, float uy, float Fj) -> unsigned char {
        ux = fminf(fmaxf(ux, 1e-9f), 1.0f - 1e-9f);
        uy = fminf(fmaxf(uy, 1e-9f), 1.0f - 1e-9f);
        float l0 = -__logf(ux);
        float l1 = -__logf(uy);
        return (l1 >= l0 * Ei * Fj) ? 1 : 0;
    };
    uchar4 r;
    r.x = bit(u01.x, u01.y, Fv.x);
    r.y = bit(u01.z, u01.w, Fv.y);
    r.z = bit(u23.x, u23.y, Fv.z);
    r.w = bit(u23.z, u23.w, Fv.w);
    *reinterpret_cast<uchar4*>(A8 + (long)(b * kN + i) * kN + j0) = r;
}

__global__ void k_colsum_part(const unsigned char* __restrict__ A8,
                              float* __restrict__ degD) {
    int b = blockIdx.x;
    int j = threadIdx.x;
    int r0 = blockIdx.y * 64;
    const unsigned char* Ab = A8 + (long)b * kN * kN;
    int s = 0;
#pragma unroll 8
    for (int r = r0; r < r0 + 64; r++) s += Ab[(long)r * kN + j];
    atomicAdd(&degD[b * kN + j], (float)s);
}

__global__ void k_degS(const int* __restrict__ colp, int* degS) {
    int e = blockIdx.x * 256 + threadIdx.x;
    if (e < kE) atomicAdd(&degS[colp[e]], 1);
}

__global__ void k_disD(const float* __restrict__ degD, float* __restrict__ disD) {
    int i = blockIdx.x * 256 + threadIdx.x;
    if (i < kNTOT) disD[i] = rsqrtf(degD[i]);
}
__global__ void k_disS(const int* __restrict__ degS, float* __restrict__ disS) {
    int i = blockIdx.x * 256 + threadIdx.x;
    if (i < kNTOT) disS[i] = rsqrtf((float)degS[i] + 1.f);
}

__global__ void k_scan(const int* __restrict__ degS, int* __restrict__ ns,
                       int* __restrict__ cur) {
    __shared__ int sm[1024];
    int tid = threadIdx.x;
    int base = tid * 16;
    int local[16];
    int sum = 0;
#pragma unroll
    for (int v = 0; v < 16; v++) { local[v] = degS[base + v]; sum += local[v]; }
    sm[tid] = sum;
    __syncthreads();
    for (int off = 1; off < 1024; off <<= 1) {
        int v = (tid >= off) ? sm[tid - off] : 0;
        __syncthreads();
        sm[tid] += v;
        __syncthreads();
    }
    int run = sm[tid] - sum;
#pragma unroll
    for (int v = 0; v < 16; v++) {
        ns[base + v] = run;
        cur[base + v] = run;
        run += local[v];
    }
    if (tid == 1023) ns[kNTOT] = run;
}

__global__ void k_fill(const int* __restrict__ rowp, const int* __restrict__ colp,
                       int* cur, int* __restrict__ esrc) {
    int e = blockIdx.x * 256 + threadIdx.x;
    if (e < kE) {
        int c = colp[e];
        int p = atomicAdd(&cur[c], 1);
        esrc[p] = rowp[e];
    }
}

// ---------------------------------------------------------------------------
// fp16 CSR gather: one warp per node; VH half2 per lane (F = VH*64).
// ---------------------------------------------------------------------------
template <int VH>
__global__ __launch_bounds__(256) void k_gather_h(
        const int* __restrict__ ns, const int* __restrict__ esrc,
        const __half2* __restrict__ xwh, const float* __restrict__ disS,
        const float* __restrict__ bias, float* __restrict__ out,
        int outStride, int outOffset) {
    constexpr int F2 = VH * 32;
    int node = (blockIdx.x * 256 + threadIdx.x) >> 5;
    int lane = threadIdx.x & 31;
    if (node >= kNTOT) return;
    int off2 = lane * VH;
    float dc = disS[node];
    float2 acc[VH];

    auto loadrow = [&](long r, uint32_t* rw) {
        const char* p = reinterpret_cast<const char*>(xwh + r * F2 + off2);
        if (VH == 4) {
            uint4 u = *reinterpret_cast<const uint4*>(p);
            rw[0] = u.x; rw[1] = u.y; rw[2] = u.z; rw[3] = u.w;
        } else {
            uint2 u = *reinterpret_cast<const uint2*>(p);
            rw[0] = u.x; rw[1] = u.y;
        }
    };

    {
        uint32_t rw[VH];
        loadrow(node, rw);
        float d2 = dc * dc;
#pragma unroll
        for (int v = 0; v < VH; v++) {
            float2 xv = __half22float2(*reinterpret_cast<__half2*>(&rw[v]));
            float2 bb = *reinterpret_cast<const float2*>(bias + (off2 + v) * 2);
            acc[v] = make_float2(xv.x * d2 + bb.x, xv.y * d2 + bb.y);
        }
    }
    int s = ns[node], e = ns[node + 1];
    int i = s;
    for (; i + 8 <= e; i += 8) {
        int r[8];
        float sc[8];
        uint32_t rw[8][VH];
#pragma unroll
        for (int q = 0; q < 8; q++) r[q] = esrc[i + q];
#pragma unroll
        for (int q = 0; q < 8; q++) sc[q] = disS[r[q]] * dc;
#pragma unroll
        for (int q = 0; q < 8; q++) loadrow(r[q], rw[q]);
#pragma unroll
        for (int q = 0; q < 8; q++)
#pragma unroll
            for (int v = 0; v < VH; v++) {
                float2 xv = __half22float2(*reinterpret_cast<__half2*>(&rw[q][v]));
                acc[v].x += xv.x * sc[q];
                acc[v].y += xv.y * sc[q];
            }
    }
    for (; i < e; i++) {
        int r = esrc[i];
        float sr = disS[r] * dc;
        uint32_t rw[VH];
        loadrow(r, rw);
#pragma unroll
        for (int v = 0; v < VH; v++) {
            float2 xv = __half22float2(*reinterpret_cast<__half2*>(&rw[v]));
            acc[v].x += xv.x * sr;
            acc[v].y += xv.y * sr;
        }
    }
    float* op = out + (long)node * outStride + outOffset + off2 * 2;
#pragma unroll
    for (int v = 0; v < VH; v++)
        *reinterpret_cast<float2*>(op + v * 2) = acc[v];
}

// ---------------------------------------------------------------------------
// tf32 NT GEMM with ldmatrix fragment loads + optional fp16 mirror output.
// ---------------------------------------------------------------------------
template <bool RELU_A>
__global__ __launch_bounds__(256) void k_gemm_tf32(
        const float* __restrict__ A, long aStride,
        const float* __restrict__ B,
        float* __restrict__ C, long cStride,
        int Nf, int K, __half* __restrict__ Ch, int hRowStart) {
    __shared__ uint32_t As[2][128][20];
    __shared__ uint32_t Bs[2][128][20];
    const float* Ab = A + (long)blockIdx.z * aStride;
    float* Cb = C + (long)blockIdx.z * cStride;
    int m0 = blockIdx.y * 128, n0 = blockIdx.x * 128;
    int t = threadIdx.x;
    int wid = t >> 5, lane = t & 31;
    int mw = (wid >> 1) * 32, nw = (wid & 1) * 64;
    int g = lane >> 2, tg = lane & 3;
    int lrow16 = lane & 15;
    int lhalf4 = (lane >> 4) * 4;
    int lr = t >> 2, lc = (t & 3) << 2;

    uint32_t sA[2] = { smem_u32(&As[0][0][0]), smem_u32(&As[1][0][0]) };
    uint32_t sB[2] = { smem_u32(&Bs[0][0][0]), smem_u32(&Bs[1][0][0]) };

    float acc[2][8][4];
#pragma unroll
    for (int i = 0; i < 2; i++)
#pragma unroll
        for (int j = 0; j < 8; j++)
#pragma unroll
            for (int c = 0; c < 4; c++) acc[i][j][c] = 0.f;

    const float* aP0 = Ab + (long)(m0 + lr) * K + lc;
    const float* aP1 = Ab + (long)(m0 + lr + 64) * K + lc;
    const float* bP0 = B + (long)(n0 + lr) * K + lc;
    const float* bP1 = B + (long)(n0 + lr + 64) * K + lc;

    auto cvt4 = [](float4 v, bool relu) -> uint4 {
        if (relu) {
            v.x = fmaxf(v.x, 0.f); v.y = fmaxf(v.y, 0.f);
            v.z = fmaxf(v.z, 0.f); v.w = fmaxf(v.w, 0.f);
        }
        uint4 r;
        r.x = f2tf(v.x); r.y = f2tf(v.y); r.z = f2tf(v.z); r.w = f2tf(v.w);
        return r;
    };

    {
        uint4 a0 = cvt4(*reinterpret_cast<const float4*>(aP0), RELU_A);
        uint4 a1 = cvt4(*reinterpret_cast<const float4*>(aP1), RELU_A);
        uint4 b0 = cvt4(*reinterpret_cast<const float4*>(bP0), false);
        uint4 b1 = cvt4(*reinterpret_cast<const float4*>(bP1), false);
        *reinterpret_cast<uint4*>(&As[0][lr][lc]) = a0;
        *reinterpret_cast<uint4*>(&As[0][lr + 64][lc]) = a1;
        *reinterpret_cast<uint4*>(&Bs[0][lr][lc]) = b0;
        *reinterpret_cast<uint4*>(&Bs[0][lr + 64][lc]) = b1;
    }
    __syncthreads();

    int buf = 0;
    for (int k0 = 0; k0 < K; k0 += 16) {
        bool more = (k0 + 16) < K;
        float4 na0, na1, nb0, nb1;
        if (more) {
            na0 = *reinterpret_cast<const float4*>(aP0 + k0 + 16);
            na1 = *reinterpret_cast<const float4*>(aP1 + k0 + 16);
            nb0 = *reinterpret_cast<const float4*>(bP0 + k0 + 16);
            nb1 = *reinterpret_cast<const float4*>(bP1 + k0 + 16);
        }
#pragma unroll
        for (int s = 0; s < 2; s++) {
            int kcol = s * 8 + lhalf4;
            uint32_t af0[4], af1[4];
            ldsm4(af0, sA[buf] + ((mw + lrow16) * 20 + kcol) * 4);
            ldsm4(af1, sA[buf] + ((mw + 16 + lrow16) * 20 + kcol) * 4);
#pragma unroll
            for (int p = 0; p < 4; p++) {
                uint32_t bf[4];
                ldsm4(bf, sB[buf] + ((nw + p * 16 + lrow16) * 20 + kcol) * 4);
                mma_tf32(acc[0][2 * p],     af0, bf[0], bf[2]);
                mma_tf32(acc[0][2 * p + 1], af0, bf[1], bf[3]);
                mma_tf32(acc[1][2 * p],     af1, bf[0], bf[2]);
                mma_tf32(acc[1][2 * p + 1], af1, bf[1], bf[3]);
            }
        }
        if (more) {
            int nb = buf ^ 1;
            *reinterpret_cast<uint4*>(&As[nb][lr][lc]) = cvt4(na0, RELU_A);
            *reinterpret_cast<uint4*>(&As[nb][lr + 64][lc]) = cvt4(na1, RELU_A);
            *reinterpret_cast<uint4*>(&Bs[nb][lr][lc]) = cvt4(nb0, false);
            *reinterpret_cast<uint4*>(&Bs[nb][lr + 64][lc]) = cvt4(nb1, false);
            __syncthreads();
            buf = nb;
        }
    }

    bool doH = (Ch != nullptr) && (m0 >= hRowStart);
#pragma unroll
    for (int mt = 0; mt < 2; mt++) {
        int row = m0 + mw + mt * 16 + g;
#pragma unroll
        for (int j = 0; j < 8; j++) {
            int col = n0 + nw + j * 8 + 2 * tg;
            float2 v0 = make_float2(acc[mt][j][0], acc[mt][j][1]);
            float2 v1 = make_float2(acc[mt][j][2], acc[mt][j][3]);
            *reinterpret_cast<float2*>(Cb + (long)row * Nf + col) = v0;
            *reinterpret_cast<float2*>(Cb + (long)(row + 8) * Nf + col) = v1;
            if (doH) {
                long hr = row - hRowStart;
                *reinterpret_cast<__half2*>(Ch + hr * Nf + col) =
                    __floats2half2_rn(v0.x, v0.y);
                *reinterpret_cast<__half2*>(Ch + (hr + 8) * Nf + col) =
                    __floats2half2_rn(v1.x, v1.y);
            }
        }
    }
}

// ---------------------------------------------------------------------------
// tf32 dense GCN propagation — A tiles loaded as uint8, expanded to tf32 one-bits
// ---------------------------------------------------------------------------
template <bool RELU>
__global__ __launch_bounds__(256) void k_prop_tf32(
        const unsigned char* __restrict__ Adj8, const float* __restrict__ XW,
        const float* __restrict__ dis, const float* __restrict__ bias,
        float* __restrict__ out, int F, int outStride, int outOffset) {
    __shared__ uint32_t As[2][16][136];
    __shared__ uint32_t Bs[2][16][136];
    int b = blockIdx.z;
    const unsigned char* Ab = Adj8 + (long)b * kN * kN;
    const float* Xb = XW + (long)b * kN * F;
    const float* db = dis + b * kN;
    float* Ob = out + (long)b * kN * outStride + outOffset;
    int i0 = blockIdx.y * 128, f0 = blockIdx.x * 128;
    int t = threadIdx.x;
    int wid = t >> 5, lane = t & 31;
    int mw = (wid >> 1) * 32, nw = (wid & 1) * 64;
    int g = lane >> 2, tg = lane & 3;
    int jj = t >> 4;
    int ii = (t & 15) << 3;

    float acc[2][8][4];
#pragma unroll
    for (int i = 0; i < 2; i++)
#pragma unroll
        for (int j = 0; j < 8; j++)
#pragma unroll
            for (int c = 0; c < 4; c++) acc[i][j][c] = 0.f;

    constexpr uint32_t ONE = 0x3F800000u;
    auto stTile = [&](int bufI, uint2 rawA, float4 x0, float4 x1, float dj) {
        uint4 ua0, ua1, ux0, ux1;
        ua0.x = (rawA.x & 0xffu)         ? ONE : 0u;
        ua0.y = ((rawA.x >> 8) & 0xffu)  ? ONE : 0u;
        ua0.z = ((rawA.x >> 16) & 0xffu) ? ONE : 0u;
        ua0.w = ((rawA.x >> 24) & 0xffu) ? ONE : 0u;
        ua1.x = (rawA.y & 0xffu)         ? ONE : 0u;
        ua1.y = ((rawA.y >> 8) & 0xffu)  ? ONE : 0u;
        ua1.z = ((rawA.y >> 16) & 0xffu) ? ONE : 0u;
        ua1.w = ((rawA.y >> 24) & 0xffu) ? ONE : 0u;
        ux0.x = f2tf(x0.x * dj); ux0.y = f2tf(x0.y * dj);
        ux0.z = f2tf(x0.z * dj); ux0.w = f2tf(x0.w * dj);
        ux1.x = f2tf(x1.x * dj); ux1.y = f2tf(x1.y * dj);
        ux1.z = f2tf(x1.z * dj); ux1.w = f2tf(x1.w * dj);
        *reinterpret_cast<uint4*>(&As[bufI][jj][ii]) = ua0;
        *reinterpret_cast<uint4*>(&As[bufI][jj][ii + 4]) = ua1;
        *reinterpret_cast<uint4*>(&Bs[bufI][jj][ii]) = ux0;
        *reinterpret_cast<uint4*>(&Bs[bufI][jj][ii + 4]) = ux1;
    };

    {
        uint2 rawA = *reinterpret_cast<const uint2*>(Ab + (long)jj * kN + i0 + ii);
        const float* xp = Xb + (long)jj * F + f0 + ii;
        stTile(0, rawA,
               *reinterpret_cast<const float4*>(xp),
               *reinterpret_cast<const float4*>(xp + 4),
               db[jj]);
    }
    __syncthreads();

    int buf = 0;
    for (int j0 = 0; j0 < kN; j0 += 16) {
        bool more = (j0 + 16) < kN;
        uint2 nraw;
        float4 nx0, nx1;
        float djn = 0.f;
        if (more) {
            nraw = *reinterpret_cast<const uint2*>(
                Ab + (long)(j0 + 16 + jj) * kN + i0 + ii);
            const float* xp = Xb + (long)(j0 + 16 + jj) * F + f0 + ii;
            nx0 = *reinterpret_cast<const float4*>(xp);
            nx1 = *reinterpret_cast<const float4*>(xp + 4);
            djn = db[j0 + 16 + jj];
        }
#pragma unroll
        for (int s = 0; s < 2; s++) {
            int kk = s * 8 + tg;
            uint32_t af[2][4];
#pragma unroll
            for (int mt = 0; mt < 2; mt++) {
                int m = mw + mt * 16 + g;
                af[mt][0] = As[buf][kk][m];
                af[mt][1] = As[buf][kk][m + 8];
                af[mt][2] = As[buf][kk + 4][m];
                af[mt][3] = As[buf][kk + 4][m + 8];
            }
#pragma unroll
            for (int j = 0; j < 8; j++) {
                int n = nw + j * 8 + g;
                uint32_t b0 = Bs[buf][kk][n];
                uint32_t b1 = Bs[buf][kk + 4][n];
                mma_tf32(acc[0][j], af[0], b0, b1);
                mma_tf32(acc[1][j], af[1], b0, b1);
            }
        }
        if (more) {
            int nb = buf ^ 1;
            stTile(nb, nraw, nx0, nx1, djn);
            __syncthreads();
            buf = nb;
        }
    }

#pragma unroll
    for (int mt = 0; mt < 2; mt++) {
        int rowA = i0 + mw + mt * 16 + g;
        float diA = db[rowA], diB = db[rowA + 8];
#pragma unroll
        for (int j = 0; j < 8; j++) {
            int col = f0 + nw + j * 8 + 2 * tg;
            float2 bb = *reinterpret_cast<const float2*>(bias + col);
            float2 xA = *reinterpret_cast<const float2*>(Xb + (long)rowA * F + col);
            float2 xB = *reinterpret_cast<const float2*>(Xb + (long)(rowA + 8) * F + col);
            float v0 = diA * (acc[mt][j][0] + diA * xA.x) + bb.x;
            float v1 = diA * (acc[mt][j][1] + diA * xA.y) + bb.y;
            float v2 = diB * (acc[mt][j][2] + diB * xB.x) + bb.x;
            float v3 = diB * (acc[mt][j][3] + diB * xB.y) + bb.y;
            if (RELU) {
                v0 = fmaxf(v0, 0.f); v1 = fmaxf(v1, 0.f);
                v2 = fmaxf(v2, 0.f); v3 = fmaxf(v3, 0.f);
            }
            *reinterpret_cast<float2*>(Ob + (long)rowA * outStride + col) =
                make_float2(v0, v1);
            *reinterpret_cast<float2*>(Ob + (long)(rowA + 8) * outStride + col) =
                make_float2(v2, v3);
        }
    }
}

// ---------------------------------------------------------------------------
// fcn1 half: h1 += emb[:, cols ≡ colOff..colOff+127 mod 256] @ W[same cols]ᵀ
// K-half = 65536; kmap(k) = (k>>7)*256 + colOff + (k&127). Double-buffered.
// ---------------------------------------------------------------------------
__global__ void k_fcn1_half(const float* __restrict__ emb, const float* __restrict__ W,
                            float* __restrict__ h1, int colOff) {
    constexpr int KH = kKTOT / 2;   // 65536
    constexpr int KC = KH / 64;     // 1024 per chunk
    __shared__ float As[16][32];
    __shared__ float Bs[16][64];
    int n0 = blockIdx.x * 64;
    int kbase = blockIdx.y * KC;
    int t = threadIdx.x;
    int m = t & 31;
    int nb = (t >> 5) << 3;
    int row = t >> 2, c4 = (t & 3) << 2;
    float acc[8];
#pragma unroll
    for (int j = 0; j < 8; j++) acc[j] = 0.f;

    auto kmap = [&](int k) -> long {
        return ((long)(k >> 7) << 8) + colOff + (k & 127);
    };

    float4 aPre, bPre;
    if (t < 128)
        aPre = *reinterpret_cast<const float4*>(emb + (long)row * kKTOT + kmap(kbase + c4));
    bPre = *reinterpret_cast<const float4*>(W + (long)(n0 + row) * kKTOT + kmap(kbase + c4));

    for (int k0 = kbase; k0 < kbase + KC; k0 += 16) {
        if (t < 128) {
            As[c4 + 0][row] = aPre.x; As[c4 + 1][row] = aPre.y;
            As[c4 + 2][row] = aPre.z; As[c4 + 3][row] = aPre.w;
        }
        Bs[c4 + 0][row] = bPre.x; Bs[c4 + 1][row] = bPre.y;
        Bs[c4 + 2][row] = bPre.z; Bs[c4 + 3][row] = bPre.w;
        __syncthreads();
        bool more = (k0 + 16) < kbase + KC;
        if (more) {
            if (t < 128)
                aPre = *reinterpret_cast<const float4*>(
                    emb + (long)row * kKTOT + kmap(k0 + 16 + c4));
            bPre = *reinterpret_cast<const float4*>(
                W + (long)(n0 + row) * kKTOT + kmap(k0 + 16 + c4));
        }
#pragma unroll
        for (int k = 0; k < 16; k++) {
            float a = As[k][m];
#pragma unroll
            for (int j = 0; j < 8; j++) acc[j] += a * Bs[k][nb + j];
        }
        __syncthreads();
    }
#pragma unroll
    for (int j = 0; j < 8; j++)
        atomicAdd(&h1[m * 256 + n0 + nb + j], acc[j]);
}

__global__ void k_fcn23(const float* __restrict__ h1g,
                        const float* __restrict__ b1, const float* __restrict__ w2,
                        const float* __restrict__ b2, const float* __restrict__ w3,
                        const float* __restrict__ b3, float* __restrict__ out) {
    __shared__ float h1s[32][256];
    __shared__ float h2s[32][32];
    int t = threadIdx.x;
    for (int idx = t; idx < 32 * 256; idx += 1024) {
        float v = h1g[idx] + b1[idx & 255];
        h1s[idx >> 8][idx & 255] = (v >= 0.f) ? v : 0.2f * v;
    }
    __syncthreads();
    {
        int b = t >> 5, o = t & 31;
        float s = 0.f;
#pragma unroll 8
        for (int k = 0; k < 256; k++) s += h1s[b][k] * w2[o * 256 + k];
        s += b2[o];
        h2s[b][o] = (s >= 0.f) ? s : 0.2f * s;
    }
    __syncthreads();
    if (t < 64) {
        int b = t >> 1, o = t & 1;
        float s = 0.f;
#pragma unroll
        for (int k = 0; k < 32; k++) s += h2s[b][k] * w3[o * 32 + k];
        out[b * 2 + o] = s + b3[o];
    }
}

// ---------------------------------------------------------------------------
// Launch — two parallel pipelines after gemm1
// ---------------------------------------------------------------------------
extern "C" void kernel_launch(void* const* d_in, const int* in_sizes, int n_in,
                              void* d_out, int out_size) {
    const float* x    = (const float*)d_in[0];
    const float* t    = (const float*)d_in[1];
    const float* gu   = (const float*)d_in[2];
    const int*   ei   = (const int*)d_in[3];
    const float* w1   = (const float*)d_in[4];
    const float* b1   = (const float*)d_in[5];
    const float* w2   = (const float*)d_in[6];
    const float* b2   = (const float*)d_in[7];
    const float* fcw  = (const float*)d_in[8];
    const float* fcb  = (const float*)d_in[9];
    const float* f1w  = (const float*)d_in[10];
    const float* f1b  = (const float*)d_in[11];
    const float* f2w  = (const float*)d_in[12];
    const float* f2b  = (const float*)d_in[13];
    const float* f3w  = (const float*)d_in[14];
    const float* f3b  = (const float*)d_in[15];
    float* out = (float*)d_out;

    const int* rowp = ei;
    const int* colp = ei + kE;

    float* base = nullptr;
    cudaGetSymbolAddress((void**)&base, g_scratch);
    float* p_E     = base + OFF_EG;
    float* p_F     = base + OFF_FG;
    unsigned char* p_A8 = (unsigned char*)(base + OFF_A8);
    float* p_disD  = base + OFF_DISD;
    float* p_degD  = base + OFF_DEGD;
    float* p_xw1   = base + OFF_XW1;
    float* p_h     = base + OFF_H;
    float* p_sc1   = base + OFF_SC1;
    float* p_xw2   = base + OFF_XW2;
    float* p_xws2  = base + OFF_XWS2;
    float* p_emb   = base + OFF_EMB;
    float* p_disS  = base + OFF_DISS;
    int*   p_degS  = (int*)(base + OFF_DEGS);
    float* p_h1    = base + OFF_H1;
    int*   p_ns    = (int*)(base + OFF_NS);
    int*   p_cur   = (int*)(base + OFF_CUR);
    int*   p_esrc  = (int*)(base + OFF_ESRC);
    __half* p_xw1h  = (__half*)(base + OFF_XW1H);
    __half* p_xws2h = (__half*)(base + OFF_XWS2H);

    static cudaStream_t sG = nullptr, sC = nullptr;
    static cudaEvent_t evStart, evG1, evCSR, evF1s;
    if (!sG) {
        cudaStreamCreateWithFlags(&sG, cudaStreamNonBlocking);
        cudaStreamCreateWithFlags(&sC, cudaStreamNonBlocking);
        cudaEventCreateWithFlags(&evStart, cudaEventDisableTiming);
        cudaEventCreateWithFlags(&evG1, cudaEventDisableTiming);
        cudaEventCreateWithFlags(&evCSR, cudaEventDisableTiming);
        cudaEventCreateWithFlags(&evF1s, cudaEventDisableTiming);
    }

    cudaEventRecord(evStart, 0);
    cudaStreamWaitEvent(sG, evStart, 0);
    cudaStreamWaitEvent(sC, evStart, 0);

    // main: dense prep
    k_zeroD<<<64, 256>>>(p_degD);                                     // 1
    k_lslr<<<kNTOT / 8, 256>>>(t, fcw, fcb, p_E, p_F);                // 2
    k_buildA<<<kBZ * kN * kN / 1024, 256>>>(gu, p_E, p_F, p_A8);      // 3

    // sG: gemm1 (writes xw1 fp32 + xw1h fp16)                        // 4 (captured)
    k_gemm_tf32<false><<<dim3(kF1 / 128, kNTOT / 128, 1), 256, 0, sG>>>(
        x, 0, w1, p_xw1, 0, kF1, kN, p_xw1h, 0);
    cudaEventRecord(evG1, sG);

    // main: dense degrees
    k_colsum_part<<<dim3(kBZ, 8), kN>>>(p_A8, p_degD);
    k_disD<<<kNTOT / 256, 256>>>(p_degD, p_disD);

    // sC: CSR chain + h1 zero
    k_zeroS<<<64, 256, 0, sC>>>(p_degS, p_h1);
    k_degS<<<kE / 256, 256, 0, sC>>>(colp, p_degS);
    k_disS<<<kNTOT / 256, 256, 0, sC>>>(p_degS, p_disS);
    k_scan<<<1, 1024, 0, sC>>>(p_degS, p_ns, p_cur);
    k_fill<<<kE / 256, 256, 0, sC>>>(rowp, colp, p_cur, p_esrc);
    cudaEventRecord(evCSR, sC);

    // ===== dense pipeline (main): prop1 -> gemm2d -> prop2 -> fcn1_dense =====
    cudaStreamWaitEvent(0, evG1, 0);
    k_prop_tf32<true><<<dim3(kF1 / 128, kN / 128, kBZ), 256>>>(
        p_A8, p_xw1, p_disD, b1, p_h, kF1, kF1, 0);
    k_gemm_tf32<true><<<dim3(kF2 / 128, kNTOT / 128, 1), 256>>>(
        p_h, 0, w2, p_xw2, 0, kF2, kF1, nullptr, 0);
    k_prop_tf32<false><<<dim3(kF2 / 128, kN / 128, kBZ), 256>>>(
        p_A8, p_xw2, p_disD, b2, p_emb, kF2, 256, 0);
    cudaStreamWaitEvent(0, evCSR, 0);   // h1 zeroed
    k_fcn1_half<<<dim3(4, 64), 256>>>(p_emb, f1w, p_h1, 0);

    // ===== sparse pipeline (sG): gather1 -> gemm2s -> gather2 -> fcn1_sparse =====
    cudaStreamWaitEvent(sG, evCSR, 0);
    k_gather_h<4><<<kNTOT / 8, 256, 0, sG>>>(p_ns, p_esrc,
        (const __half2*)p_xw1h, p_disS, b1, p_sc1, kF1, 0);
    k_gemm_tf32<true><<<dim3(kF2 / 128, kNTOT / 128, 1), 256, 0, sG>>>(
        p_sc1, 0, w2, p_xws2, 0, kF2, kF1, p_xws2h, 0);
    k_gather_h<2><<<kNTOT / 8, 256, 0, sG>>>(p_ns, p_esrc,
        (const __half2*)p_xws2h, p_disS, b2, p_emb, 256, 128);
    k_fcn1_half<<<dim3(4, 64), 256, 0, sG>>>(p_emb, f1w, p_h1, 128);
    cudaEventRecord(evF1s, sG);

    // join + head
    cudaStreamWaitEvent(0, evF1s, 0);
    k_fcn23<<<1, 1024>>>(p_h1, f1b, f2w, f2b, f3w, f3b, out);
}

// round 12
// speedup vs baseline: 1.2470x; 1.0287x over previous
#include <cuda_runtime.h>
#include <cuda_fp16.h>
#include <cstdint>

// ---------------------------------------------------------------------------
// Problem constants
// ---------------------------------------------------------------------------
constexpr int kN    = 512;
constexpr int kBZ   = 32;
constexpr int kTC   = 256;
constexpr int kF1   = 256;
constexpr int kF2   = 128;
constexpr int kE    = 524288;
constexpr int kNTOT = kBZ * kN;          // 16384
constexpr int kKTOT = kF2 * 2 * kN;      // 131072

// ---------------------------------------------------------------------------
// Scratch (offsets in floats)
// ---------------------------------------------------------------------------
constexpr long OFF_EG   = 0;
constexpr long OFF_FG   = OFF_EG   + (long)kNTOT;
constexpr long OFF_A8   = OFF_FG   + (long)kNTOT;                // u8 view
constexpr long OFF_DISD = OFF_A8   + (long)kBZ * kN * kN / 4;
constexpr long OFF_PART = OFF_DISD + (long)kNTOT;                // 32*8*512
constexpr long OFF_H    = OFF_PART + (long)kBZ * 8 * kN;
constexpr long OFF_SC1  = OFF_H    + (long)kNTOT * kF1;
constexpr long OFF_XW2  = OFF_SC1  + (long)kNTOT * kF1;
constexpr long OFF_EMB  = OFF_XW2  + (long)kNTOT * kF2;
constexpr long OFF_DISS = OFF_EMB  + (long)kNTOT * 256;
constexpr long OFF_DEGS = OFF_DISS + (long)kNTOT;                // int
constexpr long OFF_H1   = OFF_DEGS + (long)kNTOT;
constexpr long OFF_NS   = OFF_H1   + (long)kBZ * 256;            // int, kNTOT+1
constexpr long OFF_CUR  = OFF_NS   + (long)kNTOT + 4;            // int
constexpr long OFF_ESRC = OFF_CUR  + (long)kNTOT;                // int, kE
constexpr long OFF_XW1H = OFF_ESRC + (long)kE;                   // half, NTOT*F1
constexpr long OFF_XWS2H= OFF_XW1H + (long)kNTOT * kF1 / 2;      // half, NTOT*F2
constexpr long SCRATCH_FLOATS = OFF_XWS2H + (long)kNTOT * kF2 / 2;

__device__ __align__(16) float g_scratch[SCRATCH_FLOATS];

// ---------------------------------------------------------------------------
// tf32 / ldmatrix helpers
// ---------------------------------------------------------------------------
__device__ __forceinline__ uint32_t f2tf(float x) {
    uint32_t r;
    asm("cvt.rna.tf32.f32 %0, %1;" : "=r"(r) : "f"(x));
    return r;
}
__device__ __forceinline__ void mma_tf32(float* d, const uint32_t* a,
                                         uint32_t b0, uint32_t b1) {
    asm volatile(
        "mma.sync.aligned.m16n8k8.row.col.f32.tf32.tf32.f32 "
        "{%0,%1,%2,%3},{%4,%5,%6,%7},{%8,%9},{%0,%1,%2,%3};"
        : "+f"(d[0]), "+f"(d[1]), "+f"(d[2]), "+f"(d[3])
        : "r"(a[0]), "r"(a[1]), "r"(a[2]), "r"(a[3]), "r"(b0), "r"(b1));
}
__device__ __forceinline__ void ldsm4(uint32_t* r, uint32_t addr) {
    asm volatile("ldmatrix.sync.aligned.m8n8.x4.shared.b16 {%0,%1,%2,%3}, [%4];"
                 : "=r"(r[0]), "=r"(r[1]), "=r"(r[2]), "=r"(r[3]) : "r"(addr));
}
__device__ __forceinline__ uint32_t smem_u32(const void* p) {
    return (uint32_t)__cvta_generic_to_shared(p);
}

// ---------------------------------------------------------------------------
// Small kernels
// ---------------------------------------------------------------------------
__global__ void k_zeroS(int* degS, float* h1) {
    int i = blockIdx.x * 256 + threadIdx.x;
    if (i < kNTOT) degS[i] = 0;
    if (i < kBZ * 256) h1[i] = 0.f;
}

__global__ void k_lslr(const float* __restrict__ t, const float* __restrict__ fcw,
                       const float* __restrict__ fcb,
                       float* __restrict__ Eg, float* __restrict__ Fg) {
    int warp = (blockIdx.x * blockDim.x + threadIdx.x) >> 5;
    int lane = threadIdx.x & 31;
    if (warp >= kNTOT) return;
    const float* tn = t + (long)warp * kTC;
    const float* w0 = fcw;
    const float* w1 = fcw + 512;
    float s0 = 0.f, s1 = 0.f, r0 = 0.f, r1 = 0.f;
#pragma unroll
    for (int q = 0; q < 8; q++) {
        int d = lane + 32 * q;
        float u = fmaxf(tn[d], 0.f);
        s0 += u * w0[d];       s1 += u * w1[d];
        r0 += u * w0[256 + d]; r1 += u * w1[256 + d];
    }
#pragma unroll
    for (int off = 16; off; off >>= 1) {
        s0 += __shfl_down_sync(0xffffffffu, s0, off);
        s1 += __shfl_down_sync(0xffffffffu, s1, off);
        r0 += __shfl_down_sync(0xffffffffu, r0, off);
        r1 += __shfl_down_sync(0xffffffffu, r1, off);
    }
    if (lane == 0) {
        Eg[warp] = expf(r1 - r0 + fcb[1] - fcb[0]);
        Fg[warp] = expf(s1 - s0);
    }
}

__global__ void k_buildA(const float* __restrict__ gu,
                         const float* __restrict__ Eg, const float* __restrict__ Fg,
                         unsigned char* __restrict__ A8) {
    int idx = blockIdx.x * 256 + threadIdx.x;
    int j0 = (idx & 127) << 2;
    int i  = (idx >> 7) & 511;
    int b  = idx >> 16;
    float Ei = Eg[b * kN + i];
    float4 Fv = *reinterpret_cast<const float4*>(Fg + b * kN + j0);
    const float4* g4 = reinterpret_cast<const float4*>(
        gu + ((long)(b * kN + i) * kN + j0) * 2);
    float4 u01 = g4[0];
    float4 u23 = g4[1];
    auto bit = [&](float ux, float uy, float Fj) -> unsigned char {
        ux = fminf(fmaxf(ux, 1e-9f), 1.0f - 1e-9f);
        uy = fminf(fmaxf(uy, 1e-9f), 1.0f - 1e-9f);
        float l0 = -__logf(ux);
        float l1 = -__logf(uy);
        return (l1 >= l0 * Ei * Fj) ? 1 : 0;
    };
    uchar4 r;
    r.x = bit(u01.x, u01.y, Fv.x);
    r.y = bit(u01.z, u01.w, Fv.y);
    r.z = bit(u23.x, u23.y, Fv.z);
    r.w = bit(u23.z, u23.w, Fv.w);
    *reinterpret_cast<uchar4*>(A8 + (long)(b * kN + i) * kN + j0) = r;
}

// colsum partials: part[b][chunk][j] = sum of 64 rows (no atomics, no init)
__global__ void k_colsum_part(const unsigned char* __restrict__ A8,
                              float* __restrict__ part) {
    int b = blockIdx.x;
    int j = threadIdx.x;
    int r0 = blockIdx.y * 64;
    const unsigned char* Ab = A8 + (long)b * kN * kN;
    int s = 0;
#pragma unroll 8
    for (int r = r0; r < r0 + 64; r++) s += Ab[(long)r * kN + j];
    part[((long)b * 8 + blockIdx.y) * kN + j] = (float)s;
}

// disD[i] = rsqrt(1 + sum_c part[b][c][j])
__global__ void k_disD(const float* __restrict__ part, float* __restrict__ disD) {
    int i = blockIdx.x * 256 + threadIdx.x;
    if (i >= kNTOT) return;
    int b = i >> 9, j = i & 511;
    float s = 1.f;
#pragma unroll
    for (int c = 0; c < 8; c++) s += part[((long)b * 8 + c) * kN + j];
    disD[i] = rsqrtf(s);
}

__global__ void k_degS(const int* __restrict__ colp, int* degS) {
    int e = blockIdx.x * 256 + threadIdx.x;
    if (e < kE) atomicAdd(&degS[colp[e]], 1);
}

__global__ void k_disS(const int* __restrict__ degS, float* __restrict__ disS) {
    int i = blockIdx.x * 256 + threadIdx.x;
    if (i < kNTOT) disS[i] = rsqrtf((float)degS[i] + 1.f);
}

__global__ void k_scan(const int* __restrict__ degS, int* __restrict__ ns,
                       int* __restrict__ cur) {
    __shared__ int sm[1024];
    int tid = threadIdx.x;
    int base = tid * 16;
    int local[16];
    int sum = 0;
#pragma unroll
    for (int v = 0; v < 16; v++) { local[v] = degS[base + v]; sum += local[v]; }
    sm[tid] = sum;
    __syncthreads();
    for (int off = 1; off < 1024; off <<= 1) {
        int v = (tid >= off) ? sm[tid - off] : 0;
        __syncthreads();
        sm[tid] += v;
        __syncthreads();
    }
    int run = sm[tid] - sum;
#pragma unroll
    for (int v = 0; v < 16; v++) {
        ns[base + v] = run;
        cur[base + v] = run;
        run += local[v];
    }
    if (tid == 1023) ns[kNTOT] = run;
}

__global__ void k_fill(const int* __restrict__ rowp, const int* __restrict__ colp,
                       int* cur, int* __restrict__ esrc) {
    int e = blockIdx.x * 256 + threadIdx.x;
    if (e < kE) {
        int c = colp[e];
        int p = atomicAdd(&cur[c], 1);
        esrc[p] = rowp[e];
    }
}

// ---------------------------------------------------------------------------
// fp16 CSR gather: WPN warps per node, VH half2 per lane. F = WPN*VH*64 halves.
// ---------------------------------------------------------------------------
template <int WPN, int VH>
__global__ __launch_bounds__(256) void k_gather_h(
        const int* __restrict__ ns, const int* __restrict__ esrc,
        const __half2* __restrict__ xwh, const float* __restrict__ disS,
        const float* __restrict__ bias, float* __restrict__ out,
        int outStride, int outOffset) {
    constexpr int F2 = WPN * VH * 32;   // half2 per row
    int gw = (blockIdx.x * 256 + threadIdx.x) >> 5;
    int lane = threadIdx.x & 31;
    int node = gw / WPN;
    int part = gw % WPN;
    if (node >= kNTOT) return;
    int off2 = (part * 32 + lane) * VH;
    float dc = disS[node];
    float2 acc[VH];

    auto loadrow = [&](long r, uint32_t* rw) {
        const char* p = reinterpret_cast<const char*>(xwh + r * F2 + off2);
        if (VH == 4) {
            uint4 u = *reinterpret_cast<const uint4*>(p);
            rw[0] = u.x; rw[1] = u.y; rw[2] = u.z; rw[3] = u.w;
        } else {
            uint2 u = *reinterpret_cast<const uint2*>(p);
            rw[0] = u.x; rw[1] = u.y;
        }
    };

    {
        uint32_t rw[VH];
        loadrow(node, rw);
        float d2 = dc * dc;
#pragma unroll
        for (int v = 0; v < VH; v++) {
            float2 xv = __half22float2(*reinterpret_cast<__half2*>(&rw[v]));
            float2 bb = *reinterpret_cast<const float2*>(bias + (off2 + v) * 2);
            acc[v] = make_float2(xv.x * d2 + bb.x, xv.y * d2 + bb.y);
        }
    }
    int s = ns[node], e = ns[node + 1];
    int i = s;
    for (; i + 8 <= e; i += 8) {
        int r[8];
        float sc[8];
        uint32_t rw[8][VH];
#pragma unroll
        for (int q = 0; q < 8; q++) r[q] = esrc[i + q];
#pragma unroll
        for (int q = 0; q < 8; q++) sc[q] = disS[r[q]] * dc;
#pragma unroll
        for (int q = 0; q < 8; q++) loadrow(r[q], rw[q]);
#pragma unroll
        for (int q = 0; q < 8; q++)
#pragma unroll
            for (int v = 0; v < VH; v++) {
                float2 xv = __half22float2(*reinterpret_cast<__half2*>(&rw[q][v]));
                acc[v].x += xv.x * sc[q];
                acc[v].y += xv.y * sc[q];
            }
    }
    for (; i < e; i++) {
        int r = esrc[i];
        float sr = disS[r] * dc;
        uint32_t rw[VH];
        loadrow(r, rw);
#pragma unroll
        for (int v = 0; v < VH; v++) {
            float2 xv = __half22float2(*reinterpret_cast<__half2*>(&rw[v]));
            acc[v].x += xv.x * sr;
            acc[v].y += xv.y * sr;
        }
    }
    float* op = out + (long)node * outStride + outOffset + off2 * 2;
#pragma unroll
    for (int v = 0; v < VH; v++)
        *reinterpret_cast<float2*>(op + v * 2) = acc[v];
}

// ---------------------------------------------------------------------------
// tf32 NT GEMM, ldmatrix fragment loads; fp32 out optional, fp16 out optional.
// ---------------------------------------------------------------------------
template <bool RELU_A>
__global__ __launch_bounds__(256) void k_gemm_tf32(
        const float* __restrict__ A,
        const float* __restrict__ B,
        float* __restrict__ C,
        int Nf, int K, __half* __restrict__ Ch) {
    __shared__ uint32_t As[2][128][20];
    __shared__ uint32_t Bs[2][128][20];
    int m0 = blockIdx.y * 128, n0 = blockIdx.x * 128;
    int t = threadIdx.x;
    int wid = t >> 5, lane = t & 31;
    int mw = (wid >> 1) * 32, nw = (wid & 1) * 64;
    int g = lane >> 2, tg = lane & 3;
    int lrow16 = lane & 15;
    int lhalf4 = (lane >> 4) * 4;
    int lr = t >> 2, lc = (t & 3) << 2;

    uint32_t sA[2] = { smem_u32(&As[0][0][0]), smem_u32(&As[1][0][0]) };
    uint32_t sB[2] = { smem_u32(&Bs[0][0][0]), smem_u32(&Bs[1][0][0]) };

    float acc[2][8][4];
#pragma unroll
    for (int i = 0; i < 2; i++)
#pragma unroll
        for (int j = 0; j < 8; j++)
#pragma unroll
            for (int c = 0; c < 4; c++) acc[i][j][c] = 0.f;

    const float* aP0 = A + (long)(m0 + lr) * K + lc;
    const float* aP1 = A + (long)(m0 + lr + 64) * K + lc;
    const float* bP0 = B + (long)(n0 + lr) * K + lc;
    const float* bP1 = B + (long)(n0 + lr + 64) * K + lc;

    auto cvt4 = [](float4 v, bool relu) -> uint4 {
        if (relu) {
            v.x = fmaxf(v.x, 0.f); v.y = fmaxf(v.y, 0.f);
            v.z = fmaxf(v.z, 0.f); v.w = fmaxf(v.w, 0.f);
        }
        uint4 r;
        r.x = f2tf(v.x); r.y = f2tf(v.y); r.z = f2tf(v.z); r.w = f2tf(v.w);
        return r;
    };

    {
        uint4 a0 = cvt4(*reinterpret_cast<const float4*>(aP0), RELU_A);
        uint4 a1 = cvt4(*reinterpret_cast<const float4*>(aP1), RELU_A);
        uint4 b0 = cvt4(*reinterpret_cast<const float4*>(bP0), false);
        uint4 b1 = cvt4(*reinterpret_cast<const float4*>(bP1), false);
        *reinterpret_cast<uint4*>(&As[0][lr][lc]) = a0;
        *reinterpret_cast<uint4*>(&As[0][lr + 64][lc]) = a1;
        *reinterpret_cast<uint4*>(&Bs[0][lr][lc]) = b0;
        *reinterpret_cast<uint4*>(&Bs[0][lr + 64][lc]) = b1;
    }
    __syncthreads();

    int buf = 0;
    for (int k0 = 0; k0 < K; k0 += 16) {
        bool more = (k0 + 16) < K;
        float4 na0, na1, nb0, nb1;
        if (more) {
            na0 = *reinterpret_cast<const float4*>(aP0 + k0 + 16);
            na1 = *reinterpret_cast<const float4*>(aP1 + k0 + 16);
            nb0 = *reinterpret_cast<const float4*>(bP0 + k0 + 16);
            nb1 = *reinterpret_cast<const float4*>(bP1 + k0 + 16);
        }
#pragma unroll
        for (int s = 0; s < 2; s++) {
            int kcol = s * 8 + lhalf4;
            uint32_t af0[4], af1[4];
            ldsm4(af0, sA[buf] + ((mw + lrow16) * 20 + kcol) * 4);
            ldsm4(af1, sA[buf] + ((mw + 16 + lrow16) * 20 + kcol) * 4);
#pragma unroll
            for (int p = 0; p < 4; p++) {
                uint32_t bf[4];
                ldsm4(bf, sB[buf] + ((nw + p * 16 + lrow16) * 20 + kcol) * 4);
                mma_tf32(acc[0][2 * p],     af0, bf[0], bf[2]);
                mma_tf32(acc[0][2 * p + 1], af0, bf[1], bf[3]);
                mma_tf32(acc[1][2 * p],     af1, bf[0], bf[2]);
                mma_tf32(acc[1][2 * p + 1], af1, bf[1], bf[3]);
            }
        }
        if (more) {
            int nb = buf ^ 1;
            *reinterpret_cast<uint4*>(&As[nb][lr][lc]) = cvt4(na0, RELU_A);
            *reinterpret_cast<uint4*>(&As[nb][lr + 64][lc]) = cvt4(na1, RELU_A);
            *reinterpret_cast<uint4*>(&Bs[nb][lr][lc]) = cvt4(nb0, false);
            *reinterpret_cast<uint4*>(&Bs[nb][lr + 64][lc]) = cvt4(nb1, false);
            __syncthreads();
            buf = nb;
        }
    }

#pragma unroll
    for (int mt = 0; mt < 2; mt++) {
        int row = m0 + mw + mt * 16 + g;
#pragma unroll
        for (int j = 0; j < 8; j++) {
            int col = n0 + nw + j * 8 + 2 * tg;
            float2 v0 = make_float2(acc[mt][j][0], acc[mt][j][1]);
            float2 v1 = make_float2(acc[mt][j][2], acc[mt][j][3]);
            if (C) {
                *reinterpret_cast<float2*>(C + (long)row * Nf + col) = v0;
                *reinterpret_cast<float2*>(C + (long)(row + 8) * Nf + col) = v1;
            }
            if (Ch) {
                *reinterpret_cast<__half2*>(Ch + (long)row * Nf + col) =
                    __floats2half2_rn(v0.x, v0.y);
                *reinterpret_cast<__half2*>(Ch + (long)(row + 8) * Nf + col) =
                    __floats2half2_rn(v1.x, v1.y);
            }
        }
    }
}

// ---------------------------------------------------------------------------
// tf32 dense GCN propagation — A8 tiles; X source fp32 or fp16 (XHALF).
// ---------------------------------------------------------------------------
template <bool RELU, bool XHALF>
__global__ __launch_bounds__(256) void k_prop_tf32(
        const unsigned char* __restrict__ Adj8, const void* __restrict__ XWv,
        const float* __restrict__ dis, const float* __restrict__ bias,
        float* __restrict__ out, int F, int outStride, int outOffset) {
    __shared__ uint32_t As[2][16][136];
    __shared__ uint32_t Bs[2][16][136];
    int b = blockIdx.z;
    const unsigned char* Ab = Adj8 + (long)b * kN * kN;
    const float* Xf = XHALF ? nullptr : (const float*)XWv + (long)b * kN * F;
    const __half* Xh = XHALF ? (const __half*)XWv + (long)b * kN * F : nullptr;
    const float* db = dis + b * kN;
    float* Ob = out + (long)b * kN * outStride + outOffset;
    int i0 = blockIdx.y * 128, f0 = blockIdx.x * 128;
    int t = threadIdx.x;
    int wid = t >> 5, lane = t & 31;
    int mw = (wid >> 1) * 32, nw = (wid & 1) * 64;
    int g = lane >> 2, tg = lane & 3;
    int jj = t >> 4;
    int ii = (t & 15) << 3;

    float acc[2][8][4];
#pragma unroll
    for (int i = 0; i < 2; i++)
#pragma unroll
        for (int j = 0; j < 8; j++)
#pragma unroll
            for (int c = 0; c < 4; c++) acc[i][j][c] = 0.f;

    constexpr uint32_t ONE = 0x3F800000u;

    auto ldX8 = [&](int row, float* xv) {
        if (XHALF) {
            uint4 raw = *reinterpret_cast<const uint4*>(Xh + (long)row * F + f0 + ii);
            const __half2* hp = reinterpret_cast<const __half2*>(&raw);
#pragma unroll
            for (int v = 0; v < 4; v++) {
                float2 f = __half22float2(hp[v]);
                xv[2 * v] = f.x; xv[2 * v + 1] = f.y;
            }
        } else {
            *reinterpret_cast<float4*>(xv) =
                *reinterpret_cast<const float4*>(Xf + (long)row * F + f0 + ii);
            *reinterpret_cast<float4*>(xv + 4) =
                *reinterpret_cast<const float4*>(Xf + (long)row * F + f0 + ii + 4);
        }
    };

    auto stTile = [&](int bufI, uint2 rawA, const float* xv, float dj) {
        uint4 ua0, ua1;
        ua0.x = (rawA.x & 0xffu)         ? ONE : 0u;
        ua0.y = ((rawA.x >> 8) & 0xffu)  ? ONE : 0u;
        ua0.z = ((rawA.x >> 16) & 0xffu) ? ONE : 0u;
        ua0.w = ((rawA.x >> 24) & 0xffu) ? ONE : 0u;
        ua1.x = (rawA.y & 0xffu)         ? ONE : 0u;
        ua1.y = ((rawA.y >> 8) & 0xffu)  ? ONE : 0u;
        ua1.z = ((rawA.y >> 16) & 0xffu) ? ONE : 0u;
        ua1.w = ((rawA.y >> 24) & 0xffu) ? ONE : 0u;
        uint4 ux0, ux1;
        ux0.x = f2tf(xv[0] * dj); ux0.y = f2tf(xv[1] * dj);
        ux0.z = f2tf(xv[2] * dj); ux0.w = f2tf(xv[3] * dj);
        ux1.x = f2tf(xv[4] * dj); ux1.y = f2tf(xv[5] * dj);
        ux1.z = f2tf(xv[6] * dj); ux1.w = f2tf(xv[7] * dj);
        *reinterpret_cast<uint4*>(&As[bufI][jj][ii]) = ua0;
        *reinterpret_cast<uint4*>(&As[bufI][jj][ii + 4]) = ua1;
        *reinterpret_cast<uint4*>(&Bs[bufI][jj][ii]) = ux0;
        *reinterpret_cast<uint4*>(&Bs[bufI][jj][ii + 4]) = ux1;
    };

    {
        uint2 rawA = *reinterpret_cast<const uint2*>(Ab + (long)jj * kN + i0 + ii);
        float xv[8];
        ldX8(jj, xv);
        stTile(0, rawA, xv, db[jj]);
    }
    __syncthreads();

    int buf = 0;
    for (int j0 = 0; j0 < kN; j0 += 16) {
        bool more = (j0 + 16) < kN;
        uint2 nraw;
        float nxv[8];
        float djn = 0.f;
        if (more) {
            nraw = *reinterpret_cast<const uint2*>(
                Ab + (long)(j0 + 16 + jj) * kN + i0 + ii);
            ldX8(j0 + 16 + jj, nxv);
            djn = db[j0 + 16 + jj];
        }
#pragma unroll
        for (int s = 0; s < 2; s++) {
            int kk = s * 8 + tg;
            uint32_t af[2][4];
#pragma unroll
            for (int mt = 0; mt < 2; mt++) {
                int m = mw + mt * 16 + g;
                af[mt][0] = As[buf][kk][m];
                af[mt][1] = As[buf][kk][m + 8];
                af[mt][2] = As[buf][kk + 4][m];
                af[mt][3] = As[buf][kk + 4][m + 8];
            }
#pragma unroll
            for (int j = 0; j < 8; j++) {
                int n = nw + j * 8 + g;
                uint32_t b0 = Bs[buf][kk][n];
                uint32_t b1 = Bs[buf][kk + 4][n];
                mma_tf32(acc[0][j], af[0], b0, b1);
                mma_tf32(acc[1][j], af[1], b0, b1);
            }
        }
        if (more) {
            int nb = buf ^ 1;
            stTile(nb, nraw, nxv, djn);
            __syncthreads();
            buf = nb;
        }
    }

#pragma unroll
    for (int mt = 0; mt < 2; mt++) {
        int rowA = i0 + mw + mt * 16 + g;
        float diA = db[rowA], diB = db[rowA + 8];
#pragma unroll
        for (int j = 0; j < 8; j++) {
            int col = f0 + nw + j * 8 + 2 * tg;
            float2 bb = *reinterpret_cast<const float2*>(bias + col);
            float2 xA, xB;
            if (XHALF) {
                xA = __half22float2(*reinterpret_cast<const __half2*>(
                    Xh + (long)rowA * F + col));
                xB = __half22float2(*reinterpret_cast<const __half2*>(
                    Xh + (long)(rowA + 8) * F + col));
            } else {
                xA = *reinterpret_cast<const float2*>(Xf + (long)rowA * F + col);
                xB = *reinterpret_cast<const float2*>(Xf + (long)(rowA + 8) * F + col);
            }
            float v0 = diA * (acc[mt][j][0] + diA * xA.x) + bb.x;
            float v1 = diA * (acc[mt][j][1] + diA * xA.y) + bb.y;
            float v2 = diB * (acc[mt][j][2] + diB * xB.x) + bb.x;
            float v3 = diB * (acc[mt][j][3] + diB * xB.y) + bb.y;
            if (RELU) {
                v0 = fmaxf(v0, 0.f); v1 = fmaxf(v1, 0.f);
                v2 = fmaxf(v2, 0.f); v3 = fmaxf(v3, 0.f);
            }
            *reinterpret_cast<float2*>(Ob + (long)rowA * outStride + col) =
                make_float2(v0, v1);
            *reinterpret_cast<float2*>(Ob + (long)(rowA + 8) * outStride + col) =
                make_float2(v2, v3);
        }
    }
}

// ---------------------------------------------------------------------------
// fcn1 half: h1 += emb[:, strided k-half] @ W[same cols]ᵀ, double-buffered
// ---------------------------------------------------------------------------
__global__ void k_fcn1_half(const float* __restrict__ emb, const float* __restrict__ W,
                            float* __restrict__ h1, int colOff) {
    constexpr int KH = kKTOT / 2;
    constexpr int KC = KH / 64;     // 1024
    __shared__ float As[16][32];
    __shared__ float Bs[16][64];
    int n0 = blockIdx.x * 64;
    int kbase = blockIdx.y * KC;
    int t = threadIdx.x;
    int m = t & 31;
    int nb = (t >> 5) << 3;
    int row = t >> 2, c4 = (t & 3) << 2;
    float acc[8];
#pragma unroll
    for (int j = 0; j < 8; j++) acc[j] = 0.f;

    auto kmap = [&](int k) -> long {
        return ((long)(k >> 7) << 8) + colOff + (k & 127);
    };

    float4 aPre, bPre;
    if (t < 128)
        aPre = *reinterpret_cast<const float4*>(emb + (long)row * kKTOT + kmap(kbase + c4));
    bPre = *reinterpret_cast<const float4*>(W + (long)(n0 + row) * kKTOT + kmap(kbase + c4));

    for (int k0 = kbase; k0 < kbase + KC; k0 += 16) {
        if (t < 128) {
            As[c4 + 0][row] = aPre.x; As[c4 + 1][row] = aPre.y;
            As[c4 + 2][row] = aPre.z; As[c4 + 3][row] = aPre.w;
        }
        Bs[c4 + 0][row] = bPre.x; Bs[c4 + 1][row] = bPre.y;
        Bs[c4 + 2][row] = bPre.z; Bs[c4 + 3][row] = bPre.w;
        __syncthreads();
        bool more = (k0 + 16) < kbase + KC;
        if (more) {
            if (t < 128)
                aPre = *reinterpret_cast<const float4*>(
                    emb + (long)row * kKTOT + kmap(k0 + 16 + c4));
            bPre = *reinterpret_cast<const float4*>(
                W + (long)(n0 + row) * kKTOT + kmap(k0 + 16 + c4));
        }
#pragma unroll
        for (int k = 0; k < 16; k++) {
            float a = As[k][m];
#pragma unroll
            for (int j = 0; j < 8; j++) acc[j] += a * Bs[k][nb + j];
        }
        __syncthreads();
    }
#pragma unroll
    for (int j = 0; j < 8; j++)
        atomicAdd(&h1[m * 256 + n0 + nb + j], acc[j]);
}

__global__ void k_fcn23(const float* __restrict__ h1g,
                        const float* __restrict__ b1, const float* __restrict__ w2,
                        const float* __restrict__ b2, const float* __restrict__ w3,
                        const float* __restrict__ b3, float* __restrict__ out) {
    __shared__ float h1s[32][256];
    __shared__ float h2s[32][32];
    int t = threadIdx.x;
    for (int idx = t; idx < 32 * 256; idx += 1024) {
        float v = h1g[idx] + b1[idx & 255];
        h1s[idx >> 8][idx & 255] = (v >= 0.f) ? v : 0.2f * v;
    }
    __syncthreads();
    {
        int b = t >> 5, o = t & 31;
        float s = 0.f;
#pragma unroll 8
        for (int k = 0; k < 256; k++) s += h1s[b][k] * w2[o * 256 + k];
        s += b2[o];
        h2s[b][o] = (s >= 0.f) ? s : 0.2f * s;
    }
    __syncthreads();
    if (t < 64) {
        int b = t >> 1, o = t & 1;
        float s = 0.f;
#pragma unroll
        for (int k = 0; k < 32; k++) s += h2s[b][k] * w3[o * 32 + k];
        out[b * 2 + o] = s + b3[o];
    }
}

// ---------------------------------------------------------------------------
// Launch
// ---------------------------------------------------------------------------
extern "C" void kernel_launch(void* const* d_in, const int* in_sizes, int n_in,
                              void* d_out, int out_size) {
    const float* x    = (const float*)d_in[0];
    const float* t    = (const float*)d_in[1];
    const float* gu   = (const float*)d_in[2];
    const int*   ei   = (const int*)d_in[3];
    const float* w1   = (const float*)d_in[4];
    const float* b1   = (const float*)d_in[5];
    const float* w2   = (const float*)d_in[6];
    const float* b2   = (const float*)d_in[7];
    const float* fcw  = (const float*)d_in[8];
    const float* fcb  = (const float*)d_in[9];
    const float* f1w  = (const float*)d_in[10];
    const float* f1b  = (const float*)d_in[11];
    const float* f2w  = (const float*)d_in[12];
    const float* f2b  = (const float*)d_in[13];
    const float* f3w  = (const float*)d_in[14];
    const float* f3b  = (const float*)d_in[15];
    float* out = (float*)d_out;

    const int* rowp = ei;
    const int* colp = ei + kE;

    float* base = nullptr;
    cudaGetSymbolAddress((void**)&base, g_scratch);
    float* p_E     = base + OFF_EG;
    float* p_F     = base + OFF_FG;
    unsigned char* p_A8 = (unsigned char*)(base + OFF_A8);
    float* p_disD  = base + OFF_DISD;
    float* p_part  = base + OFF_PART;
    float* p_h     = base + OFF_H;
    float* p_sc1   = base + OFF_SC1;
    float* p_xw2   = base + OFF_XW2;
    float* p_emb   = base + OFF_EMB;
    float* p_disS  = base + OFF_DISS;
    int*   p_degS  = (int*)(base + OFF_DEGS);
    float* p_h1    = base + OFF_H1;
    int*   p_ns    = (int*)(base + OFF_NS);
    int*   p_cur   = (int*)(base + OFF_CUR);
    int*   p_esrc  = (int*)(base + OFF_ESRC);
    __half* p_xw1h  = (__half*)(base + OFF_XW1H);
    __half* p_xws2h = (__half*)(base + OFF_XWS2H);

    static cudaStream_t sG = nullptr, sC = nullptr;
    static cudaEvent_t evStart, evZ, evG1, evCSR, evF1s;
    if (!sG) {
        cudaStreamCreateWithFlags(&sG, cudaStreamNonBlocking);
        cudaStreamCreateWithFlags(&sC, cudaStreamNonBlocking);
        cudaEventCreateWithFlags(&evStart, cudaEventDisableTiming);
        cudaEventCreateWithFlags(&evZ, cudaEventDisableTiming);
        cudaEventCreateWithFlags(&evG1, cudaEventDisableTiming);
        cudaEventCreateWithFlags(&evCSR, cudaEventDisableTiming);
        cudaEventCreateWithFlags(&evF1s, cudaEventDisableTiming);
    }

    cudaEventRecord(evStart, 0);
    cudaStreamWaitEvent(sG, evStart, 0);
    cudaStreamWaitEvent(sC, evStart, 0);

    // main: zero + dense prep
    k_zeroS<<<64, 256>>>(p_degS, p_h1);                               // 1
    cudaEventRecord(evZ, 0);
    k_lslr<<<kNTOT / 8, 256>>>(t, fcw, fcb, p_E, p_F);                // 2
    k_buildA<<<kBZ * kN * kN / 1024, 256>>>(gu, p_E, p_F, p_A8);      // 3

    // sG: gemm1 — fp16 output only                                    // 4 (captured)
    k_gemm_tf32<false><<<dim3(kF1 / 128, kNTOT / 128, 1), 256, 0, sG>>>(
        x, w1, nullptr, kF1, kN, p_xw1h);
    cudaEventRecord(evG1, sG);

    // main: dense degrees (atomic-free)
    k_colsum_part<<<dim3(kBZ, 8), kN>>>(p_A8, p_part);
    k_disD<<<kNTOT / 256, 256>>>(p_part, p_disD);

    // sC: CSR chain
    cudaStreamWaitEvent(sC, evZ, 0);
    k_degS<<<kE / 256, 256, 0, sC>>>(colp, p_degS);
    k_disS<<<kNTOT / 256, 256, 0, sC>>>(p_degS, p_disS);
    k_scan<<<1, 1024, 0, sC>>>(p_degS, p_ns, p_cur);
    k_fill<<<kE / 256, 256, 0, sC>>>(rowp, colp, p_cur, p_esrc);
    cudaEventRecord(evCSR, sC);

    // ===== dense pipeline (main) =====
    cudaStreamWaitEvent(0, evG1, 0);
    k_prop_tf32<true, true><<<dim3(kF1 / 128, kN / 128, kBZ), 256>>>(
        p_A8, p_xw1h, p_disD, b1, p_h, kF1, kF1, 0);
    k_gemm_tf32<true><<<dim3(kF2 / 128, kNTOT / 128, 1), 256>>>(
        p_h, w2, p_xw2, kF2, kF1, nullptr);
    k_prop_tf32<false, false><<<dim3(kF2 / 128, kN / 128, kBZ), 256>>>(
        p_A8, p_xw2, p_disD, b2, p_emb, kF2, 256, 0);
    k_fcn1_half<<<dim3(4, 64), 256>>>(p_emb, f1w, p_h1, 0);

    // ===== sparse pipeline (sG) =====
    cudaStreamWaitEvent(sG, evCSR, 0);
    k_gather_h<2, 2><<<kNTOT * 2 / 8, 256, 0, sG>>>(p_ns, p_esrc,
        (const __half2*)p_xw1h, p_disS, b1, p_sc1, kF1, 0);
    k_gemm_tf32<true><<<dim3(kF2 / 128, kNTOT / 128, 1), 256, 0, sG>>>(
        p_sc1, w2, nullptr, kF2, kF1, p_xws2h);
    k_gather_h<1, 2><<<kNTOT / 8, 256, 0, sG>>>(p_ns, p_esrc,
        (const __half2*)p_xws2h, p_disS, b2, p_emb, 256, 128);
    k_fcn1_half<<<dim3(4, 64), 256, 0, sG>>>(p_emb, f1w, p_h1, 128);
    cudaEventRecord(evF1s, sG);

    // join + head
    cudaStreamWaitEvent(0, evF1s, 0);
    k_fcn23<<<1, 1024>>>(p_h1, f1b, f2w, f2b, f3w, f3b, out);
}

// round 13
// speedup vs baseline: 1.2670x; 1.0160x over previous
#include <cuda_runtime.h>
#include <cuda_fp16.h>
#include <cstdint>

// ---------------------------------------------------------------------------
// Problem constants
// ---------------------------------------------------------------------------
constexpr int kN    = 512;
constexpr int kBZ   = 32;
constexpr int kTC   = 256;
constexpr int kF1   = 256;
constexpr int kF2   = 128;
constexpr int kE    = 524288;
constexpr int kNTOT = kBZ * kN;          // 16384
constexpr int kKTOT = kF2 * 2 * kN;      // 131072

// ---------------------------------------------------------------------------
// Scratch (offsets in floats)
// ---------------------------------------------------------------------------
constexpr long OFF_EG   = 0;
constexpr long OFF_FG   = OFF_EG   + (long)kNTOT;
constexpr long OFF_A8   = OFF_FG   + (long)kNTOT;                // u8 view
constexpr long OFF_DISD = OFF_A8   + (long)kBZ * kN * kN / 4;
constexpr long OFF_PART = OFF_DISD + (long)kNTOT;                // 32*8*512
constexpr long OFF_H    = OFF_PART + (long)kBZ * 8 * kN;
constexpr long OFF_SC1  = OFF_H    + (long)kNTOT * kF1;
constexpr long OFF_XW2  = OFF_SC1  + (long)kNTOT * kF1;
constexpr long OFF_EMB  = OFF_XW2  + (long)kNTOT * kF2;
constexpr long OFF_DISS = OFF_EMB  + (long)kNTOT * 256;
constexpr long OFF_DEGS = OFF_DISS + (long)kNTOT;                // int
constexpr long OFF_H1   = OFF_DEGS + (long)kNTOT;
constexpr long OFF_NS   = OFF_H1   + (long)kBZ * 256;            // int, kNTOT+1
constexpr long OFF_CUR  = OFF_NS   + (long)kNTOT + 4;            // int
constexpr long OFF_ESRC = OFF_CUR  + (long)kNTOT;                // int, kE
constexpr long OFF_XW1H = OFF_ESRC + (long)kE;                   // half, NTOT*F1
constexpr long OFF_XWS2H= OFF_XW1H + (long)kNTOT * kF1 / 2;      // half, NTOT*F2
constexpr long SCRATCH_FLOATS = OFF_XWS2H + (long)kNTOT * kF2 / 2;

__device__ __align__(16) float g_scratch[SCRATCH_FLOATS];

// ---------------------------------------------------------------------------
// mma / ldmatrix helpers
// ---------------------------------------------------------------------------
__device__ __forceinline__ uint32_t f2tf(float x) {
    uint32_t r;
    asm("cvt.rna.tf32.f32 %0, %1;" : "=r"(r) : "f"(x));
    return r;
}
__device__ __forceinline__ void mma_tf32(float* d, const uint32_t* a,
                                         uint32_t b0, uint32_t b1) {
    asm volatile(
        "mma.sync.aligned.m16n8k8.row.col.f32.tf32.tf32.f32 "
        "{%0,%1,%2,%3},{%4,%5,%6,%7},{%8,%9},{%0,%1,%2,%3};"
        : "+f"(d[0]), "+f"(d[1]), "+f"(d[2]), "+f"(d[3])
        : "r"(a[0]), "r"(a[1]), "r"(a[2]), "r"(a[3]), "r"(b0), "r"(b1));
}
__device__ __forceinline__ void mma_f16(float* d, const uint32_t* a,
                                        uint32_t b0, uint32_t b1) {
    asm volatile(
        "mma.sync.aligned.m16n8k16.row.col.f32.f16.f16.f32 "
        "{%0,%1,%2,%3},{%4,%5,%6,%7},{%8,%9},{%0,%1,%2,%3};"
        : "+f"(d[0]), "+f"(d[1]), "+f"(d[2]), "+f"(d[3])
        : "r"(a[0]), "r"(a[1]), "r"(a[2]), "r"(a[3]), "r"(b0), "r"(b1));
}
__device__ __forceinline__ void ldsm4(uint32_t* r, uint32_t addr) {
    asm volatile("ldmatrix.sync.aligned.m8n8.x4.shared.b16 {%0,%1,%2,%3}, [%4];"
                 : "=r"(r[0]), "=r"(r[1]), "=r"(r[2]), "=r"(r[3]) : "r"(addr));
}
__device__ __forceinline__ void ldsm4t(uint32_t* r, uint32_t addr) {
    asm volatile("ldmatrix.sync.aligned.m8n8.x4.trans.shared.b16 {%0,%1,%2,%3}, [%4];"
                 : "=r"(r[0]), "=r"(r[1]), "=r"(r[2]), "=r"(r[3]) : "r"(addr));
}
__device__ __forceinline__ uint32_t smem_u32(const void* p) {
    return (uint32_t)__cvta_generic_to_shared(p);
}
__device__ __forceinline__ uint32_t h2u(__half2 h) {
    return *reinterpret_cast<uint32_t*>(&h);
}

// ---------------------------------------------------------------------------
// Small kernels
// ---------------------------------------------------------------------------
__global__ void k_zeroS(int* degS, float* h1) {
    int i = blockIdx.x * 256 + threadIdx.x;
    if (i < kNTOT) degS[i] = 0;
    if (i < kBZ * 256) h1[i] = 0.f;
}

__global__ void k_lslr(const float* __restrict__ t, const float* __restrict__ fcw,
                       const float* __restrict__ fcb,
                       float* __restrict__ Eg, float* __restrict__ Fg) {
    int warp = (blockIdx.x * blockDim.x + threadIdx.x) >> 5;
    int lane = threadIdx.x & 31;
    if (warp >= kNTOT) return;
    const float* tn = t + (long)warp * kTC;
    const float* w0 = fcw;
    const float* w1 = fcw + 512;
    float s0 = 0.f, s1 = 0.f, r0 = 0.f, r1 = 0.f;
#pragma unroll
    for (int q = 0; q < 8; q++) {
        int d = lane + 32 * q;
        float u = fmaxf(tn[d], 0.f);
        s0 += u * w0[d];       s1 += u * w1[d];
        r0 += u * w0[256 + d]; r1 += u * w1[256 + d];
    }
#pragma unroll
    for (int off = 16; off; off >>= 1) {
        s0 += __shfl_down_sync(0xffffffffu, s0, off);
        s1 += __shfl_down_sync(0xffffffffu, s1, off);
        r0 += __shfl_down_sync(0xffffffffu, r0, off);
        r1 += __shfl_down_sync(0xffffffffu, r1, off);
    }
    if (lane == 0) {
        Eg[warp] = expf(r1 - r0 + fcb[1] - fcb[0]);
        Fg[warp] = expf(s1 - s0);
    }
}

__global__ void k_buildA(const float* __restrict__ gu,
                         const float* __restrict__ Eg, const float* __restrict__ Fg,
                         unsigned char* __restrict__ A8) {
    int idx = blockIdx.x * 256 + threadIdx.x;
    int j0 = (idx & 127) << 2;
    int i  = (idx >> 7) & 511;
    int b  = idx >> 16;
    float Ei = Eg[b * kN + i];
    float4 Fv = *reinterpret_cast<const float4*>(Fg + b * kN + j0);
    const float4* g4 = reinterpret_cast<const float4*>(
        gu + ((long)(b * kN + i) * kN + j0) * 2);
    float4 u01 = g4[0];
    float4 u23 = g4[1];
    auto bit = [&](float ux, float uy, float Fj) -> unsigned char {
        ux = fminf(fmaxf(ux, 1e-9f), 1.0f - 1e-9f);
        uy = fminf(fmaxf(uy, 1e-9f), 1.0f - 1e-9f);
        float l0 = -__logf(ux);
        float l1 = -__logf(uy);
        return (l1 >= l0 * Ei * Fj) ? 1 : 0;
    };
    uchar4 r;
    r.x = bit(u01.x, u01.y, Fv.x);
    r.y = bit(u01.z, u01.w, Fv.y);
    r.z = bit(u23.x, u23.y, Fv.z);
    r.w = bit(u23.z, u23.w, Fv.w);
    *reinterpret_cast<uchar4*>(A8 + (long)(b * kN + i) * kN + j0) = r;
}

__global__ void k_colsum_part(const unsigned char* __restrict__ A8,
                              float* __restrict__ part) {
    int b = blockIdx.x;
    int j = threadIdx.x;
    int r0 = blockIdx.y * 64;
    const unsigned char* Ab = A8 + (long)b * kN * kN;
    int s = 0;
#pragma unroll 8
    for (int r = r0; r < r0 + 64; r++) s += Ab[(long)r * kN + j];
    part[((long)b * 8 + blockIdx.y) * kN + j] = (float)s;
}

__global__ void k_disD(const float* __restrict__ part, float* __restrict__ disD) {
    int i = blockIdx.x * 256 + threadIdx.x;
    if (i >= kNTOT) return;
    int b = i >> 9, j = i & 511;
    float s = 1.f;
#pragma unroll
    for (int c = 0; c < 8; c++) s += part[((long)b * 8 + c) * kN + j];
    disD[i] = rsqrtf(s);
}

__global__ void k_degS(const int* __restrict__ colp, int* degS) {
    int e = blockIdx.x * 256 + threadIdx.x;
    if (e < kE) atomicAdd(&degS[colp[e]], 1);
}

__global__ void k_disS(const int* __restrict__ degS, float* __restrict__ disS) {
    int i = blockIdx.x * 256 + threadIdx.x;
    if (i < kNTOT) disS[i] = rsqrtf((float)degS[i] + 1.f);
}

__global__ void k_scan(const int* __restrict__ degS, int* __restrict__ ns,
                       int* __restrict__ cur) {
    __shared__ int sm[1024];
    int tid = threadIdx.x;
    int base = tid * 16;
    int local[16];
    int sum = 0;
#pragma unroll
    for (int v = 0; v < 16; v++) { local[v] = degS[base + v]; sum += local[v]; }
    sm[tid] = sum;
    __syncthreads();
    for (int off = 1; off < 1024; off <<= 1) {
        int v = (tid >= off) ? sm[tid - off] : 0;
        __syncthreads();
        sm[tid] += v;
        __syncthreads();
    }
    int run = sm[tid] - sum;
#pragma unroll
    for (int v = 0; v < 16; v++) {
        ns[base + v] = run;
        cur[base + v] = run;
        run += local[v];
    }
    if (tid == 1023) ns[kNTOT] = run;
}

__global__ void k_fill(const int* __restrict__ rowp, const int* __restrict__ colp,
                       int* cur, int* __restrict__ esrc) {
    int e = blockIdx.x * 256 + threadIdx.x;
    if (e < kE) {
        int c = colp[e];
        int p = atomicAdd(&cur[c], 1);
        esrc[p] = rowp[e];
    }
}

// ---------------------------------------------------------------------------
// fp16 CSR gather: WPN warps per node, VH half2 per lane.
// ---------------------------------------------------------------------------
template <int WPN, int VH>
__global__ __launch_bounds__(256) void k_gather_h(
        const int* __restrict__ ns, const int* __restrict__ esrc,
        const __half2* __restrict__ xwh, const float* __restrict__ disS,
        const float* __restrict__ bias, float* __restrict__ out,
        int outStride, int outOffset) {
    constexpr int F2 = WPN * VH * 32;
    int gw = (blockIdx.x * 256 + threadIdx.x) >> 5;
    int lane = threadIdx.x & 31;
    int node = gw / WPN;
    int part = gw % WPN;
    if (node >= kNTOT) return;
    int off2 = (part * 32 + lane) * VH;
    float dc = disS[node];
    float2 acc[VH];

    auto loadrow = [&](long r, uint32_t* rw) {
        const char* p = reinterpret_cast<const char*>(xwh + r * F2 + off2);
        if (VH == 4) {
            uint4 u = *reinterpret_cast<const uint4*>(p);
            rw[0] = u.x; rw[1] = u.y; rw[2] = u.z; rw[3] = u.w;
        } else {
            uint2 u = *reinterpret_cast<const uint2*>(p);
            rw[0] = u.x; rw[1] = u.y;
        }
    };

    {
        uint32_t rw[VH];
        loadrow(node, rw);
        float d2 = dc * dc;
#pragma unroll
        for (int v = 0; v < VH; v++) {
            float2 xv = __half22float2(*reinterpret_cast<__half2*>(&rw[v]));
            float2 bb = *reinterpret_cast<const float2*>(bias + (off2 + v) * 2);
            acc[v] = make_float2(xv.x * d2 + bb.x, xv.y * d2 + bb.y);
        }
    }
    int s = ns[node], e = ns[node + 1];
    int i = s;
    for (; i + 8 <= e; i += 8) {
        int r[8];
        float sc[8];
        uint32_t rw[8][VH];
#pragma unroll
        for (int q = 0; q < 8; q++) r[q] = esrc[i + q];
#pragma unroll
        for (int q = 0; q < 8; q++) sc[q] = disS[r[q]] * dc;
#pragma unroll
        for (int q = 0; q < 8; q++) loadrow(r[q], rw[q]);
#pragma unroll
        for (int q = 0; q < 8; q++)
#pragma unroll
            for (int v = 0; v < VH; v++) {
                float2 xv = __half22float2(*reinterpret_cast<__half2*>(&rw[q][v]));
                acc[v].x += xv.x * sc[q];
                acc[v].y += xv.y * sc[q];
            }
    }
    for (; i < e; i++) {
        int r = esrc[i];
        float sr = disS[r] * dc;
        uint32_t rw[VH];
        loadrow(r, rw);
#pragma unroll
        for (int v = 0; v < VH; v++) {
            float2 xv = __half22float2(*reinterpret_cast<__half2*>(&rw[v]));
            acc[v].x += xv.x * sr;
            acc[v].y += xv.y * sr;
        }
    }
    float* op = out + (long)node * outStride + outOffset + off2 * 2;
#pragma unroll
    for (int v = 0; v < VH; v++)
        *reinterpret_cast<float2*>(op + v * 2) = acc[v];
}

// ---------------------------------------------------------------------------
// tf32 NT GEMM, ldmatrix fragment loads; fp32 and/or fp16 outputs.
// ---------------------------------------------------------------------------
template <bool RELU_A>
__global__ __launch_bounds__(256) void k_gemm_tf32(
        const float* __restrict__ A,
        const float* __restrict__ B,
        float* __restrict__ C,
        int Nf, int K, __half* __restrict__ Ch) {
    __shared__ uint32_t As[2][128][20];
    __shared__ uint32_t Bs[2][128][20];
    int m0 = blockIdx.y * 128, n0 = blockIdx.x * 128;
    int t = threadIdx.x;
    int wid = t >> 5, lane = t & 31;
    int mw = (wid >> 1) * 32, nw = (wid & 1) * 64;
    int g = lane >> 2, tg = lane & 3;
    int lrow16 = lane & 15;
    int lhalf4 = (lane >> 4) * 4;
    int lr = t >> 2, lc = (t & 3) << 2;

    uint32_t sA[2] = { smem_u32(&As[0][0][0]), smem_u32(&As[1][0][0]) };
    uint32_t sB[2] = { smem_u32(&Bs[0][0][0]), smem_u32(&Bs[1][0][0]) };

    float acc[2][8][4];
#pragma unroll
    for (int i = 0; i < 2; i++)
#pragma unroll
        for (int j = 0; j < 8; j++)
#pragma unroll
            for (int c = 0; c < 4; c++) acc[i][j][c] = 0.f;

    const float* aP0 = A + (long)(m0 + lr) * K + lc;
    const float* aP1 = A + (long)(m0 + lr + 64) * K + lc;
    const float* bP0 = B + (long)(n0 + lr) * K + lc;
    const float* bP1 = B + (long)(n0 + lr + 64) * K + lc;

    auto cvt4 = [](float4 v, bool relu) -> uint4 {
        if (relu) {
            v.x = fmaxf(v.x, 0.f); v.y = fmaxf(v.y, 0.f);
            v.z = fmaxf(v.z, 0.f); v.w = fmaxf(v.w, 0.f);
        }
        uint4 r;
        r.x = f2tf(v.x); r.y = f2tf(v.y); r.z = f2tf(v.z); r.w = f2tf(v.w);
        return r;
    };

    {
        uint4 a0 = cvt4(*reinterpret_cast<const float4*>(aP0), RELU_A);
        uint4 a1 = cvt4(*reinterpret_cast<const float4*>(aP1), RELU_A);
        uint4 b0 = cvt4(*reinterpret_cast<const float4*>(bP0), false);
        uint4 b1 = cvt4(*reinterpret_cast<const float4*>(bP1), false);
        *reinterpret_cast<uint4*>(&As[0][lr][lc]) = a0;
        *reinterpret_cast<uint4*>(&As[0][lr + 64][lc]) = a1;
        *reinterpret_cast<uint4*>(&Bs[0][lr][lc]) = b0;
        *reinterpret_cast<uint4*>(&Bs[0][lr + 64][lc]) = b1;
    }
    __syncthreads();

    int buf = 0;
    for (int k0 = 0; k0 < K; k0 += 16) {
        bool more = (k0 + 16) < K;
        float4 na0, na1, nb0, nb1;
        if (more) {
            na0 = *reinterpret_cast<const float4*>(aP0 + k0 + 16);
            na1 = *reinterpret_cast<const float4*>(aP1 + k0 + 16);
            nb0 = *reinterpret_cast<const float4*>(bP0 + k0 + 16);
            nb1 = *reinterpret_cast<const float4*>(bP1 + k0 + 16);
        }
#pragma unroll
        for (int s = 0; s < 2; s++) {
            int kcol = s * 8 + lhalf4;
            uint32_t af0[4], af1[4];
            ldsm4(af0, sA[buf] + ((mw + lrow16) * 20 + kcol) * 4);
            ldsm4(af1, sA[buf] + ((mw + 16 + lrow16) * 20 + kcol) * 4);
#pragma unroll
            for (int p = 0; p < 4; p++) {
                uint32_t bf[4];
                ldsm4(bf, sB[buf] + ((nw + p * 16 + lrow16) * 20 + kcol) * 4);
                mma_tf32(acc[0][2 * p],     af0, bf[0], bf[2]);
                mma_tf32(acc[0][2 * p + 1], af0, bf[1], bf[3]);
                mma_tf32(acc[1][2 * p],     af1, bf[0], bf[2]);
                mma_tf32(acc[1][2 * p + 1], af1, bf[1], bf[3]);
            }
        }
        if (more) {
            int nb = buf ^ 1;
            *reinterpret_cast<uint4*>(&As[nb][lr][lc]) = cvt4(na0, RELU_A);
            *reinterpret_cast<uint4*>(&As[nb][lr + 64][lc]) = cvt4(na1, RELU_A);
            *reinterpret_cast<uint4*>(&Bs[nb][lr][lc]) = cvt4(nb0, false);
            *reinterpret_cast<uint4*>(&Bs[nb][lr + 64][lc]) = cvt4(nb1, false);
            __syncthreads();
            buf = nb;
        }
    }

#pragma unroll
    for (int mt = 0; mt < 2; mt++) {
        int row = m0 + mw + mt * 16 + g;
#pragma unroll
        for (int j = 0; j < 8; j++) {
            int col = n0 + nw + j * 8 + 2 * tg;
            float2 v0 = make_float2(acc[mt][j][0], acc[mt][j][1]);
            float2 v1 = make_float2(acc[mt][j][2], acc[mt][j][3]);
            if (C) {
                *reinterpret_cast<float2*>(C + (long)row * Nf + col) = v0;
                *reinterpret_cast<float2*>(C + (long)(row + 8) * Nf + col) = v1;
            }
            if (Ch) {
                *reinterpret_cast<__half2*>(Ch + (long)row * Nf + col) =
                    __floats2half2_rn(v0.x, v0.y);
                *reinterpret_cast<__half2*>(Ch + (long)(row + 8) * Nf + col) =
                    __floats2half2_rn(v1.x, v1.y);
            }
        }
    }
}

// ---------------------------------------------------------------------------
// fp16 HMMA dense GCN propagation (m16n8k16, fp32 accum).
// A8 tiles -> exact 0/1 halves; X source fp32 or fp16 (XHALF).
// SMEM tiles: halves [16 k][136 m/n-pad]; ldmatrix.x4.trans fragments.
// ---------------------------------------------------------------------------
template <bool RELU, bool XHALF>
__global__ __launch_bounds__(256) void k_prop_h(
        const unsigned char* __restrict__ Adj8, const void* __restrict__ XWv,
        const float* __restrict__ dis, const float* __restrict__ bias,
        float* __restrict__ out, int F, int outStride, int outOffset) {
    __shared__ __half As[2][16][136];
    __shared__ __half Bs[2][16][136];
    int b = blockIdx.z;
    const unsigned char* Ab = Adj8 + (long)b * kN * kN;
    const float* Xf = XHALF ? nullptr : (const float*)XWv + (long)b * kN * F;
    const __half* Xh = XHALF ? (const __half*)XWv + (long)b * kN * F : nullptr;
    const float* db = dis + b * kN;
    float* Ob = out + (long)b * kN * outStride + outOffset;
    int i0 = blockIdx.y * 128, f0 = blockIdx.x * 128;
    int t = threadIdx.x;
    int wid = t >> 5, lane = t & 31;
    int mw = (wid >> 1) * 32, nw = (wid & 1) * 64;
    int g = lane >> 2, tg = lane & 3;
    int jj = t >> 4;
    int ii = (t & 15) << 3;

    // ldmatrix.trans lane addressing
    int l8 = lane & 7;
    int gA_k = (lane >> 4) * 8 + l8;        // A: group bit1 -> k offset
    int gA_m = ((lane >> 3) & 1) * 8;       //    group bit0 -> m col offset
    int gB_k = ((lane >> 3) & 1) * 8 + l8;  // B: group bit0 -> k offset
    int gB_n = (lane >> 4) * 8;             //    group bit1 -> n col offset

    uint32_t sAb[2] = { smem_u32(&As[0][0][0]), smem_u32(&As[1][0][0]) };
    uint32_t sBb[2] = { smem_u32(&Bs[0][0][0]), smem_u32(&Bs[1][0][0]) };

    float acc[2][8][4];
#pragma unroll
    for (int i = 0; i < 2; i++)
#pragma unroll
        for (int j = 0; j < 8; j++)
#pragma unroll
            for (int c = 0; c < 4; c++) acc[i][j][c] = 0.f;

    auto ldX8 = [&](int row, float* xv) {
        if (XHALF) {
            uint4 raw = *reinterpret_cast<const uint4*>(Xh + (long)row * F + f0 + ii);
            const __half2* hp = reinterpret_cast<const __half2*>(&raw);
#pragma unroll
            for (int v = 0; v < 4; v++) {
                float2 f = __half22float2(hp[v]);
                xv[2 * v] = f.x; xv[2 * v + 1] = f.y;
            }
        } else {
            *reinterpret_cast<float4*>(xv) =
                *reinterpret_cast<const float4*>(Xf + (long)row * F + f0 + ii);
            *reinterpret_cast<float4*>(xv + 4) =
                *reinterpret_cast<const float4*>(Xf + (long)row * F + f0 + ii + 4);
        }
    };

    auto hb = [](uint32_t byte) -> uint32_t { return byte ? 0x3C00u : 0u; };

    auto stTile = [&](int bufI, uint2 rawA, const float* xv, float dj) {
        uint4 ua;
        ua.x = hb(rawA.x & 0xffu)         | (hb((rawA.x >> 8) & 0xffu) << 16);
        ua.y = hb((rawA.x >> 16) & 0xffu) | (hb(rawA.x >> 24) << 16);
        ua.z = hb(rawA.y & 0xffu)         | (hb((rawA.y >> 8) & 0xffu) << 16);
        ua.w = hb((rawA.y >> 16) & 0xffu) | (hb(rawA.y >> 24) << 16);
        uint4 ub;
        ub.x = h2u(__floats2half2_rn(xv[0] * dj, xv[1] * dj));
        ub.y = h2u(__floats2half2_rn(xv[2] * dj, xv[3] * dj));
        ub.z = h2u(__floats2half2_rn(xv[4] * dj, xv[5] * dj));
        ub.w = h2u(__floats2half2_rn(xv[6] * dj, xv[7] * dj));
        *reinterpret_cast<uint4*>(&As[bufI][jj][ii]) = ua;
        *reinterpret_cast<uint4*>(&Bs[bufI][jj][ii]) = ub;
    };

    {
        uint2 rawA = *reinterpret_cast<const uint2*>(Ab + (long)jj * kN + i0 + ii);
        float xv[8];
        ldX8(jj, xv);
        stTile(0, rawA, xv, db[jj]);
    }
    __syncthreads();

    int buf = 0;
    for (int j0 = 0; j0 < kN; j0 += 16) {
        bool more = (j0 + 16) < kN;
        uint2 nraw;
        float nxv[8];
        float djn = 0.f;
        if (more) {
            nraw = *reinterpret_cast<const uint2*>(
                Ab + (long)(j0 + 16 + jj) * kN + i0 + ii);
            ldX8(j0 + 16 + jj, nxv);
            djn = db[j0 + 16 + jj];
        }
        {
            uint32_t a0[4], a1[4];
            ldsm4t(a0, sAb[buf] + (gA_k * 136 + mw + gA_m) * 2);
            ldsm4t(a1, sAb[buf] + (gA_k * 136 + mw + 16 + gA_m) * 2);
#pragma unroll
            for (int p = 0; p < 4; p++) {
                uint32_t bf[4];
                ldsm4t(bf, sBb[buf] + (gB_k * 136 + nw + p * 16 + gB_n) * 2);
                mma_f16(acc[0][2 * p],     a0, bf[0], bf[1]);
                mma_f16(acc[0][2 * p + 1], a0, bf[2], bf[3]);
                mma_f16(acc[1][2 * p],     a1, bf[0], bf[1]);
                mma_f16(acc[1][2 * p + 1], a1, bf[2], bf[3]);
            }
        }
        if (more) {
            int nb = buf ^ 1;
            stTile(nb, nraw, nxv, djn);
            __syncthreads();
            buf = nb;
        }
    }

#pragma unroll
    for (int mt = 0; mt < 2; mt++) {
        int rowA = i0 + mw + mt * 16 + g;
        float diA = db[rowA], diB = db[rowA + 8];
#pragma unroll
        for (int j = 0; j < 8; j++) {
            int col = f0 + nw + j * 8 + 2 * tg;
            float2 bb = *reinterpret_cast<const float2*>(bias + col);
            float2 xA, xB;
            if (XHALF) {
                xA = __half22float2(*reinterpret_cast<const __half2*>(
                    Xh + (long)rowA * F + col));
                xB = __half22float2(*reinterpret_cast<const __half2*>(
                    Xh + (long)(rowA + 8) * F + col));
            } else {
                xA = *reinterpret_cast<const float2*>(Xf + (long)rowA * F + col);
                xB = *reinterpret_cast<const float2*>(Xf + (long)(rowA + 8) * F + col);
            }
            float v0 = diA * (acc[mt][j][0] + diA * xA.x) + bb.x;
            float v1 = diA * (acc[mt][j][1] + diA * xA.y) + bb.y;
            float v2 = diB * (acc[mt][j][2] + diB * xB.x) + bb.x;
            float v3 = diB * (acc[mt][j][3] + diB * xB.y) + bb.y;
            if (RELU) {
                v0 = fmaxf(v0, 0.f); v1 = fmaxf(v1, 0.f);
                v2 = fmaxf(v2, 0.f); v3 = fmaxf(v3, 0.f);
            }
            *reinterpret_cast<float2*>(Ob + (long)rowA * outStride + col) =
                make_float2(v0, v1);
            *reinterpret_cast<float2*>(Ob + (long)(rowA + 8) * outStride + col) =
                make_float2(v2, v3);
        }
    }
}

// ---------------------------------------------------------------------------
// fcn1 half (strided k-half), double-buffered
// ---------------------------------------------------------------------------
__global__ void k_fcn1_half(const float* __restrict__ emb, const float* __restrict__ W,
                            float* __restrict__ h1, int colOff) {
    constexpr int KH = kKTOT / 2;
    constexpr int KC = KH / 64;     // 1024
    __shared__ float As[16][32];
    __shared__ float Bs[16][64];
    int n0 = blockIdx.x * 64;
    int kbase = blockIdx.y * KC;
    int t = threadIdx.x;
    int m = t & 31;
    int nb = (t >> 5) << 3;
    int row = t >> 2, c4 = (t & 3) << 2;
    float acc[8];
#pragma unroll
    for (int j = 0; j < 8; j++) acc[j] = 0.f;

    auto kmap = [&](int k) -> long {
        return ((long)(k >> 7) << 8) + colOff + (k & 127);
    };

    float4 aPre, bPre;
    if (t < 128)
        aPre = *reinterpret_cast<const float4*>(emb + (long)row * kKTOT + kmap(kbase + c4));
    bPre = *reinterpret_cast<const float4*>(W + (long)(n0 + row) * kKTOT + kmap(kbase + c4));

    for (int k0 = kbase; k0 < kbase + KC; k0 += 16) {
        if (t < 128) {
            As[c4 + 0][row] = aPre.x; As[c4 + 1][row] = aPre.y;
            As[c4 + 2][row] = aPre.z; As[c4 + 3][row] = aPre.w;
        }
        Bs[c4 + 0][row] = bPre.x; Bs[c4 + 1][row] = bPre.y;
        Bs[c4 + 2][row] = bPre.z; Bs[c4 + 3][row] = bPre.w;
        __syncthreads();
        bool more = (k0 + 16) < kbase + KC;
        if (more) {
            if (t < 128)
                aPre = *reinterpret_cast<const float4*>(
                    emb + (long)row * kKTOT + kmap(k0 + 16 + c4));
            bPre = *reinterpret_cast<const float4*>(
                W + (long)(n0 + row) * kKTOT + kmap(k0 + 16 + c4));
        }
#pragma unroll
        for (int k = 0; k < 16; k++) {
            float a = As[k][m];
#pragma unroll
            for (int j = 0; j < 8; j++) acc[j] += a * Bs[k][nb + j];
        }
        __syncthreads();
    }
#pragma unroll
    for (int j = 0; j < 8; j++)
        atomicAdd(&h1[m * 256 + n0 + nb + j], acc[j]);
}

__global__ void k_fcn23(const float* __restrict__ h1g,
                        const float* __restrict__ b1, const float* __restrict__ w2,
                        const float* __restrict__ b2, const float* __restrict__ w3,
                        const float* __restrict__ b3, float* __restrict__ out) {
    __shared__ float h1s[32][256];
    __shared__ float h2s[32][32];
    int t = threadIdx.x;
    for (int idx = t; idx < 32 * 256; idx += 1024) {
        float v = h1g[idx] + b1[idx & 255];
        h1s[idx >> 8][idx & 255] = (v >= 0.f) ? v : 0.2f * v;
    }
    __syncthreads();
    {
        int b = t >> 5, o = t & 31;
        float s = 0.f;
#pragma unroll 8
        for (int k = 0; k < 256; k++) s += h1s[b][k] * w2[o * 256 + k];
        s += b2[o];
        h2s[b][o] = (s >= 0.f) ? s : 0.2f * s;
    }
    __syncthreads();
    if (t < 64) {
        int b = t >> 1, o = t & 1;
        float s = 0.f;
#pragma unroll
        for (int k = 0; k < 32; k++) s += h2s[b][k] * w3[o * 32 + k];
        out[b * 2 + o] = s + b3[o];
    }
}

// ---------------------------------------------------------------------------
// Launch
// ---------------------------------------------------------------------------
extern "C" void kernel_launch(void* const* d_in, const int* in_sizes, int n_in,
                              void* d_out, int out_size) {
    const float* x    = (const float*)d_in[0];
    const float* t    = (const float*)d_in[1];
    const float* gu   = (const float*)d_in[2];
    const int*   ei   = (const int*)d_in[3];
    const float* w1   = (const float*)d_in[4];
    const float* b1   = (const float*)d_in[5];
    const float* w2   = (const float*)d_in[6];
    const float* b2   = (const float*)d_in[7];
    const float* fcw  = (const float*)d_in[8];
    const float* fcb  = (const float*)d_in[9];
    const float* f1w  = (const float*)d_in[10];
    const float* f1b  = (const float*)d_in[11];
    const float* f2w  = (const float*)d_in[12];
    const float* f2b  = (const float*)d_in[13];
    const float* f3w  = (const float*)d_in[14];
    const float* f3b  = (const float*)d_in[15];
    float* out = (float*)d_out;

    const int* rowp = ei;
    const int* colp = ei + kE;

    float* base = nullptr;
    cudaGetSymbolAddress((void**)&base, g_scratch);
    float* p_E     = base + OFF_EG;
    float* p_F     = base + OFF_FG;
    unsigned char* p_A8 = (unsigned char*)(base + OFF_A8);
    float* p_disD  = base + OFF_DISD;
    float* p_part  = base + OFF_PART;
    float* p_h     = base + OFF_H;
    float* p_sc1   = base + OFF_SC1;
    float* p_xw2   = base + OFF_XW2;
    float* p_emb   = base + OFF_EMB;
    float* p_disS  = base + OFF_DISS;
    int*   p_degS  = (int*)(base + OFF_DEGS);
    float* p_h1    = base + OFF_H1;
    int*   p_ns    = (int*)(base + OFF_NS);
    int*   p_cur   = (int*)(base + OFF_CUR);
    int*   p_esrc  = (int*)(base + OFF_ESRC);
    __half* p_xw1h  = (__half*)(base + OFF_XW1H);
    __half* p_xws2h = (__half*)(base + OFF_XWS2H);

    static cudaStream_t sG = nullptr, sC = nullptr;
    static cudaEvent_t evStart, evZ, evG1, evCSR, evF1s;
    if (!sG) {
        cudaStreamCreateWithFlags(&sG, cudaStreamNonBlocking);
        cudaStreamCreateWithFlags(&sC, cudaStreamNonBlocking);
        cudaEventCreateWithFlags(&evStart, cudaEventDisableTiming);
        cudaEventCreateWithFlags(&evZ, cudaEventDisableTiming);
        cudaEventCreateWithFlags(&evG1, cudaEventDisableTiming);
        cudaEventCreateWithFlags(&evCSR, cudaEventDisableTiming);
        cudaEventCreateWithFlags(&evF1s, cudaEventDisableTiming);
    }

    cudaEventRecord(evStart, 0);
    cudaStreamWaitEvent(sG, evStart, 0);
    cudaStreamWaitEvent(sC, evStart, 0);

    // main: zero + dense prep
    k_zeroS<<<64, 256>>>(p_degS, p_h1);
    cudaEventRecord(evZ, 0);
    k_lslr<<<kNTOT / 8, 256>>>(t, fcw, fcb, p_E, p_F);
    k_buildA<<<kBZ * kN * kN / 1024, 256>>>(gu, p_E, p_F, p_A8);

    // sG: gemm1 — fp16 output only (captured slot)
    k_gemm_tf32<false><<<dim3(kF1 / 128, kNTOT / 128, 1), 256, 0, sG>>>(
        x, w1, nullptr, kF1, kN, p_xw1h);
    cudaEventRecord(evG1, sG);

    // main: dense degrees (atomic-free)
    k_colsum_part<<<dim3(kBZ, 8), kN>>>(p_A8, p_part);
    k_disD<<<kNTOT / 256, 256>>>(p_part, p_disD);

    // sC: CSR chain
    cudaStreamWaitEvent(sC, evZ, 0);
    k_degS<<<kE / 256, 256, 0, sC>>>(colp, p_degS);
    k_disS<<<kNTOT / 256, 256, 0, sC>>>(p_degS, p_disS);
    k_scan<<<1, 1024, 0, sC>>>(p_degS, p_ns, p_cur);
    k_fill<<<kE / 256, 256, 0, sC>>>(rowp, colp, p_cur, p_esrc);
    cudaEventRecord(evCSR, sC);

    // ===== dense pipeline (main) =====
    cudaStreamWaitEvent(0, evG1, 0);
    k_prop_h<true, true><<<dim3(kF1 / 128, kN / 128, kBZ), 256>>>(
        p_A8, p_xw1h, p_disD, b1, p_h, kF1, kF1, 0);
    k_gemm_tf32<true><<<dim3(kF2 / 128, kNTOT / 128, 1), 256>>>(
        p_h, w2, p_xw2, kF2, kF1, nullptr);
    k_prop_h<false, false><<<dim3(kF2 / 128, kN / 128, kBZ), 256>>>(
        p_A8, p_xw2, p_disD, b2, p_emb, kF2, 256, 0);
    k_fcn1_half<<<dim3(4, 64), 256>>>(p_emb, f1w, p_h1, 0);

    // ===== sparse pipeline (sG) =====
    cudaStreamWaitEvent(sG, evCSR, 0);
    k_gather_h<2, 2><<<kNTOT * 2 / 8, 256, 0, sG>>>(p_ns, p_esrc,
        (const __half2*)p_xw1h, p_disS, b1, p_sc1, kF1, 0);
    k_gemm_tf32<true><<<dim3(kF2 / 128, kNTOT / 128, 1), 256, 0, sG>>>(
        p_sc1, w2, nullptr, kF2, kF1, p_xws2h);
    k_gather_h<1, 2><<<kNTOT / 8, 256, 0, sG>>>(p_ns, p_esrc,
        (const __half2*)p_xws2h, p_disS, b2, p_emb, 256, 128);
    k_fcn1_half<<<dim3(4, 64), 256, 0, sG>>>(p_emb, f1w, p_h1, 128);
    cudaEventRecord(evF1s, sG);

    // join + head
    cudaStreamWaitEvent(0, evF1s, 0);
    k_fcn23<<<1, 1024>>>(p_h1, f1b, f2w, f2b, f3w, f3b, out);
}